// round 2
// baseline (speedup 1.0000x reference)
#include <cuda_runtime.h>
#include <cuda_bf16.h>
#include <math.h>

#define NJ 30000
#define NS 12000
#define E_JS 300000
#define E_SJ 300000
#define E_SS 150000
#define E_SS_T (E_SS + NS)
#define SBERT 384
#define HID 128
#define HHID 256
#define OUTD 128

// ---------------- scratch (device globals; no allocation allowed) ----------------
__device__ float g_xj[NJ * HID];
__device__ float g_xs[NS * HID];
__device__ float g_hs[NJ * HHID];
__device__ float g_oj[NJ * HHID];
__device__ float g_os[NS * HHID];
__device__ float g_alps[NJ * 2];
__device__ float g_alpd[NJ * 2];
__device__ int   g_m[NJ * 2];
__device__ float g_den[NJ * 2];
__device__ float g_e[E_JS * 2];
__device__ float g_p[E_JS * 2];
__device__ float g_vd[2 * HID];

// ---------------- helpers ----------------
__device__ __forceinline__ int fenc(float f) {
    int b = __float_as_int(f);
    return b >= 0 ? b : (b ^ 0x7FFFFFFF);
}
__device__ __forceinline__ float fdec(int b) {
    return __int_as_float(b >= 0 ? b : (b ^ 0x7FFFFFFF));
}
__device__ __forceinline__ float warp_sum(float v) {
    #pragma unroll
    for (int o = 16; o; o >>= 1) v += __shfl_xor_sync(0xffffffffu, v, o);
    return v;
}

// ---------------- GEMM: C[M,N] = A[M,K] @ B[K,N] (+bias)(+relu) ----------------
// BM=64, BN=128, BK=16, 256 threads, 8x4 register tile.
// Requires: K % 16 == 0, N % 128 == 0. Handles M edge via guards.
__global__ __launch_bounds__(256) void gemm_kernel(
    const float* __restrict__ A, const float* __restrict__ B,
    const float* __restrict__ bias, float* __restrict__ C,
    int M, int N, int K, int relu)
{
    __shared__ float As[16][68];   // padded, transposed: As[k][row]
    __shared__ float Bs[16][128];

    const int t   = threadIdx.x;
    const int tc  = t & 31;        // 32 thread-cols * 4 = 128
    const int tr  = t >> 5;        // 8 thread-rows * 8 = 64
    const int row0 = blockIdx.x * 64;
    const int col0 = blockIdx.y * 128;

    const int arow = t >> 2;       // 0..63
    const int akq  = (t & 3) * 4;  // 0,4,8,12
    const int bs0k = t >> 5;       // for B slot s=t:   k = t/32 (0..7)
    const int bs0c = (t & 31) * 4;
    const int bs1k = bs0k + 8;     // for B slot s=t+256: k = 8..15

    float acc[8][4];
    #pragma unroll
    for (int i = 0; i < 8; i++)
        #pragma unroll
        for (int j = 0; j < 4; j++) acc[i][j] = 0.f;

    for (int k0 = 0; k0 < K; k0 += 16) {
        float4 av = make_float4(0.f, 0.f, 0.f, 0.f);
        if (row0 + arow < M)
            av = *(const float4*)(A + (size_t)(row0 + arow) * K + k0 + akq);
        float4 bv0 = *(const float4*)(B + (size_t)(k0 + bs0k) * N + col0 + bs0c);
        float4 bv1 = *(const float4*)(B + (size_t)(k0 + bs1k) * N + col0 + bs0c);

        __syncthreads();
        As[akq + 0][arow] = av.x;
        As[akq + 1][arow] = av.y;
        As[akq + 2][arow] = av.z;
        As[akq + 3][arow] = av.w;
        *(float4*)&Bs[bs0k][bs0c] = bv0;
        *(float4*)&Bs[bs1k][bs0c] = bv1;
        __syncthreads();

        #pragma unroll
        for (int kk = 0; kk < 16; kk++) {
            float4 b  = *(float4*)&Bs[kk][tc * 4];
            float4 a0 = *(float4*)&As[kk][tr * 8];
            float4 a1 = *(float4*)&As[kk][tr * 8 + 4];
            float a[8] = {a0.x, a0.y, a0.z, a0.w, a1.x, a1.y, a1.z, a1.w};
            #pragma unroll
            for (int i = 0; i < 8; i++) {
                acc[i][0] = fmaf(a[i], b.x, acc[i][0]);
                acc[i][1] = fmaf(a[i], b.y, acc[i][1]);
                acc[i][2] = fmaf(a[i], b.z, acc[i][2]);
                acc[i][3] = fmaf(a[i], b.w, acc[i][3]);
            }
        }
    }

    float4 bv = make_float4(0.f, 0.f, 0.f, 0.f);
    if (bias) bv = *(const float4*)(bias + col0 + tc * 4);
    #pragma unroll
    for (int i = 0; i < 8; i++) {
        int row = row0 + tr * 8 + i;
        if (row < M) {
            float4 o;
            o.x = acc[i][0] + bv.x;
            o.y = acc[i][1] + bv.y;
            o.z = acc[i][2] + bv.z;
            o.w = acc[i][3] + bv.w;
            if (relu) {
                o.x = fmaxf(o.x, 0.f); o.y = fmaxf(o.y, 0.f);
                o.z = fmaxf(o.z, 0.f); o.w = fmaxf(o.w, 0.f);
            }
            *(float4*)(C + (size_t)row * N + col0 + tc * 4) = o;
        }
    }
}

// ---------------- LayerNorm(128) + ReLU, in place ----------------
__global__ void ln_relu_kernel(float* __restrict__ x, const float* __restrict__ g,
                               const float* __restrict__ be)
{
    int row = blockIdx.x;
    int t = threadIdx.x;
    float v = x[(size_t)row * 128 + t];
    float s = v, sq = v * v;
    s = warp_sum(s); sq = warp_sum(sq);
    __shared__ float ss[4], ssq[4];
    if ((t & 31) == 0) { ss[t >> 5] = s; ssq[t >> 5] = sq; }
    __syncthreads();
    s  = ss[0] + ss[1] + ss[2] + ss[3];
    sq = ssq[0] + ssq[1] + ssq[2] + ssq[3];
    float mu  = s * (1.f / 128.f);
    float var = sq * (1.f / 128.f) - mu * mu;
    float r = rsqrtf(var + 1e-5f);
    float y = (v - mu) * r * g[t] + be[t];
    x[(size_t)row * 128 + t] = fmaxf(y, 0.f);
}

// ---------------- alpha_src[n,h] = sum_c hs[n, h*128+c] * a_s[h,c] ----------------
__global__ void alpha_src_kernel(const float* __restrict__ hs, const float* __restrict__ a,
                                 float* __restrict__ alp, int Nn)
{
    int wid  = (blockIdx.x * blockDim.x + threadIdx.x) >> 5;
    int lane = threadIdx.x & 31;
    int n = wid >> 1, h = wid & 1;
    if (n >= Nn) return;
    const float* hp = hs + (size_t)n * 256 + h * 128;
    const float* ap = a + h * 128;
    float acc = 0.f;
    #pragma unroll
    for (int q = 0; q < 4; q++) { int c = lane + 32 * q; acc += hp[c] * ap[c]; }
    acc = warp_sum(acc);
    if (lane == 0) alp[n * 2 + h] = acc;
}

// ---------------- vd[h,k] = sum_c Wd[k, h*128+c] * a_d[h,c] ----------------
__global__ void vd_kernel(const float* __restrict__ Wd, const float* __restrict__ ad,
                          float* __restrict__ vd)
{
    int t = threadIdx.x;        // 256
    int h = t >> 7, k = t & 127;
    const float* w = Wd + (size_t)k * 256 + h * 128;
    const float* a = ad + h * 128;
    float acc = 0.f;
    #pragma unroll 8
    for (int c = 0; c < 128; c++) acc += w[c] * a[c];
    vd[h * 128 + k] = acc;
}

// ---------------- alpha_dst via x_dst @ vd^T ----------------
__global__ void alpha_dst_kernel(const float* __restrict__ x, const float* __restrict__ vd,
                                 float* __restrict__ alp, int Nn)
{
    int wid  = (blockIdx.x * blockDim.x + threadIdx.x) >> 5;
    int lane = threadIdx.x & 31;
    if (wid >= Nn) return;
    const float* xp = x + (size_t)wid * 128;
    float a0 = 0.f, a1 = 0.f;
    #pragma unroll
    for (int q = 0; q < 4; q++) {
        int k = lane + 32 * q;
        float xv = xp[k];
        a0 += xv * vd[k];
        a1 += xv * vd[128 + k];
    }
    a0 = warp_sum(a0); a1 = warp_sum(a1);
    if (lane == 0) { alp[wid * 2] = a0; alp[wid * 2 + 1] = a1; }
}

// ---------------- init kernels ----------------
__global__ void init_md_kernel(int* __restrict__ m, float* __restrict__ den, int n2)
{
    int i = blockIdx.x * blockDim.x + threadIdx.x;
    if (i < n2) { m[i] = 0x80000000; den[i] = 0.f; }
}

__global__ void init_out_kernel(float* __restrict__ out, const float* __restrict__ b1,
                                const float* __restrict__ b2, int Nn)
{
    int i = blockIdx.x * blockDim.x + threadIdx.x;
    int tot = Nn * 256;
    if (i < tot) {
        int c = i & 255;
        float v = b1[c];
        if (b2) v += b2[c];
        out[i] = v;
    }
}

// ---------------- edge kernels ----------------
__global__ void edge_logits_kernel(const int* __restrict__ src, const int* __restrict__ dst,
                                   int Ereal, int Etot,
                                   const float* __restrict__ alps, const float* __restrict__ alpd,
                                   float* __restrict__ ge, int* __restrict__ gm)
{
    int idx = blockIdx.x * blockDim.x + threadIdx.x;
    if (idx >= Etot * 2) return;
    int eid = idx >> 1, h = idx & 1;
    int s, d;
    if (eid < Ereal) { s = src[eid]; d = dst[eid]; } else { s = d = eid - Ereal; }
    float e = alps[s * 2 + h] + alpd[d * 2 + h];
    e = e > 0.f ? e : 0.2f * e;
    ge[idx] = e;
    atomicMax(&gm[d * 2 + h], fenc(e));
}

__global__ void edge_exp_kernel(const int* __restrict__ src, const int* __restrict__ dst,
                                int Ereal, int Etot,
                                const float* __restrict__ ge, const int* __restrict__ gm,
                                float* __restrict__ gp, float* __restrict__ den)
{
    int idx = blockIdx.x * blockDim.x + threadIdx.x;
    if (idx >= Etot * 2) return;
    int eid = idx >> 1, h = idx & 1;
    int d;
    if (eid < Ereal) { d = dst[eid]; } else { d = eid - Ereal; }
    float m = fdec(gm[d * 2 + h]);
    float p = expf(ge[idx] - m);
    gp[idx] = p;
    atomicAdd(&den[d * 2 + h], p);
}

__global__ void edge_scatter_kernel(const int* __restrict__ src, const int* __restrict__ dst,
                                    int Ereal, int Etot,
                                    const float* __restrict__ gp, const float* __restrict__ den,
                                    const float* __restrict__ hs, float* __restrict__ out)
{
    int wid  = (blockIdx.x * blockDim.x + threadIdx.x) >> 5;
    int lane = threadIdx.x & 31;
    if (wid >= Etot) return;
    int s, d;
    if (wid < Ereal) { s = src[wid]; d = dst[wid]; } else { s = d = wid - Ereal; }
    float w0 = gp[wid * 2]     / (den[d * 2]     + 1e-16f);
    float w1 = gp[wid * 2 + 1] / (den[d * 2 + 1] + 1e-16f);
    const float4* hp = (const float4*)(hs + (size_t)s * 256);
    float* op = out + (size_t)d * 256;
    float4 v0 = hp[lane];
    atomicAdd(op + lane * 4 + 0, v0.x * w0);
    atomicAdd(op + lane * 4 + 1, v0.y * w0);
    atomicAdd(op + lane * 4 + 2, v0.z * w0);
    atomicAdd(op + lane * 4 + 3, v0.w * w0);
    float4 v1 = hp[32 + lane];
    atomicAdd(op + 128 + lane * 4 + 0, v1.x * w1);
    atomicAdd(op + 128 + lane * 4 + 1, v1.y * w1);
    atomicAdd(op + 128 + lane * 4 + 2, v1.z * w1);
    atomicAdd(op + 128 + lane * 4 + 3, v1.w * w1);
}

// ---------------- final small kernels ----------------
__global__ void q_kernel(const float* __restrict__ query, const float* __restrict__ Wq,
                         const float* __restrict__ bq, float* __restrict__ q)
{
    int j = threadIdx.x;   // 128
    float acc = bq[j];
    for (int k = 0; k < SBERT; k++) acc += query[k] * Wq[(size_t)k * 128 + j];
    q[j] = acc;
}

__global__ void scores_kernel(const float* __restrict__ emb, const float* __restrict__ q,
                              float* __restrict__ sc, int M)
{
    int wid  = (blockIdx.x * blockDim.x + threadIdx.x) >> 5;
    int lane = threadIdx.x & 31;
    if (wid >= M) return;
    const float* e = emb + (size_t)wid * 128;
    float acc = 0.f;
    #pragma unroll
    for (int qd = 0; qd < 4; qd++) { int k = lane + 32 * qd; acc += e[k] * q[k]; }
    acc = warp_sum(acc);
    if (lane == 0) sc[wid] = acc;
}

// ---------------- host ----------------
static void run_gat(const float* xsrc, int Nsrc, const float* xdst, int Ndst,
                    const int* esrc, const int* edst, int Ereal, int Etot,
                    const float* Ws, const float* Wd, const float* as_, const float* ad_,
                    float* outbuf,
                    float* hs, float* alps, float* alpd, int* gm, float* den,
                    float* ge, float* gp, float* vd)
{
    gemm_kernel<<<dim3((Nsrc + 63) / 64, 2), 256>>>(xsrc, Ws, nullptr, hs, Nsrc, 256, 128, 0);
    alpha_src_kernel<<<(Nsrc * 2 * 32 + 255) / 256, 256>>>(hs, as_, alps, Nsrc);
    vd_kernel<<<1, 256>>>(Wd, ad_, vd);
    alpha_dst_kernel<<<(Ndst * 32 + 255) / 256, 256>>>(xdst, vd, alpd, Ndst);
    init_md_kernel<<<(Ndst * 2 + 255) / 256, 256>>>(gm, den, Ndst * 2);
    edge_logits_kernel<<<(Etot * 2 + 255) / 256, 256>>>(esrc, edst, Ereal, Etot, alps, alpd, ge, gm);
    edge_exp_kernel<<<(Etot * 2 + 255) / 256, 256>>>(esrc, edst, Ereal, Etot, ge, gm, gp, den);
    edge_scatter_kernel<<<(Etot * 32 + 255) / 256, 256>>>(esrc, edst, Ereal, Etot, gp, den, hs, outbuf);
}

extern "C" void kernel_launch(void* const* d_in, const int* in_sizes, int n_in,
                              void* d_out, int out_size)
{
    const float* x_job    = (const float*)d_in[0];
    const float* x_skill  = (const float*)d_in[1];
    const int*   ei_js_s  = (const int*)d_in[2];
    const int*   ei_js_d  = (const int*)d_in[3];
    const int*   ei_sj_s  = (const int*)d_in[4];
    const int*   ei_sj_d  = (const int*)d_in[5];
    const int*   ei_ss_s  = (const int*)d_in[6];
    const int*   ei_ss_d  = (const int*)d_in[7];
    const float* query    = (const float*)d_in[8];
    const float* W0_job   = (const float*)d_in[9];
    const float* b0_job   = (const float*)d_in[10];
    const float* g0_job   = (const float*)d_in[11];
    const float* be0_job  = (const float*)d_in[12];
    const float* W0_skill = (const float*)d_in[13];
    const float* b0_skill = (const float*)d_in[14];
    const float* g0_skill = (const float*)d_in[15];
    const float* be0_skill= (const float*)d_in[16];
    const float* gat_Ws   = (const float*)d_in[17];
    const float* gat_Wd   = (const float*)d_in[18];
    const float* gat_as   = (const float*)d_in[19];
    const float* gat_ad   = (const float*)d_in[20];
    const float* gat_b    = (const float*)d_in[21];
    const float* inter_W  = (const float*)d_in[22];
    const float* inter_b  = (const float*)d_in[23];
    const float* Wjf      = (const float*)d_in[24];
    const float* bjf      = (const float*)d_in[25];
    const float* Wq       = (const float*)d_in[26];
    const float* bq       = (const float*)d_in[27];

    float* out     = (float*)d_out;
    float* scores  = out;                          // [NJ]
    float* job_emb = out + NJ;                     // [NJ, 128]
    float* qout    = out + NJ + (size_t)NJ * 128;  // [128]

    void* p;
    cudaGetSymbolAddress(&p, g_xj);   float* xj   = (float*)p;
    cudaGetSymbolAddress(&p, g_xs);   float* xs   = (float*)p;
    cudaGetSymbolAddress(&p, g_hs);   float* hs   = (float*)p;
    cudaGetSymbolAddress(&p, g_oj);   float* oj   = (float*)p;
    cudaGetSymbolAddress(&p, g_os);   float* os   = (float*)p;
    cudaGetSymbolAddress(&p, g_alps); float* alps = (float*)p;
    cudaGetSymbolAddress(&p, g_alpd); float* alpd = (float*)p;
    cudaGetSymbolAddress(&p, g_m);    int*   gm   = (int*)p;
    cudaGetSymbolAddress(&p, g_den);  float* den  = (float*)p;
    cudaGetSymbolAddress(&p, g_e);    float* ge   = (float*)p;
    cudaGetSymbolAddress(&p, g_p);    float* gp   = (float*)p;
    cudaGetSymbolAddress(&p, g_vd);   float* vd   = (float*)p;

    // ---- initial per-type linear + LN + relu ----
    gemm_kernel<<<dim3((NJ + 63) / 64, 1), 256>>>(x_job, W0_job, b0_job, xj, NJ, 128, SBERT, 0);
    ln_relu_kernel<<<NJ, 128>>>(xj, g0_job, be0_job);
    gemm_kernel<<<dim3((NS + 63) / 64, 1), 256>>>(x_skill, W0_skill, b0_skill, xs, NS, 128, SBERT, 0);
    ln_relu_kernel<<<NS, 128>>>(xs, g0_skill, be0_skill);

    for (int i = 0; i < 2; i++) {
        const float* Ws0 = gat_Ws + (size_t)(i * 3 + 0) * 128 * 256;
        const float* Ws1 = gat_Ws + (size_t)(i * 3 + 1) * 128 * 256;
        const float* Ws2 = gat_Ws + (size_t)(i * 3 + 2) * 128 * 256;
        const float* Wd0 = gat_Wd + (size_t)(i * 3 + 0) * 128 * 256;
        const float* Wd1 = gat_Wd + (size_t)(i * 3 + 1) * 128 * 256;
        const float* Wd2 = gat_Wd + (size_t)(i * 3 + 2) * 128 * 256;
        const float* as0 = gat_as + (size_t)(i * 3 + 0) * 256;
        const float* as1 = gat_as + (size_t)(i * 3 + 1) * 256;
        const float* as2 = gat_as + (size_t)(i * 3 + 2) * 256;
        const float* ad0 = gat_ad + (size_t)(i * 3 + 0) * 256;
        const float* ad1 = gat_ad + (size_t)(i * 3 + 1) * 256;
        const float* ad2 = gat_ad + (size_t)(i * 3 + 2) * 256;
        const float* b0  = gat_b  + (size_t)(i * 3 + 0) * 256;
        const float* b1  = gat_b  + (size_t)(i * 3 + 1) * 256;
        const float* b2  = gat_b  + (size_t)(i * 3 + 2) * 256;

        // o_s = gat_js + gat_ss (+both biases); init buffer with bias sum
        init_out_kernel<<<(NS * 256 + 255) / 256, 256>>>(os, b0, b2, NS);
        // job -> skill
        run_gat(xj, NJ, xs, NS, ei_js_s, ei_js_d, E_JS, E_JS,
                Ws0, Wd0, as0, ad0, os, hs, alps, alpd, gm, den, ge, gp, vd);
        // skill -> skill (with self loops)
        run_gat(xs, NS, xs, NS, ei_ss_s, ei_ss_d, E_SS, E_SS_T,
                Ws2, Wd2, as2, ad2, os, hs, alps, alpd, gm, den, ge, gp, vd);
        // o_j = gat_sj
        init_out_kernel<<<(NJ * 256 + 255) / 256, 256>>>(oj, b1, nullptr, NJ);
        run_gat(xs, NS, xj, NJ, ei_sj_s, ei_sj_d, E_SJ, E_SJ,
                Ws1, Wd1, as1, ad1, oj, hs, alps, alpd, gm, den, ge, gp, vd);

        // inter linear + relu (overwrites xj/xs for next layer)
        const float* iW0 = inter_W + (size_t)(i * 2 + 0) * 256 * 128;
        const float* iW1 = inter_W + (size_t)(i * 2 + 1) * 256 * 128;
        const float* ib0 = inter_b + (size_t)(i * 2 + 0) * 128;
        const float* ib1 = inter_b + (size_t)(i * 2 + 1) * 128;
        gemm_kernel<<<dim3((NJ + 63) / 64, 1), 256>>>(oj, iW0, ib0, xj, NJ, 128, 256, 1);
        gemm_kernel<<<dim3((NS + 63) / 64, 1), 256>>>(os, iW1, ib1, xs, NS, 128, 256, 1);
    }

    // ---- final projections ----
    gemm_kernel<<<dim3((NJ + 63) / 64, 1), 256>>>(xj, Wjf, bjf, job_emb, NJ, 128, 128, 0);
    q_kernel<<<1, 128>>>(query, Wq, bq, qout);
    scores_kernel<<<(NJ * 32 + 255) / 256, 256>>>(job_emb, qout, scores, NJ);
}

// round 5
// speedup vs baseline: 1.8864x; 1.8864x over previous
#include <cuda_runtime.h>
#include <cuda_bf16.h>
#include <math.h>

#define NJ 30000
#define NS 12000
#define E_JS 300000
#define E_SJ 300000
#define E_SS 150000
#define E_SS_T (E_SS + NS)
#define SBERT 384
#define HID 128
#define HHID 256
#define OUTD 128

// ---------------- scratch (device globals; no allocation allowed) ----------------
__device__ float g_xj[NJ * HID];
__device__ float g_xs[NS * HID];
__device__ float g_hs[NJ * HHID];
__device__ float g_oj[NJ * HHID];
__device__ float g_os[NS * HHID];
__device__ float g_alps[NJ * 2];
__device__ float g_alpd[NJ * 2];
__device__ float g_vd[2 * HID];
// CSR structures (built once per call; dst topology is layer-invariant)
__device__ int g_cnt_js[NS], g_off_js[NS], g_cur_js[NS];
__device__ int g_cnt_ss[NS], g_off_ss[NS], g_cur_ss[NS];
__device__ int g_cnt_sj[NJ], g_off_sj[NJ], g_cur_sj[NJ];
__device__ int g_csr_js[E_JS];
__device__ int g_csr_ss[E_SS_T];
__device__ int g_csr_sj[E_SJ];

// ---------------- helpers ----------------
__device__ __forceinline__ float warp_sum(float v) {
    #pragma unroll
    for (int o = 16; o; o >>= 1) v += __shfl_xor_sync(0xffffffffu, v, o);
    return v;
}

__device__ __forceinline__ unsigned long long pk2(float lo, float hi) {
    unsigned long long r;
    asm("mov.b64 %0, {%1, %2};" : "=l"(r) : "r"(__float_as_uint(lo)), "r"(__float_as_uint(hi)));
    return r;
}
__device__ __forceinline__ void upk2(unsigned long long v, float& lo, float& hi) {
    unsigned int a, b;
    asm("mov.b64 {%0, %1}, %2;" : "=r"(a), "=r"(b) : "l"(v));
    lo = __uint_as_float(a); hi = __uint_as_float(b);
}
__device__ __forceinline__ void fma2(unsigned long long& d, unsigned long long a, unsigned long long b) {
    asm("fma.rn.f32x2 %0, %1, %2, %0;" : "+l"(d) : "l"(a), "l"(b));
}

// ---------------- GEMM: C[M,N] = A[M,K] @ B[K,N] (+bias)(+relu) ----------------
// BM=64, BN=128, BK=16, 256 threads, 8x4 register tile via packed f32x2 FMA.
// Requires: K % 16 == 0, N % 128 == 0.
__global__ __launch_bounds__(256) void gemm_kernel(
    const float* __restrict__ A, const float* __restrict__ B,
    const float* __restrict__ bias, float* __restrict__ C,
    int M, int N, int K, int relu)
{
    __shared__ float As[16][68];   // padded, transposed: As[k][row]
    __shared__ float Bs[16][128];

    const int t   = threadIdx.x;
    const int tc  = t & 31;        // 32 thread-cols * 4 = 128
    const int tr  = t >> 5;        // 8 thread-rows * 8 = 64
    const int row0 = blockIdx.x * 64;
    const int col0 = blockIdx.y * 128;

    const int arow = t >> 2;       // 0..63
    const int akq  = (t & 3) * 4;  // 0,4,8,12
    const int bs0k = t >> 5;
    const int bs0c = (t & 31) * 4;
    const int bs1k = bs0k + 8;

    // acc2[i2][j]: packed rows (2*i2, 2*i2+1), column j (of this thread's 4 cols)
    unsigned long long acc2[4][4];
    #pragma unroll
    for (int i = 0; i < 4; i++)
        #pragma unroll
        for (int j = 0; j < 4; j++) acc2[i][j] = 0ull;

    for (int k0 = 0; k0 < K; k0 += 16) {
        float4 av = make_float4(0.f, 0.f, 0.f, 0.f);
        if (row0 + arow < M)
            av = *(const float4*)(A + (size_t)(row0 + arow) * K + k0 + akq);
        float4 bv0 = *(const float4*)(B + (size_t)(k0 + bs0k) * N + col0 + bs0c);
        float4 bv1 = *(const float4*)(B + (size_t)(k0 + bs1k) * N + col0 + bs0c);

        __syncthreads();
        As[akq + 0][arow] = av.x;
        As[akq + 1][arow] = av.y;
        As[akq + 2][arow] = av.z;
        As[akq + 3][arow] = av.w;
        *(float4*)&Bs[bs0k][bs0c] = bv0;
        *(float4*)&Bs[bs1k][bs0c] = bv1;
        __syncthreads();

        #pragma unroll
        for (int kk = 0; kk < 16; kk++) {
            float4 b  = *(float4*)&Bs[kk][tc * 4];
            float4 a0 = *(float4*)&As[kk][tr * 8];
            float4 a1 = *(float4*)&As[kk][tr * 8 + 4];
            unsigned long long ap[4];
            ap[0] = pk2(a0.x, a0.y); ap[1] = pk2(a0.z, a0.w);
            ap[2] = pk2(a1.x, a1.y); ap[3] = pk2(a1.z, a1.w);
            unsigned long long bd[4];
            bd[0] = pk2(b.x, b.x); bd[1] = pk2(b.y, b.y);
            bd[2] = pk2(b.z, b.z); bd[3] = pk2(b.w, b.w);
            #pragma unroll
            for (int i = 0; i < 4; i++) {
                fma2(acc2[i][0], ap[i], bd[0]);
                fma2(acc2[i][1], ap[i], bd[1]);
                fma2(acc2[i][2], ap[i], bd[2]);
                fma2(acc2[i][3], ap[i], bd[3]);
            }
        }
    }

    // unpack
    float acc[8][4];
    #pragma unroll
    for (int i = 0; i < 4; i++)
        #pragma unroll
        for (int j = 0; j < 4; j++)
            upk2(acc2[i][j], acc[2 * i][j], acc[2 * i + 1][j]);

    float4 bv = make_float4(0.f, 0.f, 0.f, 0.f);
    if (bias) bv = *(const float4*)(bias + col0 + tc * 4);
    #pragma unroll
    for (int i = 0; i < 8; i++) {
        int row = row0 + tr * 8 + i;
        if (row < M) {
            float4 o;
            o.x = acc[i][0] + bv.x;
            o.y = acc[i][1] + bv.y;
            o.z = acc[i][2] + bv.z;
            o.w = acc[i][3] + bv.w;
            if (relu) {
                o.x = fmaxf(o.x, 0.f); o.y = fmaxf(o.y, 0.f);
                o.z = fmaxf(o.z, 0.f); o.w = fmaxf(o.w, 0.f);
            }
            *(float4*)(C + (size_t)row * N + col0 + tc * 4) = o;
        }
    }
}

// ---------------- LayerNorm(128) + ReLU, in place ----------------
__global__ void ln_relu_kernel(float* __restrict__ x, const float* __restrict__ g,
                               const float* __restrict__ be)
{
    int row = blockIdx.x;
    int t = threadIdx.x;
    float v = x[(size_t)row * 128 + t];
    float s = v, sq = v * v;
    s = warp_sum(s); sq = warp_sum(sq);
    __shared__ float ss[4], ssq[4];
    if ((t & 31) == 0) { ss[t >> 5] = s; ssq[t >> 5] = sq; }
    __syncthreads();
    s  = ss[0] + ss[1] + ss[2] + ss[3];
    sq = ssq[0] + ssq[1] + ssq[2] + ssq[3];
    float mu  = s * (1.f / 128.f);
    float var = sq * (1.f / 128.f) - mu * mu;
    float r = rsqrtf(var + 1e-5f);
    float y = (v - mu) * r * g[t] + be[t];
    x[(size_t)row * 128 + t] = fmaxf(y, 0.f);
}

// ---------------- alpha_src[n,h] = sum_c hs[n, h*128+c] * a_s[h,c] ----------------
__global__ void alpha_src_kernel(const float* __restrict__ hs, const float* __restrict__ a,
                                 float* __restrict__ alp, int Nn)
{
    int wid  = (blockIdx.x * blockDim.x + threadIdx.x) >> 5;
    int lane = threadIdx.x & 31;
    int n = wid >> 1, h = wid & 1;
    if (n >= Nn) return;
    const float* hp = hs + (size_t)n * 256 + h * 128;
    const float* ap = a + h * 128;
    float acc = 0.f;
    #pragma unroll
    for (int q = 0; q < 4; q++) { int c = lane + 32 * q; acc += hp[c] * ap[c]; }
    acc = warp_sum(acc);
    if (lane == 0) alp[n * 2 + h] = acc;
}

// ---------------- vd[h,k] = sum_c Wd[k, h*128+c] * a_d[h,c] ----------------
__global__ void vd_kernel(const float* __restrict__ Wd, const float* __restrict__ ad,
                          float* __restrict__ vd)
{
    int t = threadIdx.x;        // 256
    int h = t >> 7, k = t & 127;
    const float* w = Wd + (size_t)k * 256 + h * 128;
    const float* a = ad + h * 128;
    float acc = 0.f;
    #pragma unroll 8
    for (int c = 0; c < 128; c++) acc += w[c] * a[c];
    vd[h * 128 + k] = acc;
}

// ---------------- alpha_dst via x_dst @ vd^T ----------------
__global__ void alpha_dst_kernel(const float* __restrict__ x, const float* __restrict__ vd,
                                 float* __restrict__ alp, int Nn)
{
    int wid  = (blockIdx.x * blockDim.x + threadIdx.x) >> 5;
    int lane = threadIdx.x & 31;
    if (wid >= Nn) return;
    const float* xp = x + (size_t)wid * 128;
    float a0 = 0.f, a1 = 0.f;
    #pragma unroll
    for (int q = 0; q < 4; q++) {
        int k = lane + 32 * q;
        float xv = xp[k];
        a0 += xv * vd[k];
        a1 += xv * vd[128 + k];
    }
    a0 = warp_sum(a0); a1 = warp_sum(a1);
    if (lane == 0) { alp[wid * 2] = a0; alp[wid * 2 + 1] = a1; }
}

// ---------------- CSR build ----------------
__global__ void zero2_kernel(int* __restrict__ a, int* __restrict__ b, int n)
{
    int i = blockIdx.x * blockDim.x + threadIdx.x;
    if (i < n) { a[i] = 0; b[i] = 0; }
}

__global__ void hist_kernel(const int* __restrict__ dst, int Ereal, int Etot,
                            int* __restrict__ cnt)
{
    int e = blockIdx.x * blockDim.x + threadIdx.x;
    if (e >= Etot) return;
    int d = (e < Ereal) ? dst[e] : e - Ereal;
    atomicAdd(&cnt[d], 1);
}

__global__ void scan_kernel(const int* __restrict__ cnt, int* __restrict__ off, int n)
{
    __shared__ int sh_carry;
    __shared__ int wsum[32];
    int lane = threadIdx.x & 31, wid = threadIdx.x >> 5;
    if (threadIdx.x == 0) sh_carry = 0;
    __syncthreads();
    for (int base = 0; base < n; base += 1024) {
        int i = base + threadIdx.x;
        int x = (i < n) ? cnt[i] : 0;
        int v = x;
        #pragma unroll
        for (int o = 1; o < 32; o <<= 1) {
            int tv = __shfl_up_sync(0xffffffffu, v, o);
            if (lane >= o) v += tv;
        }
        if (lane == 31) wsum[wid] = v;
        __syncthreads();
        if (wid == 0) {
            int s = wsum[lane];
            #pragma unroll
            for (int o = 1; o < 32; o <<= 1) {
                int tv = __shfl_up_sync(0xffffffffu, s, o);
                if (lane >= o) s += tv;
            }
            wsum[lane] = s;
        }
        __syncthreads();
        int pre = wid ? wsum[wid - 1] : 0;
        int incl = v + pre;
        int carry = sh_carry;
        if (i < n) off[i] = carry + incl - x;
        __syncthreads();
        if (threadIdx.x == 1023) sh_carry = carry + incl;
        __syncthreads();
    }
}

__global__ void fill_kernel(const int* __restrict__ src, const int* __restrict__ dst,
                            int Ereal, int Etot, const int* __restrict__ off,
                            int* __restrict__ cur, int* __restrict__ csrc)
{
    int e = blockIdx.x * blockDim.x + threadIdx.x;
    if (e >= Etot) return;
    int s, d;
    if (e < Ereal) { s = src[e]; d = dst[e]; } else { s = d = e - Ereal; }
    int pos = off[d] + atomicAdd(&cur[d], 1);
    csrc[pos] = s;
}

// ---------------- fused per-dst GAT aggregation (single pass, no max) ----------------
// warp per dst node: out[d] = sum_e exp(e)*hs[src_e] / sum_e exp(e) + bias  (+= existing if accumulate)
__global__ void gat_aggregate_kernel(const int* __restrict__ off, const int* __restrict__ cnt,
                                     const int* __restrict__ csrc,
                                     const float* __restrict__ hs,
                                     const float* __restrict__ alps,
                                     const float* __restrict__ alpd,
                                     const float* __restrict__ bias,
                                     float* __restrict__ out, int Ndst, int accumulate)
{
    int w    = (blockIdx.x * blockDim.x + threadIdx.x) >> 5;
    int lane = threadIdx.x & 31;
    if (w >= Ndst) return;
    int o = off[w], deg = cnt[w];
    float ad0 = alpd[w * 2], ad1 = alpd[w * 2 + 1];
    float4 acc0 = make_float4(0.f, 0.f, 0.f, 0.f);
    float4 acc1 = make_float4(0.f, 0.f, 0.f, 0.f);
    float den0 = 0.f, den1 = 0.f;
    const float2* ap = (const float2*)alps;

    int s = (deg > 0) ? csrc[o] : 0;
    for (int k = 0; k < deg; k++) {
        int snext = (k + 1 < deg) ? csrc[o + k + 1] : 0;
        float2 av = ap[s];
        float e0 = av.x + ad0; e0 = e0 > 0.f ? e0 : 0.2f * e0;
        float e1 = av.y + ad1; e1 = e1 > 0.f ? e1 : 0.2f * e1;
        float p0 = __expf(e0), p1 = __expf(e1);
        const float4* hp = (const float4*)(hs + (size_t)s * 256);
        float4 v0 = hp[lane];
        float4 v1 = hp[32 + lane];
        acc0.x = fmaf(p0, v0.x, acc0.x); acc0.y = fmaf(p0, v0.y, acc0.y);
        acc0.z = fmaf(p0, v0.z, acc0.z); acc0.w = fmaf(p0, v0.w, acc0.w);
        acc1.x = fmaf(p1, v1.x, acc1.x); acc1.y = fmaf(p1, v1.y, acc1.y);
        acc1.z = fmaf(p1, v1.z, acc1.z); acc1.w = fmaf(p1, v1.w, acc1.w);
        den0 += p0; den1 += p1;
        s = snext;
    }
    float r0 = 1.f / (den0 + 1e-16f);
    float r1 = 1.f / (den1 + 1e-16f);
    const float4* bp = (const float4*)bias;
    float4 b0 = bp[lane], b1 = bp[32 + lane];
    float4 o0, o1;
    o0.x = fmaf(acc0.x, r0, b0.x); o0.y = fmaf(acc0.y, r0, b0.y);
    o0.z = fmaf(acc0.z, r0, b0.z); o0.w = fmaf(acc0.w, r0, b0.w);
    o1.x = fmaf(acc1.x, r1, b1.x); o1.y = fmaf(acc1.y, r1, b1.y);
    o1.z = fmaf(acc1.z, r1, b1.z); o1.w = fmaf(acc1.w, r1, b1.w);
    float4* op = (float4*)(out + (size_t)w * 256);
    if (accumulate) {
        float4 c0 = op[lane], c1 = op[32 + lane];
        o0.x += c0.x; o0.y += c0.y; o0.z += c0.z; o0.w += c0.w;
        o1.x += c1.x; o1.y += c1.y; o1.z += c1.z; o1.w += c1.w;
    }
    op[lane] = o0;
    op[32 + lane] = o1;
}

// ---------------- final small kernels ----------------
__global__ void q_kernel(const float* __restrict__ query, const float* __restrict__ Wq,
                         const float* __restrict__ bq, float* __restrict__ q)
{
    int j = threadIdx.x;   // 128
    float acc = bq[j];
    for (int k = 0; k < SBERT; k++) acc += query[k] * Wq[(size_t)k * 128 + j];
    q[j] = acc;
}

__global__ void scores_kernel(const float* __restrict__ emb, const float* __restrict__ q,
                              float* __restrict__ sc, int M)
{
    int wid  = (blockIdx.x * blockDim.x + threadIdx.x) >> 5;
    int lane = threadIdx.x & 31;
    if (wid >= M) return;
    const float* e = emb + (size_t)wid * 128;
    float acc = 0.f;
    #pragma unroll
    for (int qd = 0; qd < 4; qd++) { int k = lane + 32 * qd; acc += e[k] * q[k]; }
    acc = warp_sum(acc);
    if (lane == 0) sc[wid] = acc;
}

// ---------------- host ----------------
static void build_csr(const int* esrc, const int* edst, int Ereal, int Etot, int Ndst,
                      int* cnt, int* off, int* cur, int* csrc)
{
    zero2_kernel<<<(Ndst + 255) / 256, 256>>>(cnt, cur, Ndst);
    hist_kernel<<<(Etot + 255) / 256, 256>>>(edst, Ereal, Etot, cnt);
    scan_kernel<<<1, 1024>>>(cnt, off, Ndst);
    fill_kernel<<<(Etot + 255) / 256, 256>>>(esrc, edst, Ereal, Etot, off, cur, csrc);
}

static void run_gat(const float* xsrc, int Nsrc, const float* xdst, int Ndst,
                    const int* off, const int* cnt, const int* csrc,
                    const float* Ws, const float* Wd, const float* as_, const float* ad_,
                    const float* bias, float* outbuf, int accumulate,
                    float* hs, float* alps, float* alpd, float* vd)
{
    gemm_kernel<<<dim3((Nsrc + 63) / 64, 2), 256>>>(xsrc, Ws, nullptr, hs, Nsrc, 256, 128, 0);
    alpha_src_kernel<<<(Nsrc * 2 * 32 + 255) / 256, 256>>>(hs, as_, alps, Nsrc);
    vd_kernel<<<1, 256>>>(Wd, ad_, vd);
    alpha_dst_kernel<<<(Ndst * 32 + 255) / 256, 256>>>(xdst, vd, alpd, Ndst);
    gat_aggregate_kernel<<<(Ndst * 32 + 255) / 256, 256>>>(off, cnt, csrc, hs, alps, alpd,
                                                           bias, outbuf, Ndst, accumulate);
}

extern "C" void kernel_launch(void* const* d_in, const int* in_sizes, int n_in,
                              void* d_out, int out_size)
{
    const float* x_job    = (const float*)d_in[0];
    const float* x_skill  = (const float*)d_in[1];
    const int*   ei_js_s  = (const int*)d_in[2];
    const int*   ei_js_d  = (const int*)d_in[3];
    const int*   ei_sj_s  = (const int*)d_in[4];
    const int*   ei_sj_d  = (const int*)d_in[5];
    const int*   ei_ss_s  = (const int*)d_in[6];
    const int*   ei_ss_d  = (const int*)d_in[7];
    const float* query    = (const float*)d_in[8];
    const float* W0_job   = (const float*)d_in[9];
    const float* b0_job   = (const float*)d_in[10];
    const float* g0_job   = (const float*)d_in[11];
    const float* be0_job  = (const float*)d_in[12];
    const float* W0_skill = (const float*)d_in[13];
    const float* b0_skill = (const float*)d_in[14];
    const float* g0_skill = (const float*)d_in[15];
    const float* be0_skill= (const float*)d_in[16];
    const float* gat_Ws   = (const float*)d_in[17];
    const float* gat_Wd   = (const float*)d_in[18];
    const float* gat_as   = (const float*)d_in[19];
    const float* gat_ad   = (const float*)d_in[20];
    const float* gat_b    = (const float*)d_in[21];
    const float* inter_W  = (const float*)d_in[22];
    const float* inter_b  = (const float*)d_in[23];
    const float* Wjf      = (const float*)d_in[24];
    const float* bjf      = (const float*)d_in[25];
    const float* Wq       = (const float*)d_in[26];
    const float* bq       = (const float*)d_in[27];

    float* out     = (float*)d_out;
    float* scores  = out;                          // [NJ]
    float* job_emb = out + NJ;                     // [NJ, 128]
    float* qout    = out + NJ + (size_t)NJ * 128;  // [128]

    void* p;
    cudaGetSymbolAddress(&p, g_xj);   float* xj   = (float*)p;
    cudaGetSymbolAddress(&p, g_xs);   float* xs   = (float*)p;
    cudaGetSymbolAddress(&p, g_hs);   float* hs   = (float*)p;
    cudaGetSymbolAddress(&p, g_oj);   float* oj   = (float*)p;
    cudaGetSymbolAddress(&p, g_os);   float* os   = (float*)p;
    cudaGetSymbolAddress(&p, g_alps); float* alps = (float*)p;
    cudaGetSymbolAddress(&p, g_alpd); float* alpd = (float*)p;
    cudaGetSymbolAddress(&p, g_vd);   float* vd   = (float*)p;
    cudaGetSymbolAddress(&p, g_cnt_js); int* cnt_js = (int*)p;
    cudaGetSymbolAddress(&p, g_off_js); int* off_js = (int*)p;
    cudaGetSymbolAddress(&p, g_cur_js); int* cur_js = (int*)p;
    cudaGetSymbolAddress(&p, g_cnt_ss); int* cnt_ss = (int*)p;
    cudaGetSymbolAddress(&p, g_off_ss); int* off_ss = (int*)p;
    cudaGetSymbolAddress(&p, g_cur_ss); int* cur_ss = (int*)p;
    cudaGetSymbolAddress(&p, g_cnt_sj); int* cnt_sj = (int*)p;
    cudaGetSymbolAddress(&p, g_off_sj); int* off_sj = (int*)p;
    cudaGetSymbolAddress(&p, g_cur_sj); int* cur_sj = (int*)p;
    cudaGetSymbolAddress(&p, g_csr_js); int* csr_js = (int*)p;
    cudaGetSymbolAddress(&p, g_csr_ss); int* csr_ss = (int*)p;
    cudaGetSymbolAddress(&p, g_csr_sj); int* csr_sj = (int*)p;

    // ---- CSR build (topology identical for both layers) ----
    build_csr(ei_js_s, ei_js_d, E_JS, E_JS,   NS, cnt_js, off_js, cur_js, csr_js);
    build_csr(ei_ss_s, ei_ss_d, E_SS, E_SS_T, NS, cnt_ss, off_ss, cur_ss, csr_ss);
    build_csr(ei_sj_s, ei_sj_d, E_SJ, E_SJ,   NJ, cnt_sj, off_sj, cur_sj, csr_sj);

    // ---- initial per-type linear + LN + relu ----
    gemm_kernel<<<dim3((NJ + 63) / 64, 1), 256>>>(x_job, W0_job, b0_job, xj, NJ, 128, SBERT, 0);
    ln_relu_kernel<<<NJ, 128>>>(xj, g0_job, be0_job);
    gemm_kernel<<<dim3((NS + 63) / 64, 1), 256>>>(x_skill, W0_skill, b0_skill, xs, NS, 128, SBERT, 0);
    ln_relu_kernel<<<NS, 128>>>(xs, g0_skill, be0_skill);

    for (int i = 0; i < 2; i++) {
        const float* Ws0 = gat_Ws + (size_t)(i * 3 + 0) * 128 * 256;
        const float* Ws1 = gat_Ws + (size_t)(i * 3 + 1) * 128 * 256;
        const float* Ws2 = gat_Ws + (size_t)(i * 3 + 2) * 128 * 256;
        const float* Wd0 = gat_Wd + (size_t)(i * 3 + 0) * 128 * 256;
        const float* Wd1 = gat_Wd + (size_t)(i * 3 + 1) * 128 * 256;
        const float* Wd2 = gat_Wd + (size_t)(i * 3 + 2) * 128 * 256;
        const float* as0 = gat_as + (size_t)(i * 3 + 0) * 256;
        const float* as1 = gat_as + (size_t)(i * 3 + 1) * 256;
        const float* as2 = gat_as + (size_t)(i * 3 + 2) * 256;
        const float* ad0 = gat_ad + (size_t)(i * 3 + 0) * 256;
        const float* ad1 = gat_ad + (size_t)(i * 3 + 1) * 256;
        const float* ad2 = gat_ad + (size_t)(i * 3 + 2) * 256;
        const float* b0  = gat_b  + (size_t)(i * 3 + 0) * 256;
        const float* b1  = gat_b  + (size_t)(i * 3 + 1) * 256;
        const float* b2  = gat_b  + (size_t)(i * 3 + 2) * 256;

        // o_s = gat_js(...) + gat_ss(...)  (HeteroConv sum; biases folded in)
        run_gat(xj, NJ, xs, NS, off_js, cnt_js, csr_js,
                Ws0, Wd0, as0, ad0, b0, os, 0, hs, alps, alpd, vd);
        run_gat(xs, NS, xs, NS, off_ss, cnt_ss, csr_ss,
                Ws2, Wd2, as2, ad2, b2, os, 1, hs, alps, alpd, vd);
        // o_j = gat_sj(...)
        run_gat(xs, NS, xj, NJ, off_sj, cnt_sj, csr_sj,
                Ws1, Wd1, as1, ad1, b1, oj, 0, hs, alps, alpd, vd);

        // inter linear + relu (overwrites xj/xs for next layer)
        const float* iW0 = inter_W + (size_t)(i * 2 + 0) * 256 * 128;
        const float* iW1 = inter_W + (size_t)(i * 2 + 1) * 256 * 128;
        const float* ib0 = inter_b + (size_t)(i * 2 + 0) * 128;
        const float* ib1 = inter_b + (size_t)(i * 2 + 1) * 128;
        gemm_kernel<<<dim3((NJ + 63) / 64, 1), 256>>>(oj, iW0, ib0, xj, NJ, 128, 256, 1);
        gemm_kernel<<<dim3((NS + 63) / 64, 1), 256>>>(os, iW1, ib1, xs, NS, 128, 256, 1);
    }

    // ---- final projections ----
    gemm_kernel<<<dim3((NJ + 63) / 64, 1), 256>>>(xj, Wjf, bjf, job_emb, NJ, 128, 128, 0);
    q_kernel<<<1, 128>>>(query, Wq, bq, qout);
    scores_kernel<<<(NJ * 32 + 255) / 256, 256>>>(job_emb, qout, scores, NJ);
}

// round 6
// speedup vs baseline: 2.4838x; 1.3167x over previous
#include <cuda_runtime.h>
#include <cuda_bf16.h>
#include <math.h>

#define NJ 30000
#define NS 12000
#define E_JS 300000
#define E_SJ 300000
#define E_SS 150000
#define E_SS_T (E_SS + NS)
#define E_ALL (E_JS + E_SS_T + E_SJ)
#define SBERT 384
#define HID 128
#define HHID 256

// ---------------- scratch (device globals; no allocation allowed) ----------------
__device__ float g_xj[NJ * HID];
__device__ float g_xs[NS * HID];
__device__ float g_hs0[NJ * HHID];   // js src features (jobs)
__device__ float g_hs1[NS * HHID];   // sj src features (skills)
__device__ float g_hs2[NS * HHID];   // ss src features (skills)
__device__ float g_oj[NJ * HHID];
__device__ float g_os[NS * HHID];
__device__ float g_alps0[NJ * 2], g_alps1[NS * 2], g_alps2[NS * 2];
__device__ float g_alpd0[NS * 2], g_alpd1[NJ * 2], g_alpd2[NS * 2];
__device__ float g_vd[3 * 256];
// CSR structures
__device__ int g_cnt_js[NS], g_off_js[NS], g_cur_js[NS];
__device__ int g_cnt_ss[NS], g_off_ss[NS], g_cur_ss[NS];
__device__ int g_cnt_sj[NJ], g_off_sj[NJ], g_cur_sj[NJ];
__device__ int g_csr_js[E_JS];
__device__ int g_csr_ss[E_SS_T];
__device__ int g_csr_sj[E_SJ];

// ---------------- helpers ----------------
__device__ __forceinline__ float warp_sum(float v) {
    #pragma unroll
    for (int o = 16; o; o >>= 1) v += __shfl_xor_sync(0xffffffffu, v, o);
    return v;
}
__device__ __forceinline__ unsigned long long pk2(float lo, float hi) {
    unsigned long long r;
    asm("mov.b64 %0, {%1, %2};" : "=l"(r) : "r"(__float_as_uint(lo)), "r"(__float_as_uint(hi)));
    return r;
}
__device__ __forceinline__ void upk2(unsigned long long v, float& lo, float& hi) {
    unsigned int a, b;
    asm("mov.b64 {%0, %1}, %2;" : "=r"(a), "=r"(b) : "l"(v));
    lo = __uint_as_float(a); hi = __uint_as_float(b);
}
__device__ __forceinline__ void fma2(unsigned long long& d, unsigned long long a, unsigned long long b) {
    asm("fma.rn.f32x2 %0, %1, %2, %0;" : "+l"(d) : "l"(a), "l"(b));
}

// ---------------- batched GEMM: up to 3 jobs selected by blockIdx.z ----------------
struct GJob { const float* A; const float* B; const float* bias; float* C; int M; };

__global__ __launch_bounds__(256) void gemm3_kernel(
    GJob j0, GJob j1, GJob j2, int N, int K, int relu)
{
    GJob jb = (blockIdx.z == 0) ? j0 : (blockIdx.z == 1) ? j1 : j2;
    const int row0 = blockIdx.x * 64;
    if (row0 >= jb.M) return;
    const float* __restrict__ A = jb.A;
    const float* __restrict__ B = jb.B;
    const int M = jb.M;

    __shared__ float As[16][68];   // transposed: As[k][row]; row-start 16B aligned
    __shared__ float Bs[16][128];

    const int t   = threadIdx.x;
    const int tc  = t & 31;
    const int tr  = t >> 5;
    const int col0 = blockIdx.y * 128;

    const int arow = t >> 2;
    const int akq  = (t & 3) * 4;
    const int bs0k = t >> 5;
    const int bs0c = (t & 31) * 4;
    const int bs1k = bs0k + 8;

    unsigned long long acc2[4][4];
    #pragma unroll
    for (int i = 0; i < 4; i++)
        #pragma unroll
        for (int j = 0; j < 4; j++) acc2[i][j] = 0ull;

    for (int k0 = 0; k0 < K; k0 += 16) {
        float4 av = make_float4(0.f, 0.f, 0.f, 0.f);
        if (row0 + arow < M)
            av = *(const float4*)(A + (size_t)(row0 + arow) * K + k0 + akq);
        float4 bv0 = *(const float4*)(B + (size_t)(k0 + bs0k) * N + col0 + bs0c);
        float4 bv1 = *(const float4*)(B + (size_t)(k0 + bs1k) * N + col0 + bs0c);

        __syncthreads();
        As[akq + 0][arow] = av.x;
        As[akq + 1][arow] = av.y;
        As[akq + 2][arow] = av.z;
        As[akq + 3][arow] = av.w;
        *(float4*)&Bs[bs0k][bs0c] = bv0;
        *(float4*)&Bs[bs1k][bs0c] = bv1;
        __syncthreads();

        #pragma unroll
        for (int kk = 0; kk < 16; kk++) {
            float4 b = *(float4*)&Bs[kk][tc * 4];
            // adjacent-row pairs are already packed in shared memory
            ulonglong2 apA = *(ulonglong2*)&As[kk][tr * 8];
            ulonglong2 apB = *(ulonglong2*)&As[kk][tr * 8 + 4];
            unsigned long long ap0 = apA.x, ap1 = apA.y, ap2 = apB.x, ap3 = apB.y;
            unsigned long long bd0 = pk2(b.x, b.x);
            unsigned long long bd1 = pk2(b.y, b.y);
            unsigned long long bd2 = pk2(b.z, b.z);
            unsigned long long bd3 = pk2(b.w, b.w);
            fma2(acc2[0][0], ap0, bd0); fma2(acc2[0][1], ap0, bd1);
            fma2(acc2[0][2], ap0, bd2); fma2(acc2[0][3], ap0, bd3);
            fma2(acc2[1][0], ap1, bd0); fma2(acc2[1][1], ap1, bd1);
            fma2(acc2[1][2], ap1, bd2); fma2(acc2[1][3], ap1, bd3);
            fma2(acc2[2][0], ap2, bd0); fma2(acc2[2][1], ap2, bd1);
            fma2(acc2[2][2], ap2, bd2); fma2(acc2[2][3], ap2, bd3);
            fma2(acc2[3][0], ap3, bd0); fma2(acc2[3][1], ap3, bd1);
            fma2(acc2[3][2], ap3, bd2); fma2(acc2[3][3], ap3, bd3);
        }
    }

    float acc[8][4];
    #pragma unroll
    for (int i = 0; i < 4; i++)
        #pragma unroll
        for (int j = 0; j < 4; j++)
            upk2(acc2[i][j], acc[2 * i][j], acc[2 * i + 1][j]);

    float4 bv = make_float4(0.f, 0.f, 0.f, 0.f);
    if (jb.bias) bv = *(const float4*)(jb.bias + col0 + tc * 4);
    #pragma unroll
    for (int i = 0; i < 8; i++) {
        int row = row0 + tr * 8 + i;
        if (row < M) {
            float4 o;
            o.x = acc[i][0] + bv.x;
            o.y = acc[i][1] + bv.y;
            o.z = acc[i][2] + bv.z;
            o.w = acc[i][3] + bv.w;
            if (relu) {
                o.x = fmaxf(o.x, 0.f); o.y = fmaxf(o.y, 0.f);
                o.z = fmaxf(o.z, 0.f); o.w = fmaxf(o.w, 0.f);
            }
            *(float4*)(jb.C + (size_t)row * N + col0 + tc * 4) = o;
        }
    }
}

// ---------------- batched LayerNorm(128) + ReLU, in place ----------------
__global__ void ln_relu2_kernel(float* __restrict__ xj, const float* __restrict__ gj,
                                const float* __restrict__ bej,
                                float* __restrict__ xs, const float* __restrict__ gs,
                                const float* __restrict__ bes)
{
    int row = blockIdx.x;
    int t = threadIdx.x;
    float* x; const float* g; const float* be;
    if (row < NJ) { x = xj + (size_t)row * 128; g = gj; be = bej; }
    else          { x = xs + (size_t)(row - NJ) * 128; g = gs; be = bes; }
    float v = x[t];
    float s = v, sq = v * v;
    s = warp_sum(s); sq = warp_sum(sq);
    __shared__ float ss[4], ssq[4];
    if ((t & 31) == 0) { ss[t >> 5] = s; ssq[t >> 5] = sq; }
    __syncthreads();
    s  = ss[0] + ss[1] + ss[2] + ss[3];
    sq = ssq[0] + ssq[1] + ssq[2] + ssq[3];
    float mu  = s * (1.f / 128.f);
    float var = sq * (1.f / 128.f) - mu * mu;
    float r = rsqrtf(var + 1e-5f);
    float y = (v - mu) * r * g[t] + be[t];
    x[t] = fmaxf(y, 0.f);
}

// ---------------- batched alpha_src over 3 relations ----------------
// warp per (node, head); segments: rel0 jobs (hs0, as0), rel1 skills (hs1, as1), rel2 skills (hs2, as2)
__global__ void alpha_src3_kernel(const float* __restrict__ hs0, const float* __restrict__ as0,
                                  float* __restrict__ alps0,
                                  const float* __restrict__ hs1, const float* __restrict__ as1,
                                  float* __restrict__ alps1,
                                  const float* __restrict__ hs2, const float* __restrict__ as2,
                                  float* __restrict__ alps2)
{
    int wid  = (blockIdx.x * blockDim.x + threadIdx.x) >> 5;
    int lane = threadIdx.x & 31;
    const float* hs; const float* a; float* alp; int n;
    if (wid < NJ * 2)               { hs = hs0; a = as0; alp = alps0; n = wid; }
    else if (wid < (NJ + NS) * 2)   { hs = hs1; a = as1; alp = alps1; n = wid - NJ * 2; }
    else if (wid < (NJ + 2*NS) * 2) { hs = hs2; a = as2; alp = alps2; n = wid - (NJ + NS) * 2; }
    else return;
    int node = n >> 1, h = n & 1;
    const float* hp = hs + (size_t)node * 256 + h * 128;
    const float* ap = a + h * 128;
    float acc = 0.f;
    #pragma unroll
    for (int q = 0; q < 4; q++) { int c = lane + 32 * q; acc += hp[c] * ap[c]; }
    acc = warp_sum(acc);
    if (lane == 0) alp[node * 2 + h] = acc;
}

// ---------------- batched vd: vd[r][h*128+k] = sum_c Wd_r[k, h*128+c] * ad_r[h,c] ----------------
__global__ void vd3_kernel(const float* __restrict__ Wd, const float* __restrict__ ad,
                           float* __restrict__ vd)
{
    int r = blockIdx.x;           // relation 0..2
    int t = threadIdx.x;          // 256
    int h = t >> 7, k = t & 127;
    const float* w = Wd + (size_t)r * 128 * 256 + (size_t)k * 256 + h * 128;
    const float* a = ad + (size_t)r * 256 + h * 128;
    float acc = 0.f;
    #pragma unroll 8
    for (int c = 0; c < 128; c++) acc += w[c] * a[c];
    vd[r * 256 + h * 128 + k] = acc;
}

// ---------------- batched alpha_dst over 3 relations ----------------
__global__ void alpha_dst3_kernel(const float* __restrict__ xs, const float* __restrict__ xj,
                                  const float* __restrict__ vd,
                                  float* __restrict__ alpd0, float* __restrict__ alpd1,
                                  float* __restrict__ alpd2)
{
    int wid  = (blockIdx.x * blockDim.x + threadIdx.x) >> 5;
    int lane = threadIdx.x & 31;
    const float* x; const float* v; float* alp; int n;
    if (wid < NS)            { x = xs; v = vd;       alp = alpd0; n = wid; }
    else if (wid < NS + NJ)  { x = xj; v = vd + 256; alp = alpd1; n = wid - NS; }
    else if (wid < 2*NS + NJ){ x = xs; v = vd + 512; alp = alpd2; n = wid - NS - NJ; }
    else return;
    const float* xp = x + (size_t)n * 128;
    float a0 = 0.f, a1 = 0.f;
    #pragma unroll
    for (int q = 0; q < 4; q++) {
        int k = lane + 32 * q;
        float xv = xp[k];
        a0 += xv * v[k];
        a1 += xv * v[128 + k];
    }
    a0 = warp_sum(a0); a1 = warp_sum(a1);
    if (lane == 0) { alp[n * 2] = a0; alp[n * 2 + 1] = a1; }
}

// ---------------- CSR build (batched) ----------------
__global__ void csr_zero_kernel(int* cnt_js, int* cur_js, int* cnt_ss, int* cur_ss,
                                int* cnt_sj, int* cur_sj)
{
    int i = blockIdx.x * blockDim.x + threadIdx.x;
    if (i < NS) { cnt_js[i] = 0; cur_js[i] = 0; cnt_ss[i] = 0; cur_ss[i] = 0; }
    if (i < NJ) { cnt_sj[i] = 0; cur_sj[i] = 0; }
}

__global__ void hist3_kernel(const int* __restrict__ js_d, const int* __restrict__ ss_d,
                             const int* __restrict__ sj_d,
                             int* __restrict__ cnt_js, int* __restrict__ cnt_ss,
                             int* __restrict__ cnt_sj)
{
    int e = blockIdx.x * blockDim.x + threadIdx.x;
    if (e >= E_ALL) return;
    if (e < E_JS)                  atomicAdd(&cnt_js[js_d[e]], 1);
    else if (e < E_JS + E_SS)      atomicAdd(&cnt_ss[ss_d[e - E_JS]], 1);
    else if (e < E_JS + E_SS + NS) atomicAdd(&cnt_ss[e - E_JS - E_SS], 1);
    else                           atomicAdd(&cnt_sj[sj_d[e - E_JS - E_SS_T]], 1);
}

__global__ void scan3_kernel(const int* __restrict__ cnt_js, int* __restrict__ off_js,
                             const int* __restrict__ cnt_ss, int* __restrict__ off_ss,
                             const int* __restrict__ cnt_sj, int* __restrict__ off_sj)
{
    const int* cnt; int* off; int n;
    if (blockIdx.x == 0)      { cnt = cnt_js; off = off_js; n = NS; }
    else if (blockIdx.x == 1) { cnt = cnt_ss; off = off_ss; n = NS; }
    else                      { cnt = cnt_sj; off = off_sj; n = NJ; }
    __shared__ int sh_carry;
    __shared__ int wsum[32];
    int lane = threadIdx.x & 31, wid = threadIdx.x >> 5;
    if (threadIdx.x == 0) sh_carry = 0;
    __syncthreads();
    for (int base = 0; base < n; base += 1024) {
        int i = base + threadIdx.x;
        int x = (i < n) ? cnt[i] : 0;
        int v = x;
        #pragma unroll
        for (int o = 1; o < 32; o <<= 1) {
            int tv = __shfl_up_sync(0xffffffffu, v, o);
            if (lane >= o) v += tv;
        }
        if (lane == 31) wsum[wid] = v;
        __syncthreads();
        if (wid == 0) {
            int s = wsum[lane];
            #pragma unroll
            for (int o = 1; o < 32; o <<= 1) {
                int tv = __shfl_up_sync(0xffffffffu, s, o);
                if (lane >= o) s += tv;
            }
            wsum[lane] = s;
        }
        __syncthreads();
        int pre = wid ? wsum[wid - 1] : 0;
        int incl = v + pre;
        int carry = sh_carry;
        if (i < n) off[i] = carry + incl - x;
        __syncthreads();
        if (threadIdx.x == 1023) sh_carry = carry + incl;
        __syncthreads();
    }
}

__global__ void fill3_kernel(const int* __restrict__ js_s, const int* __restrict__ js_d,
                             const int* __restrict__ ss_s, const int* __restrict__ ss_d,
                             const int* __restrict__ sj_s, const int* __restrict__ sj_d,
                             const int* __restrict__ off_js, int* __restrict__ cur_js,
                             int* __restrict__ csr_js,
                             const int* __restrict__ off_ss, int* __restrict__ cur_ss,
                             int* __restrict__ csr_ss,
                             const int* __restrict__ off_sj, int* __restrict__ cur_sj,
                             int* __restrict__ csr_sj)
{
    int e = blockIdx.x * blockDim.x + threadIdx.x;
    if (e >= E_ALL) return;
    int s, d;
    const int* off; int* cur; int* csr;
    if (e < E_JS) {
        s = js_s[e]; d = js_d[e]; off = off_js; cur = cur_js; csr = csr_js;
    } else if (e < E_JS + E_SS) {
        int i = e - E_JS; s = ss_s[i]; d = ss_d[i]; off = off_ss; cur = cur_ss; csr = csr_ss;
    } else if (e < E_JS + E_SS + NS) {
        s = d = e - E_JS - E_SS; off = off_ss; cur = cur_ss; csr = csr_ss;
    } else {
        int i = e - E_JS - E_SS_T; s = sj_s[i]; d = sj_d[i]; off = off_sj; cur = cur_sj; csr = csr_sj;
    }
    int pos = off[d] + atomicAdd(&cur[d], 1);
    csr[pos] = s;
}

// ---------------- single-relation softmax-aggregate into register accumulators ----------
__device__ __forceinline__ void agg_one(int o, int deg, const int* __restrict__ csrc,
                                        const float* __restrict__ hs,
                                        const float* __restrict__ alps,
                                        float ad0, float ad1, int lane,
                                        float4& o0, float4& o1)
{
    float4 acc0 = make_float4(0.f, 0.f, 0.f, 0.f);
    float4 acc1 = make_float4(0.f, 0.f, 0.f, 0.f);
    float den0 = 0.f, den1 = 0.f;
    const float2* ap = (const float2*)alps;
    int s = (deg > 0) ? csrc[o] : 0;
    for (int k = 0; k < deg; k++) {
        int snext = (k + 1 < deg) ? csrc[o + k + 1] : 0;
        float2 av = ap[s];
        float e0 = av.x + ad0; e0 = e0 > 0.f ? e0 : 0.2f * e0;
        float e1 = av.y + ad1; e1 = e1 > 0.f ? e1 : 0.2f * e1;
        float p0 = __expf(e0), p1 = __expf(e1);
        const float4* hp = (const float4*)(hs + (size_t)s * 256);
        float4 v0 = hp[lane];
        float4 v1 = hp[32 + lane];
        acc0.x = fmaf(p0, v0.x, acc0.x); acc0.y = fmaf(p0, v0.y, acc0.y);
        acc0.z = fmaf(p0, v0.z, acc0.z); acc0.w = fmaf(p0, v0.w, acc0.w);
        acc1.x = fmaf(p1, v1.x, acc1.x); acc1.y = fmaf(p1, v1.y, acc1.y);
        acc1.z = fmaf(p1, v1.z, acc1.z); acc1.w = fmaf(p1, v1.w, acc1.w);
        den0 += p0; den1 += p1;
        s = snext;
    }
    float r0 = 1.f / (den0 + 1e-16f);
    float r1 = 1.f / (den1 + 1e-16f);
    o0.x = fmaf(acc0.x, r0, o0.x); o0.y = fmaf(acc0.y, r0, o0.y);
    o0.z = fmaf(acc0.z, r0, o0.z); o0.w = fmaf(acc0.w, r0, o0.w);
    o1.x = fmaf(acc1.x, r1, o1.x); o1.y = fmaf(acc1.y, r1, o1.y);
    o1.z = fmaf(acc1.z, r1, o1.z); o1.w = fmaf(acc1.w, r1, o1.w);
}

// ---------------- fused aggregation for all relations of one layer ----------------
// warp w < NS: skill dst = js-agg + ss-agg + b0 + b2 -> os
// warp w >= NS: job dst  = sj-agg + b1 -> oj
__global__ void gat_all_kernel(const int* __restrict__ off_js, const int* __restrict__ cnt_js,
                               const int* __restrict__ csr_js,
                               const int* __restrict__ off_ss, const int* __restrict__ cnt_ss,
                               const int* __restrict__ csr_ss,
                               const int* __restrict__ off_sj, const int* __restrict__ cnt_sj,
                               const int* __restrict__ csr_sj,
                               const float* __restrict__ hs0, const float* __restrict__ hs1,
                               const float* __restrict__ hs2,
                               const float* __restrict__ alps0, const float* __restrict__ alps1,
                               const float* __restrict__ alps2,
                               const float* __restrict__ alpd0, const float* __restrict__ alpd1,
                               const float* __restrict__ alpd2,
                               const float* __restrict__ b0, const float* __restrict__ b1,
                               const float* __restrict__ b2,
                               float* __restrict__ os, float* __restrict__ oj)
{
    int w    = (blockIdx.x * blockDim.x + threadIdx.x) >> 5;
    int lane = threadIdx.x & 31;
    if (w < NS) {
        int d = w;
        float4 o0 = ((const float4*)b0)[lane];
        float4 o1 = ((const float4*)b0)[32 + lane];
        float4 t0 = ((const float4*)b2)[lane];
        float4 t1 = ((const float4*)b2)[32 + lane];
        o0.x += t0.x; o0.y += t0.y; o0.z += t0.z; o0.w += t0.w;
        o1.x += t1.x; o1.y += t1.y; o1.z += t1.z; o1.w += t1.w;
        agg_one(off_js[d], cnt_js[d], csr_js, hs0, alps0,
                alpd0[d * 2], alpd0[d * 2 + 1], lane, o0, o1);
        agg_one(off_ss[d], cnt_ss[d], csr_ss, hs2, alps2,
                alpd2[d * 2], alpd2[d * 2 + 1], lane, o0, o1);
        float4* op = (float4*)(os + (size_t)d * 256);
        op[lane] = o0;
        op[32 + lane] = o1;
    } else if (w < NS + NJ) {
        int d = w - NS;
        float4 o0 = ((const float4*)b1)[lane];
        float4 o1 = ((const float4*)b1)[32 + lane];
        agg_one(off_sj[d], cnt_sj[d], csr_sj, hs1, alps1,
                alpd1[d * 2], alpd1[d * 2 + 1], lane, o0, o1);
        float4* op = (float4*)(oj + (size_t)d * 256);
        op[lane] = o0;
        op[32 + lane] = o1;
    }
}

// ---------------- final small kernels ----------------
__global__ void q_kernel(const float* __restrict__ query, const float* __restrict__ Wq,
                         const float* __restrict__ bq, float* __restrict__ q)
{
    int j = threadIdx.x;   // 128
    float acc = bq[j];
    for (int k = 0; k < SBERT; k++) acc += query[k] * Wq[(size_t)k * 128 + j];
    q[j] = acc;
}

__global__ void scores_kernel(const float* __restrict__ emb, const float* __restrict__ q,
                              float* __restrict__ sc, int M)
{
    int wid  = (blockIdx.x * blockDim.x + threadIdx.x) >> 5;
    int lane = threadIdx.x & 31;
    if (wid >= M) return;
    const float* e = emb + (size_t)wid * 128;
    float acc = 0.f;
    #pragma unroll
    for (int qd = 0; qd < 4; qd++) { int k = lane + 32 * qd; acc += e[k] * q[k]; }
    acc = warp_sum(acc);
    if (lane == 0) sc[wid] = acc;
}

// ---------------- host ----------------
extern "C" void kernel_launch(void* const* d_in, const int* in_sizes, int n_in,
                              void* d_out, int out_size)
{
    const float* x_job    = (const float*)d_in[0];
    const float* x_skill  = (const float*)d_in[1];
    const int*   ei_js_s  = (const int*)d_in[2];
    const int*   ei_js_d  = (const int*)d_in[3];
    const int*   ei_sj_s  = (const int*)d_in[4];
    const int*   ei_sj_d  = (const int*)d_in[5];
    const int*   ei_ss_s  = (const int*)d_in[6];
    const int*   ei_ss_d  = (const int*)d_in[7];
    const float* query    = (const float*)d_in[8];
    const float* W0_job   = (const float*)d_in[9];
    const float* b0_job   = (const float*)d_in[10];
    const float* g0_job   = (const float*)d_in[11];
    const float* be0_job  = (const float*)d_in[12];
    const float* W0_skill = (const float*)d_in[13];
    const float* b0_skill = (const float*)d_in[14];
    const float* g0_skill = (const float*)d_in[15];
    const float* be0_skill= (const float*)d_in[16];
    const float* gat_Ws   = (const float*)d_in[17];
    const float* gat_Wd   = (const float*)d_in[18];
    const float* gat_as   = (const float*)d_in[19];
    const float* gat_ad   = (const float*)d_in[20];
    const float* gat_b    = (const float*)d_in[21];
    const float* inter_W  = (const float*)d_in[22];
    const float* inter_b  = (const float*)d_in[23];
    const float* Wjf      = (const float*)d_in[24];
    const float* bjf      = (const float*)d_in[25];
    const float* Wq       = (const float*)d_in[26];
    const float* bq       = (const float*)d_in[27];

    float* out     = (float*)d_out;
    float* scores  = out;
    float* job_emb = out + NJ;
    float* qout    = out + NJ + (size_t)NJ * 128;

    void* p;
    cudaGetSymbolAddress(&p, g_xj);    float* xj    = (float*)p;
    cudaGetSymbolAddress(&p, g_xs);    float* xs    = (float*)p;
    cudaGetSymbolAddress(&p, g_hs0);   float* hs0   = (float*)p;
    cudaGetSymbolAddress(&p, g_hs1);   float* hs1   = (float*)p;
    cudaGetSymbolAddress(&p, g_hs2);   float* hs2   = (float*)p;
    cudaGetSymbolAddress(&p, g_oj);    float* oj    = (float*)p;
    cudaGetSymbolAddress(&p, g_os);    float* os    = (float*)p;
    cudaGetSymbolAddress(&p, g_alps0); float* alps0 = (float*)p;
    cudaGetSymbolAddress(&p, g_alps1); float* alps1 = (float*)p;
    cudaGetSymbolAddress(&p, g_alps2); float* alps2 = (float*)p;
    cudaGetSymbolAddress(&p, g_alpd0); float* alpd0 = (float*)p;
    cudaGetSymbolAddress(&p, g_alpd1); float* alpd1 = (float*)p;
    cudaGetSymbolAddress(&p, g_alpd2); float* alpd2 = (float*)p;
    cudaGetSymbolAddress(&p, g_vd);    float* vd    = (float*)p;
    cudaGetSymbolAddress(&p, g_cnt_js); int* cnt_js = (int*)p;
    cudaGetSymbolAddress(&p, g_off_js); int* off_js = (int*)p;
    cudaGetSymbolAddress(&p, g_cur_js); int* cur_js = (int*)p;
    cudaGetSymbolAddress(&p, g_cnt_ss); int* cnt_ss = (int*)p;
    cudaGetSymbolAddress(&p, g_off_ss); int* off_ss = (int*)p;
    cudaGetSymbolAddress(&p, g_cur_ss); int* cur_ss = (int*)p;
    cudaGetSymbolAddress(&p, g_cnt_sj); int* cnt_sj = (int*)p;
    cudaGetSymbolAddress(&p, g_off_sj); int* off_sj = (int*)p;
    cudaGetSymbolAddress(&p, g_cur_sj); int* cur_sj = (int*)p;
    cudaGetSymbolAddress(&p, g_csr_js); int* csr_js = (int*)p;
    cudaGetSymbolAddress(&p, g_csr_ss); int* csr_ss = (int*)p;
    cudaGetSymbolAddress(&p, g_csr_sj); int* csr_sj = (int*)p;

    GJob none = { nullptr, nullptr, nullptr, nullptr, 0 };

    // ---- CSR build (batched; 4 launches) ----
    csr_zero_kernel<<<(NJ + 255) / 256, 256>>>(cnt_js, cur_js, cnt_ss, cur_ss, cnt_sj, cur_sj);
    hist3_kernel<<<(E_ALL + 255) / 256, 256>>>(ei_js_d, ei_ss_d, ei_sj_d, cnt_js, cnt_ss, cnt_sj);
    scan3_kernel<<<3, 1024>>>(cnt_js, off_js, cnt_ss, off_ss, cnt_sj, off_sj);
    fill3_kernel<<<(E_ALL + 255) / 256, 256>>>(ei_js_s, ei_js_d, ei_ss_s, ei_ss_d, ei_sj_s, ei_sj_d,
                                               off_js, cur_js, csr_js,
                                               off_ss, cur_ss, csr_ss,
                                               off_sj, cur_sj, csr_sj);

    // ---- initial per-type linear + LN + relu (batched) ----
    {
        GJob j0 = { x_job,   W0_job,   b0_job,   xj, NJ };
        GJob j1 = { x_skill, W0_skill, b0_skill, xs, NS };
        gemm3_kernel<<<dim3((NJ + 63) / 64, 1, 2), 256>>>(j0, j1, none, 128, SBERT, 0);
    }
    ln_relu2_kernel<<<NJ + NS, 128>>>(xj, g0_job, be0_job, xs, g0_skill, be0_skill);

    for (int i = 0; i < 2; i++) {
        const float* Ws_l = gat_Ws + (size_t)i * 3 * 128 * 256;
        const float* Wd_l = gat_Wd + (size_t)i * 3 * 128 * 256;
        const float* as_l = gat_as + (size_t)i * 3 * 256;
        const float* ad_l = gat_ad + (size_t)i * 3 * 256;
        const float* b_l  = gat_b  + (size_t)i * 3 * 256;

        // hs for all 3 relations in one launch (rel0: jobs@Ws0, rel1: skills@Ws1, rel2: skills@Ws2)
        {
            GJob j0 = { xj, Ws_l,               nullptr, hs0, NJ };
            GJob j1 = { xs, Ws_l + 1 * 128*256, nullptr, hs1, NS };
            GJob j2 = { xs, Ws_l + 2 * 128*256, nullptr, hs2, NS };
            gemm3_kernel<<<dim3((NJ + 63) / 64, 2, 3), 256>>>(j0, j1, j2, 256, 128, 0);
        }
        alpha_src3_kernel<<<((NJ + 2 * NS) * 2 * 32 + 255) / 256, 256>>>(
            hs0, as_l, alps0, hs1, as_l + 256, alps1, hs2, as_l + 512, alps2);
        vd3_kernel<<<3, 256>>>(Wd_l, ad_l, vd);
        alpha_dst3_kernel<<<((2 * NS + NJ) * 32 + 255) / 256, 256>>>(
            xs, xj, vd, alpd0, alpd1, alpd2);

        gat_all_kernel<<<((NS + NJ) * 32 + 255) / 256, 256>>>(
            off_js, cnt_js, csr_js, off_ss, cnt_ss, csr_ss, off_sj, cnt_sj, csr_sj,
            hs0, hs1, hs2, alps0, alps1, alps2, alpd0, alpd1, alpd2,
            b_l, b_l + 256, b_l + 512, os, oj);

        // inter linear + relu (batched)
        {
            GJob j0 = { oj, inter_W + (size_t)(i * 2 + 0) * 256 * 128,
                        inter_b + (size_t)(i * 2 + 0) * 128, xj, NJ };
            GJob j1 = { os, inter_W + (size_t)(i * 2 + 1) * 256 * 128,
                        inter_b + (size_t)(i * 2 + 1) * 128, xs, NS };
            gemm3_kernel<<<dim3((NJ + 63) / 64, 1, 2), 256>>>(j0, j1, none, 128, 256, 1);
        }
    }

    // ---- final projections ----
    {
        GJob j0 = { xj, Wjf, bjf, job_emb, NJ };
        gemm3_kernel<<<dim3((NJ + 63) / 64, 1, 1), 256>>>(j0, none, none, 128, 128, 0);
    }
    q_kernel<<<1, 128>>>(query, Wq, bq, qout);
    scores_kernel<<<(NJ * 32 + 255) / 256, 256>>>(job_emb, qout, scores, NJ);
}

// round 10
// speedup vs baseline: 3.0242x; 1.2176x over previous
#include <cuda_runtime.h>
#include <cuda_bf16.h>
#include <math.h>

#define NJ 30000
#define NS 12000
#define E_JS 300000
#define E_SJ 300000
#define E_SS 150000
#define E_SS_T (E_SS + NS)
#define E_ALL (E_JS + E_SS_T + E_SJ)
#define SBERT 384
#define HID 128
#define HHID 256

// ---------------- scratch (device globals; no allocation allowed) ----------------
__device__ float g_xj[NJ * HID];
__device__ float g_xs[NS * HID];
__device__ float g_hw0[NJ * HHID];   // js src folded features (jobs)
__device__ float g_hw1[NS * HHID];   // sj src folded features (skills)
__device__ float g_hw2[NS * HHID];   // ss src folded features (skills)
__device__ float g_mw[2 * 3 * 128 * 256];   // folded Ws@Winter per layer/relation
__device__ float g_fvj[2 * 4 * 128];        // job alpha fold vecs  [layer][col][k]
__device__ float g_fvs[2 * 8 * 128];        // skill alpha fold vecs
__device__ float g_cvj[2 * 128];            // job const vec (biases through inter)
__device__ float g_cvs[2 * 128];            // skill const vec
__device__ float g_alps0[NJ * 2], g_alps1[NS * 2], g_alps2[NS * 2];
__device__ float g_alpd0[NS * 2], g_alpd1[NJ * 2], g_alpd2[NS * 2];
// CSR structures
__device__ int g_cnt_js[NS], g_off_js[NS], g_cur_js[NS];
__device__ int g_cnt_ss[NS], g_off_ss[NS], g_cur_ss[NS];
__device__ int g_cnt_sj[NJ], g_off_sj[NJ], g_cur_sj[NJ];
__device__ int g_csr_js[E_JS];
__device__ int g_csr_ss[E_SS_T];
__device__ int g_csr_sj[E_SJ];

// ---------------- helpers ----------------
__device__ __forceinline__ float warp_sum(float v) {
    #pragma unroll
    for (int o = 16; o; o >>= 1) v += __shfl_xor_sync(0xffffffffu, v, o);
    return v;
}
__device__ __forceinline__ unsigned long long pk2(float lo, float hi) {
    unsigned long long r;
    asm("mov.b64 %0, {%1, %2};" : "=l"(r) : "r"(__float_as_uint(lo)), "r"(__float_as_uint(hi)));
    return r;
}
__device__ __forceinline__ void upk2(unsigned long long v, float& lo, float& hi) {
    unsigned int a, b;
    asm("mov.b64 {%0, %1}, %2;" : "=r"(a), "=r"(b) : "l"(v));
    lo = __uint_as_float(a); hi = __uint_as_float(b);
}
__device__ __forceinline__ void fma2(unsigned long long& d, unsigned long long a, unsigned long long b) {
    asm("fma.rn.f32x2 %0, %1, %2, %0;" : "+l"(d) : "l"(a), "l"(b));
}

// ---------------- batched GEMM: up to 6 jobs selected by blockIdx.z ----------------
struct GJob { const float* A; const float* B; const float* bias; float* C; int M; int lda; int ldC; };
struct GJobs { GJob j[6]; };

__global__ __launch_bounds__(256) void gemm_kernel(GJobs js, int N, int K, int relu)
{
    GJob jb = js.j[blockIdx.z];
    const int row0 = blockIdx.x * 64;
    if (jb.A == nullptr || row0 >= jb.M) return;
    const float* __restrict__ A = jb.A;
    const float* __restrict__ B = jb.B;
    const int M = jb.M;
    const int lda = jb.lda;

    __shared__ float As[16][68];   // transposed: As[k][row]; row-start 16B aligned
    __shared__ float Bs[16][128];

    const int t   = threadIdx.x;
    const int tc  = t & 31;
    const int tr  = t >> 5;
    const int col0 = blockIdx.y * 128;

    const int arow = t >> 2;
    const int akq  = (t & 3) * 4;
    const int bs0k = t >> 5;
    const int bs0c = (t & 31) * 4;
    const int bs1k = bs0k + 8;

    unsigned long long acc2[4][4];
    #pragma unroll
    for (int i = 0; i < 4; i++)
        #pragma unroll
        for (int j = 0; j < 4; j++) acc2[i][j] = 0ull;

    for (int k0 = 0; k0 < K; k0 += 16) {
        float4 av = make_float4(0.f, 0.f, 0.f, 0.f);
        if (row0 + arow < M)
            av = *(const float4*)(A + (size_t)(row0 + arow) * lda + k0 + akq);
        float4 bv0 = *(const float4*)(B + (size_t)(k0 + bs0k) * N + col0 + bs0c);
        float4 bv1 = *(const float4*)(B + (size_t)(k0 + bs1k) * N + col0 + bs0c);

        __syncthreads();
        As[akq + 0][arow] = av.x;
        As[akq + 1][arow] = av.y;
        As[akq + 2][arow] = av.z;
        As[akq + 3][arow] = av.w;
        *(float4*)&Bs[bs0k][bs0c] = bv0;
        *(float4*)&Bs[bs1k][bs0c] = bv1;
        __syncthreads();

        #pragma unroll
        for (int kk = 0; kk < 16; kk++) {
            float4 b = *(float4*)&Bs[kk][tc * 4];
            ulonglong2 apA = *(ulonglong2*)&As[kk][tr * 8];
            ulonglong2 apB = *(ulonglong2*)&As[kk][tr * 8 + 4];
            unsigned long long ap0 = apA.x, ap1 = apA.y, ap2 = apB.x, ap3 = apB.y;
            unsigned long long bd0 = pk2(b.x, b.x);
            unsigned long long bd1 = pk2(b.y, b.y);
            unsigned long long bd2 = pk2(b.z, b.z);
            unsigned long long bd3 = pk2(b.w, b.w);
            fma2(acc2[0][0], ap0, bd0); fma2(acc2[0][1], ap0, bd1);
            fma2(acc2[0][2], ap0, bd2); fma2(acc2[0][3], ap0, bd3);
            fma2(acc2[1][0], ap1, bd0); fma2(acc2[1][1], ap1, bd1);
            fma2(acc2[1][2], ap1, bd2); fma2(acc2[1][3], ap1, bd3);
            fma2(acc2[2][0], ap2, bd0); fma2(acc2[2][1], ap2, bd1);
            fma2(acc2[2][2], ap2, bd2); fma2(acc2[2][3], ap2, bd3);
            fma2(acc2[3][0], ap3, bd0); fma2(acc2[3][1], ap3, bd1);
            fma2(acc2[3][2], ap3, bd2); fma2(acc2[3][3], ap3, bd3);
        }
    }

    float acc[8][4];
    #pragma unroll
    for (int i = 0; i < 4; i++)
        #pragma unroll
        for (int j = 0; j < 4; j++)
            upk2(acc2[i][j], acc[2 * i][j], acc[2 * i + 1][j]);

    float4 bv = make_float4(0.f, 0.f, 0.f, 0.f);
    if (jb.bias) bv = *(const float4*)(jb.bias + col0 + tc * 4);
    #pragma unroll
    for (int i = 0; i < 8; i++) {
        int row = row0 + tr * 8 + i;
        if (row < M) {
            float4 o;
            o.x = acc[i][0] + bv.x;
            o.y = acc[i][1] + bv.y;
            o.z = acc[i][2] + bv.z;
            o.w = acc[i][3] + bv.w;
            if (relu) {
                o.x = fmaxf(o.x, 0.f); o.y = fmaxf(o.y, 0.f);
                o.z = fmaxf(o.z, 0.f); o.w = fmaxf(o.w, 0.f);
            }
            *(float4*)(jb.C + (size_t)row * jb.ldC + col0 + tc * 4) = o;
        }
    }
}

// ---------------- batched LayerNorm(128) + ReLU, in place ----------------
__global__ void ln_relu2_kernel(float* __restrict__ xj, const float* __restrict__ gj,
                                const float* __restrict__ bej,
                                float* __restrict__ xs, const float* __restrict__ gs,
                                const float* __restrict__ bes)
{
    int row = blockIdx.x;
    int t = threadIdx.x;
    float* x; const float* g; const float* be;
    if (row < NJ) { x = xj + (size_t)row * 128; g = gj; be = bej; }
    else          { x = xs + (size_t)(row - NJ) * 128; g = gs; be = bes; }
    float v = x[t];
    float s = v, sq = v * v;
    s = warp_sum(s); sq = warp_sum(sq);
    __shared__ float ss[4], ssq[4];
    if ((t & 31) == 0) { ss[t >> 5] = s; ssq[t >> 5] = sq; }
    __syncthreads();
    s  = ss[0] + ss[1] + ss[2] + ss[3];
    sq = ssq[0] + ssq[1] + ssq[2] + ssq[3];
    float mu  = s * (1.f / 128.f);
    float var = sq * (1.f / 128.f) - mu * mu;
    float r = rsqrtf(var + 1e-5f);
    float y = (v - mu) * r * g[t] + be[t];
    x[t] = fmaxf(y, 0.f);
}

// ---------------- weight folding: alpha vectors (both layers upfront) ----------------
// fvj[l][col][k]: col 0,1 = Ws(rel0)@as heads; col 2,3 = Wd(rel1)@ad heads
// fvs[l][col][k]: col 0,1 = Ws(rel1)@as; 2,3 = Ws(rel2)@as; 4,5 = Wd(rel0)@ad; 6,7 = Wd(rel2)@ad
__global__ void fold_fv_kernel(const float* __restrict__ Ws, const float* __restrict__ Wd,
                               const float* __restrict__ as_, const float* __restrict__ ad_,
                               float* __restrict__ fvj, float* __restrict__ fvs)
{
    int l = blockIdx.x / 12, v = blockIdx.x % 12;
    int k = threadIdx.x;   // 128
    int rel, h, col, useWd, isJob;
    if (v < 2)       { rel = 0; h = v;      col = v;     useWd = 0; isJob = 1; }
    else if (v < 4)  { rel = 1; h = v - 2;  col = v;     useWd = 1; isJob = 1; }
    else if (v < 6)  { rel = 1; h = v - 4;  col = v - 4; useWd = 0; isJob = 0; }
    else if (v < 8)  { rel = 2; h = v - 6;  col = v - 4; useWd = 0; isJob = 0; }
    else if (v < 10) { rel = 0; h = v - 8;  col = v - 4; useWd = 1; isJob = 0; }
    else             { rel = 2; h = v - 10; col = v - 4; useWd = 1; isJob = 0; }
    const float* W = (useWd ? Wd : Ws) + (size_t)(l * 3 + rel) * 32768 + h * 128;
    const float* a = (useWd ? ad_ : as_) + (size_t)((l * 3 + rel) * 2 + h) * 128;
    float acc = 0.f;
    #pragma unroll 8
    for (int c = 0; c < 128; c++) acc += W[(size_t)k * 256 + c] * a[c];
    float* out = isJob ? (fvj + l * 512) : (fvs + l * 1024);
    out[col * 128 + k] = acc;
}

// ---------------- weight folding: constant vectors (biases through inter) ----------------
__global__ void fold_cvec_kernel(const float* __restrict__ gat_b,
                                 const float* __restrict__ inter_W,
                                 const float* __restrict__ inter_b,
                                 float* __restrict__ cvj, float* __restrict__ cvs)
{
    int l = blockIdx.x >> 1, t = blockIdx.x & 1;
    int j = threadIdx.x;    // 128
    const float* W = inter_W + (size_t)(l * 2 + t) * 256 * 128;
    float acc = inter_b[(l * 2 + t) * 128 + j];
    if (t == 0) {
        const float* b = gat_b + (size_t)(l * 3 + 1) * 256;
        for (int c = 0; c < 256; c++) acc += b[c] * W[(size_t)c * 128 + j];
        cvj[l * 128 + j] = acc;
    } else {
        const float* b0 = gat_b + (size_t)(l * 3 + 0) * 256;
        const float* b2 = gat_b + (size_t)(l * 3 + 2) * 256;
        for (int c = 0; c < 256; c++) acc += (b0[c] + b2[c]) * W[(size_t)c * 128 + j];
        cvs[l * 128 + j] = acc;
    }
}

// ---------------- fused alpha (src+dst) for one layer ----------------
__global__ void alpha_fold_kernel(const float* __restrict__ xj, const float* __restrict__ xs,
                                  const float* __restrict__ fvj, const float* __restrict__ fvs,
                                  float* __restrict__ alps0, float* __restrict__ alps1,
                                  float* __restrict__ alps2,
                                  float* __restrict__ alpd0, float* __restrict__ alpd1,
                                  float* __restrict__ alpd2)
{
    int w    = (blockIdx.x * blockDim.x + threadIdx.x) >> 5;
    int lane = threadIdx.x & 31;
    if (w < NJ) {
        const float* xp = xj + (size_t)w * 128;
        float xv[4];
        #pragma unroll
        for (int q = 0; q < 4; q++) xv[q] = xp[lane + 32 * q];
        float a[4];
        #pragma unroll
        for (int col = 0; col < 4; col++) {
            float acc = 0.f;
            #pragma unroll
            for (int q = 0; q < 4; q++) acc += xv[q] * fvj[col * 128 + lane + 32 * q];
            a[col] = warp_sum(acc);
        }
        if (lane == 0) {
            alps0[w * 2] = a[0]; alps0[w * 2 + 1] = a[1];
            alpd1[w * 2] = a[2]; alpd1[w * 2 + 1] = a[3];
        }
    } else if (w < NJ + NS) {
        int n = w - NJ;
        const float* xp = xs + (size_t)n * 128;
        float xv[4];
        #pragma unroll
        for (int q = 0; q < 4; q++) xv[q] = xp[lane + 32 * q];
        float a[8];
        #pragma unroll
        for (int col = 0; col < 8; col++) {
            float acc = 0.f;
            #pragma unroll
            for (int q = 0; q < 4; q++) acc += xv[q] * fvs[col * 128 + lane + 32 * q];
            a[col] = warp_sum(acc);
        }
        if (lane == 0) {
            alps1[n * 2] = a[0]; alps1[n * 2 + 1] = a[1];
            alps2[n * 2] = a[2]; alps2[n * 2 + 1] = a[3];
            alpd0[n * 2] = a[4]; alpd0[n * 2 + 1] = a[5];
            alpd2[n * 2] = a[6]; alpd2[n * 2 + 1] = a[7];
        }
    }
}

// ---------------- CSR build ----------------
__global__ void csr_zero_kernel(int* cnt_js, int* cur_js, int* cnt_ss, int* cur_ss,
                                int* cnt_sj, int* cur_sj)
{
    int i = blockIdx.x * blockDim.x + threadIdx.x;
    if (i < NS) { cnt_js[i] = 0; cur_js[i] = 0; cnt_ss[i] = 0; cur_ss[i] = 0; }
    if (i < NJ) { cnt_sj[i] = 0; cur_sj[i] = 0; }
}

__global__ void hist3_kernel(const int* __restrict__ js_d, const int* __restrict__ ss_d,
                             const int* __restrict__ sj_d,
                             int* __restrict__ cnt_js, int* __restrict__ cnt_ss,
                             int* __restrict__ cnt_sj)
{
    int e = blockIdx.x * blockDim.x + threadIdx.x;
    if (e >= E_ALL) return;
    if (e < E_JS)                  atomicAdd(&cnt_js[js_d[e]], 1);
    else if (e < E_JS + E_SS)      atomicAdd(&cnt_ss[ss_d[e - E_JS]], 1);
    else if (e < E_JS + E_SS + NS) atomicAdd(&cnt_ss[e - E_JS - E_SS], 1);
    else                           atomicAdd(&cnt_sj[sj_d[e - E_JS - E_SS_T]], 1);
}

__global__ void scan3_kernel(const int* __restrict__ cnt_js, int* __restrict__ off_js,
                             const int* __restrict__ cnt_ss, int* __restrict__ off_ss,
                             const int* __restrict__ cnt_sj, int* __restrict__ off_sj)
{
    const int* cnt; int* off; int n;
    if (blockIdx.x == 0)      { cnt = cnt_js; off = off_js; n = NS; }
    else if (blockIdx.x == 1) { cnt = cnt_ss; off = off_ss; n = NS; }
    else                      { cnt = cnt_sj; off = off_sj; n = NJ; }
    __shared__ int sh_carry;
    __shared__ int wsum[32];
    int lane = threadIdx.x & 31, wid = threadIdx.x >> 5;
    if (threadIdx.x == 0) sh_carry = 0;
    __syncthreads();
    for (int base = 0; base < n; base += 1024) {
        int i = base + threadIdx.x;
        int x = (i < n) ? cnt[i] : 0;
        int v = x;
        #pragma unroll
        for (int o = 1; o < 32; o <<= 1) {
            int tv = __shfl_up_sync(0xffffffffu, v, o);
            if (lane >= o) v += tv;
        }
        if (lane == 31) wsum[wid] = v;
        __syncthreads();
        if (wid == 0) {
            int s = wsum[lane];
            #pragma unroll
            for (int o = 1; o < 32; o <<= 1) {
                int tv = __shfl_up_sync(0xffffffffu, s, o);
                if (lane >= o) s += tv;
            }
            wsum[lane] = s;
        }
        __syncthreads();
        int pre = wid ? wsum[wid - 1] : 0;
        int incl = v + pre;
        int carry = sh_carry;
        if (i < n) off[i] = carry + incl - x;
        __syncthreads();
        if (threadIdx.x == 1023) sh_carry = carry + incl;
        __syncthreads();
    }
}

__global__ void fill3_kernel(const int* __restrict__ js_s, const int* __restrict__ js_d,
                             const int* __restrict__ ss_s, const int* __restrict__ ss_d,
                             const int* __restrict__ sj_s, const int* __restrict__ sj_d,
                             const int* __restrict__ off_js, int* __restrict__ cur_js,
                             int* __restrict__ csr_js,
                             const int* __restrict__ off_ss, int* __restrict__ cur_ss,
                             int* __restrict__ csr_ss,
                             const int* __restrict__ off_sj, int* __restrict__ cur_sj,
                             int* __restrict__ csr_sj)
{
    int e = blockIdx.x * blockDim.x + threadIdx.x;
    if (e >= E_ALL) return;
    int s, d;
    const int* off; int* cur; int* csr;
    if (e < E_JS) {
        s = js_s[e]; d = js_d[e]; off = off_js; cur = cur_js; csr = csr_js;
    } else if (e < E_JS + E_SS) {
        int i = e - E_JS; s = ss_s[i]; d = ss_d[i]; off = off_ss; cur = cur_ss; csr = csr_ss;
    } else if (e < E_JS + E_SS + NS) {
        s = d = e - E_JS - E_SS; off = off_ss; cur = cur_ss; csr = csr_ss;
    } else {
        int i = e - E_JS - E_SS_T; s = sj_s[i]; d = sj_d[i]; off = off_sj; cur = cur_sj; csr = csr_sj;
    }
    int pos = off[d] + atomicAdd(&cur[d], 1);
    csr[pos] = s;
}

// ---------------- softmax-aggregate one relation into 128-d accumulator ----------------
// out[j] += (1/den0)*sum_e p0*hw[s][j] + (1/den1)*sum_e p1*hw[s][128+j]
__device__ __forceinline__ void agg_one(int o, int deg, const int* __restrict__ csrc,
                                        const float* __restrict__ hw,
                                        const float* __restrict__ alps,
                                        float ad0, float ad1, int lane, float4& out)
{
    if (deg <= 0) return;
    float4 acc0 = make_float4(0.f, 0.f, 0.f, 0.f);
    float4 acc1 = make_float4(0.f, 0.f, 0.f, 0.f);
    float den0 = 0.f, den1 = 0.f;
    const float2* ap = (const float2*)alps;

    int s  = csrc[o];
    int s1 = (deg > 1) ? csrc[o + 1] : 0;
    float2 av = ap[s];
    const float4* hp = (const float4*)(hw + (size_t)s * 256);
    float4 v0 = hp[lane];
    float4 v1 = hp[32 + lane];

    for (int k = 0; k < deg; k++) {
        // prefetch iteration k+1 (indices already 1 ahead, values issued now)
        int s2 = (k + 2 < deg) ? csrc[o + k + 2] : 0;
        float2 avn = ap[s1];
        const float4* hpn = (const float4*)(hw + (size_t)s1 * 256);
        float4 v0n = hpn[lane];
        float4 v1n = hpn[32 + lane];

        float e0 = av.x + ad0; e0 = e0 > 0.f ? e0 : 0.2f * e0;
        float e1 = av.y + ad1; e1 = e1 > 0.f ? e1 : 0.2f * e1;
        float p0 = __expf(e0), p1 = __expf(e1);
        acc0.x = fmaf(p0, v0.x, acc0.x); acc0.y = fmaf(p0, v0.y, acc0.y);
        acc0.z = fmaf(p0, v0.z, acc0.z); acc0.w = fmaf(p0, v0.w, acc0.w);
        acc1.x = fmaf(p1, v1.x, acc1.x); acc1.y = fmaf(p1, v1.y, acc1.y);
        acc1.z = fmaf(p1, v1.z, acc1.z); acc1.w = fmaf(p1, v1.w, acc1.w);
        den0 += p0; den1 += p1;

        s1 = s2; av = avn; v0 = v0n; v1 = v1n;
    }
    float r0 = 1.f / (den0 + 1e-16f);
    float r1 = 1.f / (den1 + 1e-16f);
    out.x = fmaf(acc0.x, r0, out.x); out.y = fmaf(acc0.y, r0, out.y);
    out.z = fmaf(acc0.z, r0, out.z); out.w = fmaf(acc0.w, r0, out.w);
    out.x = fmaf(acc1.x, r1, out.x); out.y = fmaf(acc1.y, r1, out.y);
    out.z = fmaf(acc1.z, r1, out.z); out.w = fmaf(acc1.w, r1, out.w);
}

// ---------------- fused aggregation + (folded inter linear) + relu for one layer ----------------
// warp w < NS: xs[d] = relu(js-agg + ss-agg + cvs);  warp w >= NS: xj[d] = relu(sj-agg + cvj)
__global__ void gat_all_kernel(const int* __restrict__ off_js, const int* __restrict__ cnt_js,
                               const int* __restrict__ csr_js,
                               const int* __restrict__ off_ss, const int* __restrict__ cnt_ss,
                               const int* __restrict__ csr_ss,
                               const int* __restrict__ off_sj, const int* __restrict__ cnt_sj,
                               const int* __restrict__ csr_sj,
                               const float* __restrict__ hw0, const float* __restrict__ hw1,
                               const float* __restrict__ hw2,
                               const float* __restrict__ alps0, const float* __restrict__ alps1,
                               const float* __restrict__ alps2,
                               const float* __restrict__ alpd0, const float* __restrict__ alpd1,
                               const float* __restrict__ alpd2,
                               const float* __restrict__ cvj, const float* __restrict__ cvs,
                               float* __restrict__ xj, float* __restrict__ xs)
{
    int w    = (blockIdx.x * blockDim.x + threadIdx.x) >> 5;
    int lane = threadIdx.x & 31;
    if (w < NS) {
        int d = w;
        float4 acc = ((const float4*)cvs)[lane];
        agg_one(off_js[d], cnt_js[d], csr_js, hw0, alps0,
                alpd0[d * 2], alpd0[d * 2 + 1], lane, acc);
        agg_one(off_ss[d], cnt_ss[d], csr_ss, hw2, alps2,
                alpd2[d * 2], alpd2[d * 2 + 1], lane, acc);
        acc.x = fmaxf(acc.x, 0.f); acc.y = fmaxf(acc.y, 0.f);
        acc.z = fmaxf(acc.z, 0.f); acc.w = fmaxf(acc.w, 0.f);
        ((float4*)(xs + (size_t)d * 128))[lane] = acc;
    } else if (w < NS + NJ) {
        int d = w - NS;
        float4 acc = ((const float4*)cvj)[lane];
        agg_one(off_sj[d], cnt_sj[d], csr_sj, hw1, alps1,
                alpd1[d * 2], alpd1[d * 2 + 1], lane, acc);
        acc.x = fmaxf(acc.x, 0.f); acc.y = fmaxf(acc.y, 0.f);
        acc.z = fmaxf(acc.z, 0.f); acc.w = fmaxf(acc.w, 0.f);
        ((float4*)(xj + (size_t)d * 128))[lane] = acc;
    }
}

// ---------------- final small kernels ----------------
__global__ void q_kernel(const float* __restrict__ query, const float* __restrict__ Wq,
                         const float* __restrict__ bq, float* __restrict__ q)
{
    int j = threadIdx.x;   // 128
    float acc = bq[j];
    for (int k = 0; k < SBERT; k++) acc += query[k] * Wq[(size_t)k * 128 + j];
    q[j] = acc;
}

__global__ void scores_kernel(const float* __restrict__ emb, const float* __restrict__ q,
                              float* __restrict__ sc, int M)
{
    int wid  = (blockIdx.x * blockDim.x + threadIdx.x) >> 5;
    int lane = threadIdx.x & 31;
    if (wid >= M) return;
    const float* e = emb + (size_t)wid * 128;
    float acc = 0.f;
    #pragma unroll
    for (int qd = 0; qd < 4; qd++) { int k = lane + 32 * qd; acc += e[k] * q[k]; }
    acc = warp_sum(acc);
    if (lane == 0) sc[wid] = acc;
}

// ---------------- host ----------------
extern "C" void kernel_launch(void* const* d_in, const int* in_sizes, int n_in,
                              void* d_out, int out_size)
{
    const float* x_job    = (const float*)d_in[0];
    const float* x_skill  = (const float*)d_in[1];
    const int*   ei_js_s  = (const int*)d_in[2];
    const int*   ei_js_d  = (const int*)d_in[3];
    const int*   ei_sj_s  = (const int*)d_in[4];
    const int*   ei_sj_d  = (const int*)d_in[5];
    const int*   ei_ss_s  = (const int*)d_in[6];
    const int*   ei_ss_d  = (const int*)d_in[7];
    const float* query    = (const float*)d_in[8];
    const float* W0_job   = (const float*)d_in[9];
    const float* b0_job   = (const float*)d_in[10];
    const float* g0_job   = (const float*)d_in[11];
    const float* be0_job  = (const float*)d_in[12];
    const float* W0_skill = (const float*)d_in[13];
    const float* b0_skill = (const float*)d_in[14];
    const float* g0_skill = (const float*)d_in[15];
    const float* be0_skill= (const float*)d_in[16];
    const float* gat_Ws   = (const float*)d_in[17];
    const float* gat_Wd   = (const float*)d_in[18];
    const float* gat_as   = (const float*)d_in[19];
    const float* gat_ad   = (const float*)d_in[20];
    const float* gat_b    = (const float*)d_in[21];
    const float* inter_W  = (const float*)d_in[22];
    const float* inter_b  = (const float*)d_in[23];
    const float* Wjf      = (const float*)d_in[24];
    const float* bjf      = (const float*)d_in[25];
    const float* Wq       = (const float*)d_in[26];
    const float* bq       = (const float*)d_in[27];

    float* out     = (float*)d_out;
    float* scores  = out;
    float* job_emb = out + NJ;
    float* qout    = out + NJ + (size_t)NJ * 128;

    void* p;
    cudaGetSymbolAddress(&p, g_xj);    float* xj    = (float*)p;
    cudaGetSymbolAddress(&p, g_xs);    float* xs    = (float*)p;
    cudaGetSymbolAddress(&p, g_hw0);   float* hw0   = (float*)p;
    cudaGetSymbolAddress(&p, g_hw1);   float* hw1   = (float*)p;
    cudaGetSymbolAddress(&p, g_hw2);   float* hw2   = (float*)p;
    cudaGetSymbolAddress(&p, g_mw);    float* mw    = (float*)p;
    cudaGetSymbolAddress(&p, g_fvj);   float* fvj   = (float*)p;
    cudaGetSymbolAddress(&p, g_fvs);   float* fvs   = (float*)p;
    cudaGetSymbolAddress(&p, g_cvj);   float* cvj   = (float*)p;
    cudaGetSymbolAddress(&p, g_cvs);   float* cvs   = (float*)p;
    cudaGetSymbolAddress(&p, g_alps0); float* alps0 = (float*)p;
    cudaGetSymbolAddress(&p, g_alps1); float* alps1 = (float*)p;
    cudaGetSymbolAddress(&p, g_alps2); float* alps2 = (float*)p;
    cudaGetSymbolAddress(&p, g_alpd0); float* alpd0 = (float*)p;
    cudaGetSymbolAddress(&p, g_alpd1); float* alpd1 = (float*)p;
    cudaGetSymbolAddress(&p, g_alpd2); float* alpd2 = (float*)p;
    cudaGetSymbolAddress(&p, g_cnt_js); int* cnt_js = (int*)p;
    cudaGetSymbolAddress(&p, g_off_js); int* off_js = (int*)p;
    cudaGetSymbolAddress(&p, g_cur_js); int* cur_js = (int*)p;
    cudaGetSymbolAddress(&p, g_cnt_ss); int* cnt_ss = (int*)p;
    cudaGetSymbolAddress(&p, g_off_ss); int* off_ss = (int*)p;
    cudaGetSymbolAddress(&p, g_cur_ss); int* cur_ss = (int*)p;
    cudaGetSymbolAddress(&p, g_cnt_sj); int* cnt_sj = (int*)p;
    cudaGetSymbolAddress(&p, g_off_sj); int* off_sj = (int*)p;
    cudaGetSymbolAddress(&p, g_cur_sj); int* cur_sj = (int*)p;
    cudaGetSymbolAddress(&p, g_csr_js); int* csr_js = (int*)p;
    cudaGetSymbolAddress(&p, g_csr_ss); int* csr_ss = (int*)p;
    cudaGetSymbolAddress(&p, g_csr_sj); int* csr_sj = (int*)p;

    GJob none = { nullptr, nullptr, nullptr, nullptr, 0, 0, 0 };
    GJobs J;

    // ---- CSR build ----
    csr_zero_kernel<<<(NJ + 255) / 256, 256>>>(cnt_js, cur_js, cnt_ss, cur_ss, cnt_sj, cur_sj);
    hist3_kernel<<<(E_ALL + 255) / 256, 256>>>(ei_js_d, ei_ss_d, ei_sj_d, cnt_js, cnt_ss, cnt_sj);
    scan3_kernel<<<3, 1024>>>(cnt_js, off_js, cnt_ss, off_ss, cnt_sj, off_sj);
    fill3_kernel<<<(E_ALL + 255) / 256, 256>>>(ei_js_s, ei_js_d, ei_ss_s, ei_ss_d, ei_sj_s, ei_sj_d,
                                               off_js, cur_js, csr_js,
                                               off_ss, cur_ss, csr_ss,
                                               off_sj, cur_sj, csr_sj);

    // ---- weight folding (both layers upfront) ----
    fold_fv_kernel<<<24, 128>>>(gat_Ws, gat_Wd, gat_as, gat_ad, fvj, fvs);
    fold_cvec_kernel<<<4, 128>>>(gat_b, inter_W, inter_b, cvj, cvs);
    // MW[l][r] = Ws_h @ Winter_h for each head; r=1 pairs with inter type 0, r=0,2 with type 1
    for (int l = 0; l < 2; l++) {
        for (int r = 0; r < 3; r++) {
            int t = (r == 1) ? 0 : 1;
            for (int h = 0; h < 2; h++) {
                J.j[r * 2 + h] = GJob{
                    gat_Ws + (size_t)(l * 3 + r) * 32768 + h * 128,
                    inter_W + (size_t)(l * 2 + t) * 32768 + (size_t)h * 16384,
                    nullptr,
                    mw + (size_t)(l * 3 + r) * 32768 + h * 128,
                    128, 256, 256 };
            }
        }
        gemm_kernel<<<dim3(2, 1, 6), 256>>>(J, 128, 128, 0);
    }

    // ---- initial per-type linear + LN + relu ----
    J.j[0] = GJob{ x_job,   W0_job,   b0_job,   xj, NJ, SBERT, 128 };
    J.j[1] = GJob{ x_skill, W0_skill, b0_skill, xs, NS, SBERT, 128 };
    for (int z = 2; z < 6; z++) J.j[z] = none;
    gemm_kernel<<<dim3((NJ + 63) / 64, 1, 2), 256>>>(J, 128, SBERT, 0);
    ln_relu2_kernel<<<NJ + NS, 128>>>(xj, g0_job, be0_job, xs, g0_skill, be0_skill);

    for (int i = 0; i < 2; i++) {
        // hsW = x_src @ MW for all 3 relations (one launch)
        J.j[0] = GJob{ xj, mw + (size_t)(i * 3 + 0) * 32768, nullptr, hw0, NJ, 128, 256 };
        J.j[1] = GJob{ xs, mw + (size_t)(i * 3 + 1) * 32768, nullptr, hw1, NS, 128, 256 };
        J.j[2] = GJob{ xs, mw + (size_t)(i * 3 + 2) * 32768, nullptr, hw2, NS, 128, 256 };
        for (int z = 3; z < 6; z++) J.j[z] = none;
        gemm_kernel<<<dim3((NJ + 63) / 64, 2, 3), 256>>>(J, 256, 128, 0);

        alpha_fold_kernel<<<((NJ + NS) * 32 + 255) / 256, 256>>>(
            xj, xs, fvj + i * 512, fvs + i * 1024,
            alps0, alps1, alps2, alpd0, alpd1, alpd2);

        gat_all_kernel<<<((NS + NJ) * 32 + 255) / 256, 256>>>(
            off_js, cnt_js, csr_js, off_ss, cnt_ss, csr_ss, off_sj, cnt_sj, csr_sj,
            hw0, hw1, hw2, alps0, alps1, alps2, alpd0, alpd1, alpd2,
            cvj + i * 128, cvs + i * 128, xj, xs);
    }

    // ---- final projections ----
    J.j[0] = GJob{ xj, Wjf, bjf, job_emb, NJ, 128, 128 };
    for (int z = 1; z < 6; z++) J.j[z] = none;
    gemm_kernel<<<dim3((NJ + 63) / 64, 1, 1), 256>>>(J, 128, 128, 0);
    q_kernel<<<1, 128>>>(query, Wq, bq, qout);
    scores_kernel<<<(NJ * 32 + 255) / 256, 256>>>(job_emb, qout, scores, NJ);
}

// round 11
// speedup vs baseline: 3.6115x; 1.1942x over previous
#include <cuda_runtime.h>
#include <cuda_bf16.h>
#include <math.h>

#define NJ 30000
#define NS 12000
#define E_JS 300000
#define E_SJ 300000
#define E_SS 150000
#define E_SS_T (E_SS + NS)
#define E_ALL (E_JS + E_SS_T + E_SJ)
#define SBERT 384
#define HID 128
#define HHID 256

// ---------------- scratch (device globals; no allocation allowed) ----------------
__device__ float g_xj[NJ * HID];
__device__ float g_xs[NS * HID];
__device__ float g_xs2[NS * HID];
__device__ float g_hw0[NJ * HHID];   // js src folded features (jobs)
__device__ float g_hw1[NS * HHID];   // sj src folded features (skills)
__device__ float g_hw2[NS * HHID];   // ss src folded features (skills)
__device__ float g_mw[2 * 3 * 128 * 256];   // folded Ws@Winter per layer/relation
__device__ float g_fvj[2 * 4 * 128];        // job alpha fold vecs  [layer][col][k]
__device__ float g_fvs[2 * 8 * 128];        // skill alpha fold vecs
__device__ float g_cvj[2 * 128];            // job const vec (biases through inter)
__device__ float g_cvs[2 * 128];            // skill const vec
__device__ float g_alps0[NJ * 2], g_alps1[NS * 2], g_alps2[NS * 2];
__device__ float g_alpd0[NS * 2], g_alpd1[NJ * 2], g_alpd2[NS * 2];
// CSR structures
__device__ int g_cnt_js[NS], g_off_js[NS], g_cur_js[NS];
__device__ int g_cnt_ss[NS], g_off_ss[NS], g_cur_ss[NS];
__device__ int g_cnt_sj[NJ], g_off_sj[NJ], g_cur_sj[NJ];
__device__ int g_csr_js[E_JS];
__device__ int g_csr_ss[E_SS_T];
__device__ int g_csr_sj[E_SJ];

// ---------------- helpers ----------------
__device__ __forceinline__ float warp_sum(float v) {
    #pragma unroll
    for (int o = 16; o; o >>= 1) v += __shfl_xor_sync(0xffffffffu, v, o);
    return v;
}
__device__ __forceinline__ unsigned long long pk2(float lo, float hi) {
    unsigned long long r;
    asm("mov.b64 %0, {%1, %2};" : "=l"(r) : "r"(__float_as_uint(lo)), "r"(__float_as_uint(hi)));
    return r;
}
__device__ __forceinline__ void upk2(unsigned long long v, float& lo, float& hi) {
    unsigned int a, b;
    asm("mov.b64 {%0, %1}, %2;" : "=r"(a), "=r"(b) : "l"(v));
    lo = __uint_as_float(a); hi = __uint_as_float(b);
}
__device__ __forceinline__ void fma2(unsigned long long& d, unsigned long long a, unsigned long long b) {
    asm("fma.rn.f32x2 %0, %1, %2, %0;" : "+l"(d) : "l"(a), "l"(b));
}

// ---------------- batched GEMM (up to 6 jobs via blockIdx.z) ----------------
// Optional per-job: A2 (summed into A with relu on load), bias, g/be (LN+relu epilogue; needs N==128)
struct GJob {
    const float* A; const float* A2; const float* B; const float* bias;
    const float* g; const float* be;
    float* C; int M; int lda; int ldC;
};
struct GJobs { GJob j[6]; };

__global__ __launch_bounds__(256) void gemm_kernel(GJobs js, int N, int K)
{
    GJob jb = js.j[blockIdx.z];
    const int row0 = blockIdx.x * 64;
    if (jb.A == nullptr || row0 >= jb.M) return;
    const float* __restrict__ A = jb.A;
    const float* __restrict__ B = jb.B;
    const int M = jb.M;
    const int lda = jb.lda;

    __shared__ float As[16][68];   // transposed: As[k][row]; row-start 16B aligned
    __shared__ float Bs[16][128];

    const int t   = threadIdx.x;
    const int tc  = t & 31;
    const int tr  = t >> 5;
    const int col0 = blockIdx.y * 128;

    const int arow = t >> 2;
    const int akq  = (t & 3) * 4;
    const int bs0k = t >> 5;
    const int bs0c = (t & 31) * 4;
    const int bs1k = bs0k + 8;

    unsigned long long acc2[4][4];
    #pragma unroll
    for (int i = 0; i < 4; i++)
        #pragma unroll
        for (int j = 0; j < 4; j++) acc2[i][j] = 0ull;

    for (int k0 = 0; k0 < K; k0 += 16) {
        float4 av = make_float4(0.f, 0.f, 0.f, 0.f);
        if (row0 + arow < M) {
            av = *(const float4*)(A + (size_t)(row0 + arow) * lda + k0 + akq);
            if (jb.A2) {
                float4 a2 = *(const float4*)(jb.A2 + (size_t)(row0 + arow) * lda + k0 + akq);
                av.x = fmaxf(av.x + a2.x, 0.f); av.y = fmaxf(av.y + a2.y, 0.f);
                av.z = fmaxf(av.z + a2.z, 0.f); av.w = fmaxf(av.w + a2.w, 0.f);
            }
        }
        float4 bv0 = *(const float4*)(B + (size_t)(k0 + bs0k) * N + col0 + bs0c);
        float4 bv1 = *(const float4*)(B + (size_t)(k0 + bs1k) * N + col0 + bs0c);

        __syncthreads();
        As[akq + 0][arow] = av.x;
        As[akq + 1][arow] = av.y;
        As[akq + 2][arow] = av.z;
        As[akq + 3][arow] = av.w;
        *(float4*)&Bs[bs0k][bs0c] = bv0;
        *(float4*)&Bs[bs1k][bs0c] = bv1;
        __syncthreads();

        #pragma unroll
        for (int kk = 0; kk < 16; kk++) {
            float4 b = *(float4*)&Bs[kk][tc * 4];
            ulonglong2 apA = *(ulonglong2*)&As[kk][tr * 8];
            ulonglong2 apB = *(ulonglong2*)&As[kk][tr * 8 + 4];
            unsigned long long ap0 = apA.x, ap1 = apA.y, ap2 = apB.x, ap3 = apB.y;
            unsigned long long bd0 = pk2(b.x, b.x);
            unsigned long long bd1 = pk2(b.y, b.y);
            unsigned long long bd2 = pk2(b.z, b.z);
            unsigned long long bd3 = pk2(b.w, b.w);
            fma2(acc2[0][0], ap0, bd0); fma2(acc2[0][1], ap0, bd1);
            fma2(acc2[0][2], ap0, bd2); fma2(acc2[0][3], ap0, bd3);
            fma2(acc2[1][0], ap1, bd0); fma2(acc2[1][1], ap1, bd1);
            fma2(acc2[1][2], ap1, bd2); fma2(acc2[1][3], ap1, bd3);
            fma2(acc2[2][0], ap2, bd0); fma2(acc2[2][1], ap2, bd1);
            fma2(acc2[2][2], ap2, bd2); fma2(acc2[2][3], ap2, bd3);
            fma2(acc2[3][0], ap3, bd0); fma2(acc2[3][1], ap3, bd1);
            fma2(acc2[3][2], ap3, bd2); fma2(acc2[3][3], ap3, bd3);
        }
    }

    float acc[8][4];
    #pragma unroll
    for (int i = 0; i < 4; i++)
        #pragma unroll
        for (int j = 0; j < 4; j++)
            upk2(acc2[i][j], acc[2 * i][j], acc[2 * i + 1][j]);

    float4 bv = make_float4(0.f, 0.f, 0.f, 0.f);
    if (jb.bias) bv = *(const float4*)(jb.bias + col0 + tc * 4);

    if (jb.g) {
        // LN + relu epilogue: warp (fixed tr) holds the whole 128-wide row.
        float4 gv  = *(const float4*)(jb.g  + tc * 4);
        float4 bev = *(const float4*)(jb.be + tc * 4);
        #pragma unroll
        for (int i = 0; i < 8; i++) {
            float4 o;
            o.x = acc[i][0] + bv.x; o.y = acc[i][1] + bv.y;
            o.z = acc[i][2] + bv.z; o.w = acc[i][3] + bv.w;
            float s  = warp_sum(o.x + o.y + o.z + o.w);
            float sq = warp_sum(o.x * o.x + o.y * o.y + o.z * o.z + o.w * o.w);
            float mu  = s * (1.f / 128.f);
            float var = sq * (1.f / 128.f) - mu * mu;
            float r = rsqrtf(var + 1e-5f);
            o.x = fmaxf((o.x - mu) * r * gv.x + bev.x, 0.f);
            o.y = fmaxf((o.y - mu) * r * gv.y + bev.y, 0.f);
            o.z = fmaxf((o.z - mu) * r * gv.z + bev.z, 0.f);
            o.w = fmaxf((o.w - mu) * r * gv.w + bev.w, 0.f);
            int row = row0 + tr * 8 + i;
            if (row < M)
                *(float4*)(jb.C + (size_t)row * jb.ldC + col0 + tc * 4) = o;
        }
    } else {
        #pragma unroll
        for (int i = 0; i < 8; i++) {
            int row = row0 + tr * 8 + i;
            if (row < M) {
                float4 o;
                o.x = acc[i][0] + bv.x; o.y = acc[i][1] + bv.y;
                o.z = acc[i][2] + bv.z; o.w = acc[i][3] + bv.w;
                *(float4*)(jb.C + (size_t)row * jb.ldC + col0 + tc * 4) = o;
            }
        }
    }
}

// ---------------- weight folding: alpha vectors (both layers upfront) ----------------
// fvj[l][col][k]: col 0,1 = Ws(rel0)@as heads; col 2,3 = Wd(rel1)@ad heads
// fvs[l][col][k]: col 0,1 = Ws(rel1)@as; 2,3 = Ws(rel2)@as; 4,5 = Wd(rel0)@ad; 6,7 = Wd(rel2)@ad
__global__ void fold_fv_kernel(const float* __restrict__ Ws, const float* __restrict__ Wd,
                               const float* __restrict__ as_, const float* __restrict__ ad_,
                               float* __restrict__ fvj, float* __restrict__ fvs)
{
    int l = blockIdx.x / 12, v = blockIdx.x % 12;
    int k = threadIdx.x;   // 128
    int rel, h, col, useWd, isJob;
    if (v < 2)       { rel = 0; h = v;      col = v;     useWd = 0; isJob = 1; }
    else if (v < 4)  { rel = 1; h = v - 2;  col = v;     useWd = 1; isJob = 1; }
    else if (v < 6)  { rel = 1; h = v - 4;  col = v - 4; useWd = 0; isJob = 0; }
    else if (v < 8)  { rel = 2; h = v - 6;  col = v - 4; useWd = 0; isJob = 0; }
    else if (v < 10) { rel = 0; h = v - 8;  col = v - 4; useWd = 1; isJob = 0; }
    else             { rel = 2; h = v - 10; col = v - 4; useWd = 1; isJob = 0; }
    const float* W = (useWd ? Wd : Ws) + (size_t)(l * 3 + rel) * 32768 + h * 128;
    const float* a = (useWd ? ad_ : as_) + (size_t)((l * 3 + rel) * 2 + h) * 128;
    float acc = 0.f;
    #pragma unroll 8
    for (int c = 0; c < 128; c++) acc += W[(size_t)k * 256 + c] * a[c];
    float* out = isJob ? (fvj + l * 512) : (fvs + l * 1024);
    out[col * 128 + k] = acc;
}

// ---------------- weight folding: constant vectors (biases through inter) ----------------
__global__ void fold_cvec_kernel(const float* __restrict__ gat_b,
                                 const float* __restrict__ inter_W,
                                 const float* __restrict__ inter_b,
                                 float* __restrict__ cvj, float* __restrict__ cvs)
{
    int l = blockIdx.x >> 1, t = blockIdx.x & 1;
    int j = threadIdx.x;    // 128
    const float* W = inter_W + (size_t)(l * 2 + t) * 256 * 128;
    float acc = inter_b[(l * 2 + t) * 128 + j];
    if (t == 0) {
        const float* b = gat_b + (size_t)(l * 3 + 1) * 256;
        for (int c = 0; c < 256; c++) acc += b[c] * W[(size_t)c * 128 + j];
        cvj[l * 128 + j] = acc;
    } else {
        const float* b0 = gat_b + (size_t)(l * 3 + 0) * 256;
        const float* b2 = gat_b + (size_t)(l * 3 + 2) * 256;
        for (int c = 0; c < 256; c++) acc += (b0[c] + b2[c]) * W[(size_t)c * 128 + j];
        cvs[l * 128 + j] = acc;
    }
}

// ---------------- fused alpha (src+dst) ----------------
// layer 0: jobs -> alps0(+alpd1), skills -> alps1,alps2,alpd0,alpd2 (reads xs)
// layer 1: jobs -> alpd1 only; skills -> alps1 only (reads relu(xs+xs2))
__global__ void alpha_fold_kernel(const float* __restrict__ xj, const float* __restrict__ xs,
                                  const float* __restrict__ xs2,
                                  const float* __restrict__ fvj, const float* __restrict__ fvs,
                                  float* __restrict__ alps0, float* __restrict__ alps1,
                                  float* __restrict__ alps2,
                                  float* __restrict__ alpd0, float* __restrict__ alpd1,
                                  float* __restrict__ alpd2, int layer)
{
    int w    = (blockIdx.x * blockDim.x + threadIdx.x) >> 5;
    int lane = threadIdx.x & 31;
    if (w >= NJ + NS) return;
    if (layer == 0) {
        if (w < NJ) {
            const float* xp = xj + (size_t)w * 128;
            float xv[4];
            #pragma unroll
            for (int q = 0; q < 4; q++) xv[q] = xp[lane + 32 * q];
            float a[4];
            #pragma unroll
            for (int col = 0; col < 4; col++) {
                float acc = 0.f;
                #pragma unroll
                for (int q = 0; q < 4; q++) acc += xv[q] * fvj[col * 128 + lane + 32 * q];
                a[col] = warp_sum(acc);
            }
            if (lane == 0) {
                alps0[w * 2] = a[0]; alps0[w * 2 + 1] = a[1];
                alpd1[w * 2] = a[2]; alpd1[w * 2 + 1] = a[3];
            }
        } else {
            int n = w - NJ;
            const float* xp = xs + (size_t)n * 128;
            float xv[4];
            #pragma unroll
            for (int q = 0; q < 4; q++) xv[q] = xp[lane + 32 * q];
            float a[8];
            #pragma unroll
            for (int col = 0; col < 8; col++) {
                float acc = 0.f;
                #pragma unroll
                for (int q = 0; q < 4; q++) acc += xv[q] * fvs[col * 128 + lane + 32 * q];
                a[col] = warp_sum(acc);
            }
            if (lane == 0) {
                alps1[n * 2] = a[0]; alps1[n * 2 + 1] = a[1];
                alps2[n * 2] = a[2]; alps2[n * 2 + 1] = a[3];
                alpd0[n * 2] = a[4]; alpd0[n * 2 + 1] = a[5];
                alpd2[n * 2] = a[6]; alpd2[n * 2 + 1] = a[7];
            }
        }
    } else {
        if (w < NJ) {
            const float* xp = xj + (size_t)w * 128;
            float xv[4];
            #pragma unroll
            for (int q = 0; q < 4; q++) xv[q] = xp[lane + 32 * q];
            float a2 = 0.f, a3 = 0.f;
            #pragma unroll
            for (int q = 0; q < 4; q++) {
                a2 += xv[q] * fvj[2 * 128 + lane + 32 * q];
                a3 += xv[q] * fvj[3 * 128 + lane + 32 * q];
            }
            a2 = warp_sum(a2); a3 = warp_sum(a3);
            if (lane == 0) { alpd1[w * 2] = a2; alpd1[w * 2 + 1] = a3; }
        } else {
            int n = w - NJ;
            const float* xp  = xs  + (size_t)n * 128;
            const float* xp2 = xs2 + (size_t)n * 128;
            float xv[4];
            #pragma unroll
            for (int q = 0; q < 4; q++)
                xv[q] = fmaxf(xp[lane + 32 * q] + xp2[lane + 32 * q], 0.f);
            float a0 = 0.f, a1 = 0.f;
            #pragma unroll
            for (int q = 0; q < 4; q++) {
                a0 += xv[q] * fvs[0 * 128 + lane + 32 * q];
                a1 += xv[q] * fvs[1 * 128 + lane + 32 * q];
            }
            a0 = warp_sum(a0); a1 = warp_sum(a1);
            if (lane == 0) { alps1[n * 2] = a0; alps1[n * 2 + 1] = a1; }
        }
    }
}

// ---------------- CSR build ----------------
__global__ void csr_zero_kernel(int* cnt_js, int* cur_js, int* cnt_ss, int* cur_ss,
                                int* cnt_sj, int* cur_sj)
{
    int i = blockIdx.x * blockDim.x + threadIdx.x;
    if (i < NS) { cnt_js[i] = 0; cur_js[i] = 0; cnt_ss[i] = 0; cur_ss[i] = 0; }
    if (i < NJ) { cnt_sj[i] = 0; cur_sj[i] = 0; }
}

__global__ void hist3_kernel(const int* __restrict__ js_d, const int* __restrict__ ss_d,
                             const int* __restrict__ sj_d,
                             int* __restrict__ cnt_js, int* __restrict__ cnt_ss,
                             int* __restrict__ cnt_sj)
{
    int e = blockIdx.x * blockDim.x + threadIdx.x;
    if (e >= E_ALL) return;
    if (e < E_JS)                  atomicAdd(&cnt_js[js_d[e]], 1);
    else if (e < E_JS + E_SS)      atomicAdd(&cnt_ss[ss_d[e - E_JS]], 1);
    else if (e < E_JS + E_SS + NS) atomicAdd(&cnt_ss[e - E_JS - E_SS], 1);
    else                           atomicAdd(&cnt_sj[sj_d[e - E_JS - E_SS_T]], 1);
}

__global__ void scan3_kernel(const int* __restrict__ cnt_js, int* __restrict__ off_js,
                             const int* __restrict__ cnt_ss, int* __restrict__ off_ss,
                             const int* __restrict__ cnt_sj, int* __restrict__ off_sj)
{
    const int* cnt; int* off; int n;
    if (blockIdx.x == 0)      { cnt = cnt_js; off = off_js; n = NS; }
    else if (blockIdx.x == 1) { cnt = cnt_ss; off = off_ss; n = NS; }
    else                      { cnt = cnt_sj; off = off_sj; n = NJ; }
    __shared__ int sh_carry;
    __shared__ int wsum[32];
    int lane = threadIdx.x & 31, wid = threadIdx.x >> 5;
    if (threadIdx.x == 0) sh_carry = 0;
    __syncthreads();
    for (int base = 0; base < n; base += 1024) {
        int i = base + threadIdx.x;
        int x = (i < n) ? cnt[i] : 0;
        int v = x;
        #pragma unroll
        for (int o = 1; o < 32; o <<= 1) {
            int tv = __shfl_up_sync(0xffffffffu, v, o);
            if (lane >= o) v += tv;
        }
        if (lane == 31) wsum[wid] = v;
        __syncthreads();
        if (wid == 0) {
            int s = wsum[lane];
            #pragma unroll
            for (int o = 1; o < 32; o <<= 1) {
                int tv = __shfl_up_sync(0xffffffffu, s, o);
                if (lane >= o) s += tv;
            }
            wsum[lane] = s;
        }
        __syncthreads();
        int pre = wid ? wsum[wid - 1] : 0;
        int incl = v + pre;
        int carry = sh_carry;
        if (i < n) off[i] = carry + incl - x;
        __syncthreads();
        if (threadIdx.x == 1023) sh_carry = carry + incl;
        __syncthreads();
    }
}

__global__ void fill3_kernel(const int* __restrict__ js_s, const int* __restrict__ js_d,
                             const int* __restrict__ ss_s, const int* __restrict__ ss_d,
                             const int* __restrict__ sj_s, const int* __restrict__ sj_d,
                             const int* __restrict__ off_js, int* __restrict__ cur_js,
                             int* __restrict__ csr_js,
                             const int* __restrict__ off_ss, int* __restrict__ cur_ss,
                             int* __restrict__ csr_ss,
                             const int* __restrict__ off_sj, int* __restrict__ cur_sj,
                             int* __restrict__ csr_sj)
{
    int e = blockIdx.x * blockDim.x + threadIdx.x;
    if (e >= E_ALL) return;
    int s, d;
    const int* off; int* cur; int* csr;
    if (e < E_JS) {
        s = js_s[e]; d = js_d[e]; off = off_js; cur = cur_js; csr = csr_js;
    } else if (e < E_JS + E_SS) {
        int i = e - E_JS; s = ss_s[i]; d = ss_d[i]; off = off_ss; cur = cur_ss; csr = csr_ss;
    } else if (e < E_JS + E_SS + NS) {
        s = d = e - E_JS - E_SS; off = off_ss; cur = cur_ss; csr = csr_ss;
    } else {
        int i = e - E_JS - E_SS_T; s = sj_s[i]; d = sj_d[i]; off = off_sj; cur = cur_sj; csr = csr_sj;
    }
    int pos = off[d] + atomicAdd(&cur[d], 1);
    csr[pos] = s;
}

// ---------------- softmax-aggregate one relation into 128-d accumulator ----------------
__device__ __forceinline__ void agg_one(int o, int deg, const int* __restrict__ csrc,
                                        const float* __restrict__ hw,
                                        const float* __restrict__ alps,
                                        float ad0, float ad1, int lane, float4& out)
{
    if (deg <= 0) return;
    float4 acc0 = make_float4(0.f, 0.f, 0.f, 0.f);
    float4 acc1 = make_float4(0.f, 0.f, 0.f, 0.f);
    float den0 = 0.f, den1 = 0.f;
    const float2* ap = (const float2*)alps;

    int s  = csrc[o];
    int s1 = (deg > 1) ? csrc[o + 1] : 0;
    float2 av = ap[s];
    const float4* hp = (const float4*)(hw + (size_t)s * 256);
    float4 v0 = hp[lane];
    float4 v1 = hp[32 + lane];

    for (int k = 0; k < deg; k++) {
        int s2 = (k + 2 < deg) ? csrc[o + k + 2] : 0;
        float2 avn = ap[s1];
        const float4* hpn = (const float4*)(hw + (size_t)s1 * 256);
        float4 v0n = hpn[lane];
        float4 v1n = hpn[32 + lane];

        float e0 = av.x + ad0; e0 = e0 > 0.f ? e0 : 0.2f * e0;
        float e1 = av.y + ad1; e1 = e1 > 0.f ? e1 : 0.2f * e1;
        float p0 = __expf(e0), p1 = __expf(e1);
        acc0.x = fmaf(p0, v0.x, acc0.x); acc0.y = fmaf(p0, v0.y, acc0.y);
        acc0.z = fmaf(p0, v0.z, acc0.z); acc0.w = fmaf(p0, v0.w, acc0.w);
        acc1.x = fmaf(p1, v1.x, acc1.x); acc1.y = fmaf(p1, v1.y, acc1.y);
        acc1.z = fmaf(p1, v1.z, acc1.z); acc1.w = fmaf(p1, v1.w, acc1.w);
        den0 += p0; den1 += p1;

        s1 = s2; av = avn; v0 = v0n; v1 = v1n;
    }
    float r0 = 1.f / (den0 + 1e-16f);
    float r1 = 1.f / (den1 + 1e-16f);
    out.x = fmaf(acc0.x, r0, out.x); out.y = fmaf(acc0.y, r0, out.y);
    out.z = fmaf(acc0.z, r0, out.z); out.w = fmaf(acc0.w, r0, out.w);
    out.x = fmaf(acc1.x, r1, out.x); out.y = fmaf(acc1.y, r1, out.y);
    out.z = fmaf(acc1.z, r1, out.z); out.w = fmaf(acc1.w, r1, out.w);
}

// ---------------- fused aggregation + folded inter linear ----------------
// layer 0: warps [0,NS): js -> xs (raw, incl cvs); [NS,2NS): ss -> xs2 (raw);
//          [2NS,2NS+NJ): sj -> xj (relu'd, incl cvj)
// layer 1: warps [0,NJ): sj -> xj (relu'd, incl cvj); skill output is dead code.
__global__ void gat_kernel(const int* __restrict__ off_js, const int* __restrict__ cnt_js,
                           const int* __restrict__ csr_js,
                           const int* __restrict__ off_ss, const int* __restrict__ cnt_ss,
                           const int* __restrict__ csr_ss,
                           const int* __restrict__ off_sj, const int* __restrict__ cnt_sj,
                           const int* __restrict__ csr_sj,
                           const float* __restrict__ hw0, const float* __restrict__ hw1,
                           const float* __restrict__ hw2,
                           const float* __restrict__ alps0, const float* __restrict__ alps1,
                           const float* __restrict__ alps2,
                           const float* __restrict__ alpd0, const float* __restrict__ alpd1,
                           const float* __restrict__ alpd2,
                           const float* __restrict__ cvj, const float* __restrict__ cvs,
                           float* __restrict__ xj, float* __restrict__ xs,
                           float* __restrict__ xs2, int layer)
{
    int w    = (blockIdx.x * blockDim.x + threadIdx.x) >> 5;
    int lane = threadIdx.x & 31;
    if (layer == 0) {
        if (w < NS) {
            int d = w;
            float4 acc = ((const float4*)cvs)[lane];
            agg_one(off_js[d], cnt_js[d], csr_js, hw0, alps0,
                    alpd0[d * 2], alpd0[d * 2 + 1], lane, acc);
            ((float4*)(xs + (size_t)d * 128))[lane] = acc;
        } else if (w < 2 * NS) {
            int d = w - NS;
            float4 acc = make_float4(0.f, 0.f, 0.f, 0.f);
            agg_one(off_ss[d], cnt_ss[d], csr_ss, hw2, alps2,
                    alpd2[d * 2], alpd2[d * 2 + 1], lane, acc);
            ((float4*)(xs2 + (size_t)d * 128))[lane] = acc;
        } else if (w < 2 * NS + NJ) {
            int d = w - 2 * NS;
            float4 acc = ((const float4*)cvj)[lane];
            agg_one(off_sj[d], cnt_sj[d], csr_sj, hw1, alps1,
                    alpd1[d * 2], alpd1[d * 2 + 1], lane, acc);
            acc.x = fmaxf(acc.x, 0.f); acc.y = fmaxf(acc.y, 0.f);
            acc.z = fmaxf(acc.z, 0.f); acc.w = fmaxf(acc.w, 0.f);
            ((float4*)(xj + (size_t)d * 128))[lane] = acc;
        }
    } else {
        if (w < NJ) {
            int d = w;
            float4 acc = ((const float4*)cvj)[lane];
            agg_one(off_sj[d], cnt_sj[d], csr_sj, hw1, alps1,
                    alpd1[d * 2], alpd1[d * 2 + 1], lane, acc);
            acc.x = fmaxf(acc.x, 0.f); acc.y = fmaxf(acc.y, 0.f);
            acc.z = fmaxf(acc.z, 0.f); acc.w = fmaxf(acc.w, 0.f);
            ((float4*)(xj + (size_t)d * 128))[lane] = acc;
        }
    }
}

// ---------------- final small kernels ----------------
__global__ void q_kernel(const float* __restrict__ query, const float* __restrict__ Wq,
                         const float* __restrict__ bq, float* __restrict__ q)
{
    int j = threadIdx.x;   // 128
    float acc = bq[j];
    for (int k = 0; k < SBERT; k++) acc += query[k] * Wq[(size_t)k * 128 + j];
    q[j] = acc;
}

__global__ void scores_kernel(const float* __restrict__ emb, const float* __restrict__ q,
                              float* __restrict__ sc, int M)
{
    int wid  = (blockIdx.x * blockDim.x + threadIdx.x) >> 5;
    int lane = threadIdx.x & 31;
    if (wid >= M) return;
    const float* e = emb + (size_t)wid * 128;
    float acc = 0.f;
    #pragma unroll
    for (int qd = 0; qd < 4; qd++) { int k = lane + 32 * qd; acc += e[k] * q[k]; }
    acc = warp_sum(acc);
    if (lane == 0) sc[wid] = acc;
}

// ---------------- host ----------------
extern "C" void kernel_launch(void* const* d_in, const int* in_sizes, int n_in,
                              void* d_out, int out_size)
{
    const float* x_job    = (const float*)d_in[0];
    const float* x_skill  = (const float*)d_in[1];
    const int*   ei_js_s  = (const int*)d_in[2];
    const int*   ei_js_d  = (const int*)d_in[3];
    const int*   ei_sj_s  = (const int*)d_in[4];
    const int*   ei_sj_d  = (const int*)d_in[5];
    const int*   ei_ss_s  = (const int*)d_in[6];
    const int*   ei_ss_d  = (const int*)d_in[7];
    const float* query    = (const float*)d_in[8];
    const float* W0_job   = (const float*)d_in[9];
    const float* b0_job   = (const float*)d_in[10];
    const float* g0_job   = (const float*)d_in[11];
    const float* be0_job  = (const float*)d_in[12];
    const float* W0_skill = (const float*)d_in[13];
    const float* b0_skill = (const float*)d_in[14];
    const float* g0_skill = (const float*)d_in[15];
    const float* be0_skill= (const float*)d_in[16];
    const float* gat_Ws   = (const float*)d_in[17];
    const float* gat_Wd   = (const float*)d_in[18];
    const float* gat_as   = (const float*)d_in[19];
    const float* gat_ad   = (const float*)d_in[20];
    const float* gat_b    = (const float*)d_in[21];
    const float* inter_W  = (const float*)d_in[22];
    const float* inter_b  = (const float*)d_in[23];
    const float* Wjf      = (const float*)d_in[24];
    const float* bjf      = (const float*)d_in[25];
    const float* Wq       = (const float*)d_in[26];
    const float* bq       = (const float*)d_in[27];

    float* out     = (float*)d_out;
    float* scores  = out;
    float* job_emb = out + NJ;
    float* qout    = out + NJ + (size_t)NJ * 128;

    void* p;
    cudaGetSymbolAddress(&p, g_xj);    float* xj    = (float*)p;
    cudaGetSymbolAddress(&p, g_xs);    float* xs    = (float*)p;
    cudaGetSymbolAddress(&p, g_xs2);   float* xs2   = (float*)p;
    cudaGetSymbolAddress(&p, g_hw0);   float* hw0   = (float*)p;
    cudaGetSymbolAddress(&p, g_hw1);   float* hw1   = (float*)p;
    cudaGetSymbolAddress(&p, g_hw2);   float* hw2   = (float*)p;
    cudaGetSymbolAddress(&p, g_mw);    float* mw    = (float*)p;
    cudaGetSymbolAddress(&p, g_fvj);   float* fvj   = (float*)p;
    cudaGetSymbolAddress(&p, g_fvs);   float* fvs   = (float*)p;
    cudaGetSymbolAddress(&p, g_cvj);   float* cvj   = (float*)p;
    cudaGetSymbolAddress(&p, g_cvs);   float* cvs   = (float*)p;
    cudaGetSymbolAddress(&p, g_alps0); float* alps0 = (float*)p;
    cudaGetSymbolAddress(&p, g_alps1); float* alps1 = (float*)p;
    cudaGetSymbolAddress(&p, g_alps2); float* alps2 = (float*)p;
    cudaGetSymbolAddress(&p, g_alpd0); float* alpd0 = (float*)p;
    cudaGetSymbolAddress(&p, g_alpd1); float* alpd1 = (float*)p;
    cudaGetSymbolAddress(&p, g_alpd2); float* alpd2 = (float*)p;
    cudaGetSymbolAddress(&p, g_cnt_js); int* cnt_js = (int*)p;
    cudaGetSymbolAddress(&p, g_off_js); int* off_js = (int*)p;
    cudaGetSymbolAddress(&p, g_cur_js); int* cur_js = (int*)p;
    cudaGetSymbolAddress(&p, g_cnt_ss); int* cnt_ss = (int*)p;
    cudaGetSymbolAddress(&p, g_off_ss); int* off_ss = (int*)p;
    cudaGetSymbolAddress(&p, g_cur_ss); int* cur_ss = (int*)p;
    cudaGetSymbolAddress(&p, g_cnt_sj); int* cnt_sj = (int*)p;
    cudaGetSymbolAddress(&p, g_off_sj); int* off_sj = (int*)p;
    cudaGetSymbolAddress(&p, g_cur_sj); int* cur_sj = (int*)p;
    cudaGetSymbolAddress(&p, g_csr_js); int* csr_js = (int*)p;
    cudaGetSymbolAddress(&p, g_csr_ss); int* csr_ss = (int*)p;
    cudaGetSymbolAddress(&p, g_csr_sj); int* csr_sj = (int*)p;

    GJob none = { nullptr, nullptr, nullptr, nullptr, nullptr, nullptr, nullptr, 0, 0, 0 };
    GJobs J;

    // ---- CSR build ----
    csr_zero_kernel<<<(NJ + 255) / 256, 256>>>(cnt_js, cur_js, cnt_ss, cur_ss, cnt_sj, cur_sj);
    hist3_kernel<<<(E_ALL + 255) / 256, 256>>>(ei_js_d, ei_ss_d, ei_sj_d, cnt_js, cnt_ss, cnt_sj);
    scan3_kernel<<<3, 1024>>>(cnt_js, off_js, cnt_ss, off_ss, cnt_sj, off_sj);
    fill3_kernel<<<(E_ALL + 255) / 256, 256>>>(ei_js_s, ei_js_d, ei_ss_s, ei_ss_d, ei_sj_s, ei_sj_d,
                                               off_js, cur_js, csr_js,
                                               off_ss, cur_ss, csr_ss,
                                               off_sj, cur_sj, csr_sj);

    // ---- weight folding ----
    fold_fv_kernel<<<24, 128>>>(gat_Ws, gat_Wd, gat_as, gat_ad, fvj, fvs);
    fold_cvec_kernel<<<4, 128>>>(gat_b, inter_W, inter_b, cvj, cvs);
    // MW[l][r] = Ws_h @ Winter_h; layer 0 needs rel 0,1,2; layer 1 needs rel 1 only
    {
        for (int r = 0; r < 3; r++) {
            int t = (r == 1) ? 0 : 1;
            for (int h = 0; h < 2; h++) {
                J.j[r * 2 + h] = GJob{
                    gat_Ws + (size_t)r * 32768 + h * 128, nullptr,
                    inter_W + (size_t)t * 32768 + (size_t)h * 16384, nullptr,
                    nullptr, nullptr,
                    mw + (size_t)r * 32768 + h * 128, 128, 256, 256 };
            }
        }
        gemm_kernel<<<dim3(2, 1, 6), 256>>>(J, 128, 128);
        // layer 1, rel 1 (pairs with inter type 0)
        for (int h = 0; h < 2; h++) {
            J.j[h] = GJob{
                gat_Ws + (size_t)(3 + 1) * 32768 + h * 128, nullptr,
                inter_W + (size_t)(2 + 0) * 32768 + (size_t)h * 16384, nullptr,
                nullptr, nullptr,
                mw + (size_t)(3 + 1) * 32768 + h * 128, 128, 256, 256 };
        }
        for (int z = 2; z < 6; z++) J.j[z] = none;
        gemm_kernel<<<dim3(2, 1, 2), 256>>>(J, 128, 128);
    }

    // ---- initial per-type linear + fused LN + relu ----
    J.j[0] = GJob{ x_job,   nullptr, W0_job,   b0_job,   g0_job,   be0_job,   xj, NJ, SBERT, 128 };
    J.j[1] = GJob{ x_skill, nullptr, W0_skill, b0_skill, g0_skill, be0_skill, xs, NS, SBERT, 128 };
    for (int z = 2; z < 6; z++) J.j[z] = none;
    gemm_kernel<<<dim3((NJ + 63) / 64, 1, 2), 256>>>(J, 128, SBERT);

    // ---- layer 1 (all 3 relations) ----
    J.j[0] = GJob{ xj, nullptr, mw + 0 * 32768, nullptr, nullptr, nullptr, hw0, NJ, 128, 256 };
    J.j[1] = GJob{ xs, nullptr, mw + 1 * 32768, nullptr, nullptr, nullptr, hw1, NS, 128, 256 };
    J.j[2] = GJob{ xs, nullptr, mw + 2 * 32768, nullptr, nullptr, nullptr, hw2, NS, 128, 256 };
    for (int z = 3; z < 6; z++) J.j[z] = none;
    gemm_kernel<<<dim3((NJ + 63) / 64, 2, 3), 256>>>(J, 256, 128);

    alpha_fold_kernel<<<((NJ + NS) * 32 + 255) / 256, 256>>>(
        xj, xs, nullptr, fvj, fvs, alps0, alps1, alps2, alpd0, alpd1, alpd2, 0);

    gat_kernel<<<((2 * NS + NJ) * 32 + 255) / 256, 256>>>(
        off_js, cnt_js, csr_js, off_ss, cnt_ss, csr_ss, off_sj, cnt_sj, csr_sj,
        hw0, hw1, hw2, alps0, alps1, alps2, alpd0, alpd1, alpd2,
        cvj, cvs, xj, xs, xs2, 0);

    // ---- layer 2 (sj relation only; skill output is dead) ----
    J.j[0] = GJob{ xs, xs2, mw + (size_t)(3 + 1) * 32768, nullptr, nullptr, nullptr, hw1, NS, 128, 256 };
    for (int z = 1; z < 6; z++) J.j[z] = none;
    gemm_kernel<<<dim3((NS + 63) / 64, 2, 1), 256>>>(J, 256, 128);

    alpha_fold_kernel<<<((NJ + NS) * 32 + 255) / 256, 256>>>(
        xj, xs, xs2, fvj + 512, fvs + 1024, alps0, alps1, alps2, alpd0, alpd1, alpd2, 1);

    gat_kernel<<<(NJ * 32 + 255) / 256, 256>>>(
        off_js, cnt_js, csr_js, off_ss, cnt_ss, csr_ss, off_sj, cnt_sj, csr_sj,
        hw0, hw1, hw2, alps0, alps1, alps2, alpd0, alpd1, alpd2,
        cvj + 128, cvs + 128, xj, xs, xs2, 1);

    // ---- final projections ----
    J.j[0] = GJob{ xj, nullptr, Wjf, bjf, nullptr, nullptr, job_emb, NJ, 128, 128 };
    for (int z = 1; z < 6; z++) J.j[z] = none;
    gemm_kernel<<<dim3((NJ + 63) / 64, 1, 1), 256>>>(J, 128, 128);
    q_kernel<<<1, 128>>>(query, Wq, bq, qout);
    scores_kernel<<<(NJ * 32 + 255) / 256, 256>>>(job_emb, qout, scores, NJ);
}

// round 13
// speedup vs baseline: 3.6343x; 1.0063x over previous
#include <cuda_runtime.h>
#include <cuda_bf16.h>
#include <math.h>

#define NJ 30000
#define NS 12000
#define E_JS 300000
#define E_SJ 300000
#define E_SS 150000
#define E_SS_T (E_SS + NS)
#define E_ALL (E_JS + E_SS_T + E_SJ)
#define SBERT 384
#define HID 128
#define HHID 256

// ---------------- scratch (device globals; no allocation allowed) ----------------
__device__ float g_xj[NJ * HID];
__device__ float g_xs[NS * HID];
__device__ float g_xs2[NS * HID];
__device__ float g_hw0[NJ * HHID];
__device__ float g_hw1[NS * HHID];
__device__ float g_hw2[NS * HHID];
__device__ float g_mw[2 * 3 * 128 * 256];
__device__ float g_fvj[2 * 4 * 128];
__device__ float g_fvs[2 * 8 * 128];
__device__ float g_cvj[2 * 128];
__device__ float g_cvs[2 * 128];
__device__ float g_alps0[NJ * 2], g_alps1[NS * 2], g_alps2[NS * 2];
__device__ float g_alpd0[NS * 2], g_alpd1[NJ * 2], g_alpd2[NS * 2];
// CSR: cnt/cur packed into ONE buffer for single zero pass
// layout: [cnt_js NS][cur_js NS][cnt_ss NS][cur_ss NS][cnt_sj NJ][cur_sj NJ]
#define CNTCUR_N (4 * NS + 2 * NJ)
__device__ int g_cntcur[CNTCUR_N];
__device__ int g_off_js[NS], g_off_ss[NS], g_off_sj[NJ];
__device__ int g_csr_js[E_JS];
__device__ int g_csr_ss[E_SS_T];
__device__ int g_csr_sj[E_SJ];

// ---------------- helpers ----------------
__device__ __forceinline__ float warp_sum(float v) {
    #pragma unroll
    for (int o = 16; o; o >>= 1) v += __shfl_xor_sync(0xffffffffu, v, o);
    return v;
}
__device__ __forceinline__ unsigned long long pk2(float lo, float hi) {
    unsigned long long r;
    asm("mov.b64 %0, {%1, %2};" : "=l"(r) : "r"(__float_as_uint(lo)), "r"(__float_as_uint(hi)));
    return r;
}
__device__ __forceinline__ void upk2(unsigned long long v, float& lo, float& hi) {
    unsigned int a, b;
    asm("mov.b64 {%0, %1}, %2;" : "=r"(a), "=r"(b) : "l"(v));
    lo = __uint_as_float(a); hi = __uint_as_float(b);
}
__device__ __forceinline__ void fma2(unsigned long long& d, unsigned long long a, unsigned long long b) {
    asm("fma.rn.f32x2 %0, %1, %2, %0;" : "+l"(d) : "l"(a), "l"(b));
}

// ---------------- batched GEMM (up to 6 jobs via blockIdx.z) ----------------
// Options per job: A2 (relu(A+A2) on load), bias, g/be (LN+relu epilogue, N==128),
// qv/sc (score = row . qv written to sc, N==128).
struct GJob {
    const float* A; const float* A2; const float* B; const float* bias;
    const float* g; const float* be; const float* qv;
    float* C; float* sc; int M; int lda; int ldC;
};
struct GJobs { GJob j[6]; };

__global__ __launch_bounds__(256) void gemm_kernel(GJobs js, int N, int K)
{
    GJob jb = js.j[blockIdx.z];
    const int row0 = blockIdx.x * 64;
    if (jb.A == nullptr || row0 >= jb.M) return;
    const float* __restrict__ A = jb.A;
    const float* __restrict__ B = jb.B;
    const int M = jb.M;
    const int lda = jb.lda;

    __shared__ float As[16][68];
    __shared__ float Bs[16][128];

    const int t   = threadIdx.x;
    const int tc  = t & 31;
    const int tr  = t >> 5;
    const int col0 = blockIdx.y * 128;

    const int arow = t >> 2;
    const int akq  = (t & 3) * 4;
    const int bs0k = t >> 5;
    const int bs0c = (t & 31) * 4;
    const int bs1k = bs0k + 8;

    unsigned long long acc2[4][4];
    #pragma unroll
    for (int i = 0; i < 4; i++)
        #pragma unroll
        for (int j = 0; j < 4; j++) acc2[i][j] = 0ull;

    for (int k0 = 0; k0 < K; k0 += 16) {
        float4 av = make_float4(0.f, 0.f, 0.f, 0.f);
        if (row0 + arow < M) {
            av = *(const float4*)(A + (size_t)(row0 + arow) * lda + k0 + akq);
            if (jb.A2) {
                float4 a2 = *(const float4*)(jb.A2 + (size_t)(row0 + arow) * lda + k0 + akq);
                av.x = fmaxf(av.x + a2.x, 0.f); av.y = fmaxf(av.y + a2.y, 0.f);
                av.z = fmaxf(av.z + a2.z, 0.f); av.w = fmaxf(av.w + a2.w, 0.f);
            }
        }
        float4 bv0 = *(const float4*)(B + (size_t)(k0 + bs0k) * N + col0 + bs0c);
        float4 bv1 = *(const float4*)(B + (size_t)(k0 + bs1k) * N + col0 + bs0c);

        __syncthreads();
        As[akq + 0][arow] = av.x;
        As[akq + 1][arow] = av.y;
        As[akq + 2][arow] = av.z;
        As[akq + 3][arow] = av.w;
        *(float4*)&Bs[bs0k][bs0c] = bv0;
        *(float4*)&Bs[bs1k][bs0c] = bv1;
        __syncthreads();

        #pragma unroll
        for (int kk = 0; kk < 16; kk++) {
            float4 b = *(float4*)&Bs[kk][tc * 4];
            ulonglong2 apA = *(ulonglong2*)&As[kk][tr * 8];
            ulonglong2 apB = *(ulonglong2*)&As[kk][tr * 8 + 4];
            unsigned long long ap0 = apA.x, ap1 = apA.y, ap2 = apB.x, ap3 = apB.y;
            unsigned long long bd0 = pk2(b.x, b.x);
            unsigned long long bd1 = pk2(b.y, b.y);
            unsigned long long bd2 = pk2(b.z, b.z);
            unsigned long long bd3 = pk2(b.w, b.w);
            fma2(acc2[0][0], ap0, bd0); fma2(acc2[0][1], ap0, bd1);
            fma2(acc2[0][2], ap0, bd2); fma2(acc2[0][3], ap0, bd3);
            fma2(acc2[1][0], ap1, bd0); fma2(acc2[1][1], ap1, bd1);
            fma2(acc2[1][2], ap1, bd2); fma2(acc2[1][3], ap1, bd3);
            fma2(acc2[2][0], ap2, bd0); fma2(acc2[2][1], ap2, bd1);
            fma2(acc2[2][2], ap2, bd2); fma2(acc2[2][3], ap2, bd3);
            fma2(acc2[3][0], ap3, bd0); fma2(acc2[3][1], ap3, bd1);
            fma2(acc2[3][2], ap3, bd2); fma2(acc2[3][3], ap3, bd3);
        }
    }

    float acc[8][4];
    #pragma unroll
    for (int i = 0; i < 4; i++)
        #pragma unroll
        for (int j = 0; j < 4; j++)
            upk2(acc2[i][j], acc[2 * i][j], acc[2 * i + 1][j]);

    float4 bv = make_float4(0.f, 0.f, 0.f, 0.f);
    if (jb.bias) bv = *(const float4*)(jb.bias + col0 + tc * 4);

    if (jb.g) {
        // LN + relu epilogue: warp (fixed tr) holds the whole 128-wide row.
        float4 gv  = *(const float4*)(jb.g  + tc * 4);
        float4 bev = *(const float4*)(jb.be + tc * 4);
        #pragma unroll
        for (int i = 0; i < 8; i++) {
            float4 o;
            o.x = acc[i][0] + bv.x; o.y = acc[i][1] + bv.y;
            o.z = acc[i][2] + bv.z; o.w = acc[i][3] + bv.w;
            float s  = warp_sum(o.x + o.y + o.z + o.w);
            float sq = warp_sum(o.x * o.x + o.y * o.y + o.z * o.z + o.w * o.w);
            float mu  = s * (1.f / 128.f);
            float var = sq * (1.f / 128.f) - mu * mu;
            float r = rsqrtf(var + 1e-5f);
            o.x = fmaxf((o.x - mu) * r * gv.x + bev.x, 0.f);
            o.y = fmaxf((o.y - mu) * r * gv.y + bev.y, 0.f);
            o.z = fmaxf((o.z - mu) * r * gv.z + bev.z, 0.f);
            o.w = fmaxf((o.w - mu) * r * gv.w + bev.w, 0.f);
            int row = row0 + tr * 8 + i;
            if (row < M)
                *(float4*)(jb.C + (size_t)row * jb.ldC + col0 + tc * 4) = o;
        }
    } else if (jb.qv) {
        // bias + write + fused dot-with-q epilogue (N==128)
        float4 qv4 = *(const float4*)(jb.qv + tc * 4);
        #pragma unroll
        for (int i = 0; i < 8; i++) {
            int row = row0 + tr * 8 + i;
            float4 o;
            o.x = acc[i][0] + bv.x; o.y = acc[i][1] + bv.y;
            o.z = acc[i][2] + bv.z; o.w = acc[i][3] + bv.w;
            float dot = warp_sum(o.x * qv4.x + o.y * qv4.y + o.z * qv4.z + o.w * qv4.w);
            if (row < M) {
                *(float4*)(jb.C + (size_t)row * jb.ldC + tc * 4) = o;
                if (tc == 0) jb.sc[row] = dot;
            }
        }
    } else {
        #pragma unroll
        for (int i = 0; i < 8; i++) {
            int row = row0 + tr * 8 + i;
            if (row < M) {
                float4 o;
                o.x = acc[i][0] + bv.x; o.y = acc[i][1] + bv.y;
                o.z = acc[i][2] + bv.z; o.w = acc[i][3] + bv.w;
                *(float4*)(jb.C + (size_t)row * jb.ldC + col0 + tc * 4) = o;
            }
        }
    }
}

// ---------------- weight folding: alpha vectors ----------------
// fvj[l][col][k]: col 0,1 = Ws(rel0)@as heads; col 2,3 = Wd(rel1)@ad heads
// fvs[l][col][k]: col 0,1 = Ws(rel1)@as; 2,3 = Ws(rel2)@as; 4,5 = Wd(rel0)@ad; 6,7 = Wd(rel2)@ad
__global__ void fold_fv_kernel(const float* __restrict__ Ws, const float* __restrict__ Wd,
                               const float* __restrict__ as_, const float* __restrict__ ad_,
                               float* __restrict__ fvj, float* __restrict__ fvs)
{
    int l = blockIdx.x / 12, v = blockIdx.x % 12;
    int k = threadIdx.x;
    int rel, h, col, useWd, isJob;
    if (v < 2)       { rel = 0; h = v;      col = v;     useWd = 0; isJob = 1; }
    else if (v < 4)  { rel = 1; h = v - 2;  col = v;     useWd = 1; isJob = 1; }
    else if (v < 6)  { rel = 1; h = v - 4;  col = v - 4; useWd = 0; isJob = 0; }
    else if (v < 8)  { rel = 2; h = v - 6;  col = v - 4; useWd = 0; isJob = 0; }
    else if (v < 10) { rel = 0; h = v - 8;  col = v - 4; useWd = 1; isJob = 0; }
    else             { rel = 2; h = v - 10; col = v - 4; useWd = 1; isJob = 0; }
    const float* W = (useWd ? Wd : Ws) + (size_t)(l * 3 + rel) * 32768 + h * 128;
    const float* a = (useWd ? ad_ : as_) + (size_t)((l * 3 + rel) * 2 + h) * 128;
    float acc = 0.f;
    #pragma unroll 8
    for (int c = 0; c < 128; c++) acc += W[(size_t)k * 256 + c] * a[c];
    float* out = isJob ? (fvj + l * 512) : (fvs + l * 1024);
    out[col * 128 + k] = acc;
}

// ---------------- weight folding: constant vectors ----------------
__global__ void fold_cvec_kernel(const float* __restrict__ gat_b,
                                 const float* __restrict__ inter_W,
                                 const float* __restrict__ inter_b,
                                 float* __restrict__ cvj, float* __restrict__ cvs)
{
    int l = blockIdx.x >> 1, t = blockIdx.x & 1;
    int j = threadIdx.x;
    const float* W = inter_W + (size_t)(l * 2 + t) * 256 * 128;
    float acc = inter_b[(l * 2 + t) * 128 + j];
    if (t == 0) {
        const float* b = gat_b + (size_t)(l * 3 + 1) * 256;
        for (int c = 0; c < 256; c++) acc += b[c] * W[(size_t)c * 128 + j];
        cvj[l * 128 + j] = acc;
    } else {
        const float* b0 = gat_b + (size_t)(l * 3 + 0) * 256;
        const float* b2 = gat_b + (size_t)(l * 3 + 2) * 256;
        for (int c = 0; c < 256; c++) acc += (b0[c] + b2[c]) * W[(size_t)c * 128 + j];
        cvs[l * 128 + j] = acc;
    }
}

// ---------------- fused alpha (src+dst) ----------------
// layer 0: jobs -> alps0+alpd1; skills -> alps1,alps2,alpd0,alpd2 (grid NJ+NS warps)
// layer 1: ONLY skills -> alps1 from relu(xs+xs2)  (grid NS warps; job part fused into gat_kernel)
__global__ void alpha_fold_kernel(const float* __restrict__ xj, const float* __restrict__ xs,
                                  const float* __restrict__ xs2,
                                  const float* __restrict__ fvj, const float* __restrict__ fvs,
                                  float* __restrict__ alps0, float* __restrict__ alps1,
                                  float* __restrict__ alps2,
                                  float* __restrict__ alpd0, float* __restrict__ alpd1,
                                  float* __restrict__ alpd2, int layer)
{
    int w    = (blockIdx.x * blockDim.x + threadIdx.x) >> 5;
    int lane = threadIdx.x & 31;
    if (layer == 0) {
        if (w < NJ) {
            const float* xp = xj + (size_t)w * 128;
            float xv[4];
            #pragma unroll
            for (int q = 0; q < 4; q++) xv[q] = xp[lane + 32 * q];
            float a[4];
            #pragma unroll
            for (int col = 0; col < 4; col++) {
                float acc = 0.f;
                #pragma unroll
                for (int q = 0; q < 4; q++) acc += xv[q] * fvj[col * 128 + lane + 32 * q];
                a[col] = warp_sum(acc);
            }
            if (lane == 0) {
                alps0[w * 2] = a[0]; alps0[w * 2 + 1] = a[1];
                alpd1[w * 2] = a[2]; alpd1[w * 2 + 1] = a[3];
            }
        } else if (w < NJ + NS) {
            int n = w - NJ;
            const float* xp = xs + (size_t)n * 128;
            float xv[4];
            #pragma unroll
            for (int q = 0; q < 4; q++) xv[q] = xp[lane + 32 * q];
            float a[8];
            #pragma unroll
            for (int col = 0; col < 8; col++) {
                float acc = 0.f;
                #pragma unroll
                for (int q = 0; q < 4; q++) acc += xv[q] * fvs[col * 128 + lane + 32 * q];
                a[col] = warp_sum(acc);
            }
            if (lane == 0) {
                alps1[n * 2] = a[0]; alps1[n * 2 + 1] = a[1];
                alps2[n * 2] = a[2]; alps2[n * 2 + 1] = a[3];
                alpd0[n * 2] = a[4]; alpd0[n * 2 + 1] = a[5];
                alpd2[n * 2] = a[6]; alpd2[n * 2 + 1] = a[7];
            }
        }
    } else {
        if (w < NS) {
            const float* xp  = xs  + (size_t)w * 128;
            const float* xp2 = xs2 + (size_t)w * 128;
            float xv[4];
            #pragma unroll
            for (int q = 0; q < 4; q++)
                xv[q] = fmaxf(xp[lane + 32 * q] + xp2[lane + 32 * q], 0.f);
            float a0 = 0.f, a1 = 0.f;
            #pragma unroll
            for (int q = 0; q < 4; q++) {
                a0 += xv[q] * fvs[0 * 128 + lane + 32 * q];
                a1 += xv[q] * fvs[1 * 128 + lane + 32 * q];
            }
            a0 = warp_sum(a0); a1 = warp_sum(a1);
            if (lane == 0) { alps1[w * 2] = a0; alps1[w * 2 + 1] = a1; }
        }
    }
}

// ---------------- CSR build ----------------
__global__ void csr_zero_kernel(int* __restrict__ cntcur)
{
    int i = blockIdx.x * blockDim.x + threadIdx.x;
    if (i < CNTCUR_N) cntcur[i] = 0;
}

__global__ void hist3_kernel(const int* __restrict__ js_d, const int* __restrict__ ss_d,
                             const int* __restrict__ sj_d,
                             int* __restrict__ cnt_js, int* __restrict__ cnt_ss,
                             int* __restrict__ cnt_sj)
{
    int e = blockIdx.x * blockDim.x + threadIdx.x;
    if (e >= E_ALL) return;
    if (e < E_JS)                  atomicAdd(&cnt_js[js_d[e]], 1);
    else if (e < E_JS + E_SS)      atomicAdd(&cnt_ss[ss_d[e - E_JS]], 1);
    else if (e < E_JS + E_SS + NS) atomicAdd(&cnt_ss[e - E_JS - E_SS], 1);
    else                           atomicAdd(&cnt_sj[sj_d[e - E_JS - E_SS_T]], 1);
}

__global__ void scan3_kernel(const int* __restrict__ cnt_js, int* __restrict__ off_js,
                             const int* __restrict__ cnt_ss, int* __restrict__ off_ss,
                             const int* __restrict__ cnt_sj, int* __restrict__ off_sj)
{
    const int* cnt; int* off; int n;
    if (blockIdx.x == 0)      { cnt = cnt_js; off = off_js; n = NS; }
    else if (blockIdx.x == 1) { cnt = cnt_ss; off = off_ss; n = NS; }
    else                      { cnt = cnt_sj; off = off_sj; n = NJ; }
    __shared__ int sh_carry;
    __shared__ int wsum[32];
    int lane = threadIdx.x & 31, wid = threadIdx.x >> 5;
    if (threadIdx.x == 0) sh_carry = 0;
    __syncthreads();
    for (int base = 0; base < n; base += 1024) {
        int i = base + threadIdx.x;
        int x = (i < n) ? cnt[i] : 0;
        int v = x;
        #pragma unroll
        for (int o = 1; o < 32; o <<= 1) {
            int tv = __shfl_up_sync(0xffffffffu, v, o);
            if (lane >= o) v += tv;
        }
        if (lane == 31) wsum[wid] = v;
        __syncthreads();
        if (wid == 0) {
            int s = wsum[lane];
            #pragma unroll
            for (int o = 1; o < 32; o <<= 1) {
                int tv = __shfl_up_sync(0xffffffffu, s, o);
                if (lane >= o) s += tv;
            }
            wsum[lane] = s;
        }
        __syncthreads();
        int pre = wid ? wsum[wid - 1] : 0;
        int incl = v + pre;
        int carry = sh_carry;
        if (i < n) off[i] = carry + incl - x;
        __syncthreads();
        if (threadIdx.x == 1023) sh_carry = carry + incl;
        __syncthreads();
    }
}

__global__ void fill3_kernel(const int* __restrict__ js_s, const int* __restrict__ js_d,
                             const int* __restrict__ ss_s, const int* __restrict__ ss_d,
                             const int* __restrict__ sj_s, const int* __restrict__ sj_d,
                             const int* __restrict__ off_js, int* __restrict__ cur_js,
                             int* __restrict__ csr_js,
                             const int* __restrict__ off_ss, int* __restrict__ cur_ss,
                             int* __restrict__ csr_ss,
                             const int* __restrict__ off_sj, int* __restrict__ cur_sj,
                             int* __restrict__ csr_sj)
{
    int e = blockIdx.x * blockDim.x + threadIdx.x;
    if (e >= E_ALL) return;
    int s, d;
    const int* off; int* cur; int* csr;
    if (e < E_JS) {
        s = js_s[e]; d = js_d[e]; off = off_js; cur = cur_js; csr = csr_js;
    } else if (e < E_JS + E_SS) {
        int i = e - E_JS; s = ss_s[i]; d = ss_d[i]; off = off_ss; cur = cur_ss; csr = csr_ss;
    } else if (e < E_JS + E_SS + NS) {
        s = d = e - E_JS - E_SS; off = off_ss; cur = cur_ss; csr = csr_ss;
    } else {
        int i = e - E_JS - E_SS_T; s = sj_s[i]; d = sj_d[i]; off = off_sj; cur = cur_sj; csr = csr_sj;
    }
    int pos = off[d] + atomicAdd(&cur[d], 1);
    csr[pos] = s;
}

// ---------------- softmax-aggregate one relation into 128-d accumulator ----------------
__device__ __forceinline__ void agg_one(int o, int deg, const int* __restrict__ csrc,
                                        const float* __restrict__ hw,
                                        const float* __restrict__ alps,
                                        float ad0, float ad1, int lane, float4& out)
{
    if (deg <= 0) return;
    float4 acc0 = make_float4(0.f, 0.f, 0.f, 0.f);
    float4 acc1 = make_float4(0.f, 0.f, 0.f, 0.f);
    float den0 = 0.f, den1 = 0.f;
    const float2* ap = (const float2*)alps;

    int s  = csrc[o];
    int s1 = (deg > 1) ? csrc[o + 1] : 0;
    float2 av = ap[s];
    const float4* hp = (const float4*)(hw + (size_t)s * 256);
    float4 v0 = hp[lane];
    float4 v1 = hp[32 + lane];

    for (int k = 0; k < deg; k++) {
        int s2 = (k + 2 < deg) ? csrc[o + k + 2] : 0;
        float2 avn = ap[s1];
        const float4* hpn = (const float4*)(hw + (size_t)s1 * 256);
        float4 v0n = hpn[lane];
        float4 v1n = hpn[32 + lane];

        float e0 = av.x + ad0; e0 = e0 > 0.f ? e0 : 0.2f * e0;
        float e1 = av.y + ad1; e1 = e1 > 0.f ? e1 : 0.2f * e1;
        float p0 = __expf(e0), p1 = __expf(e1);
        acc0.x = fmaf(p0, v0.x, acc0.x); acc0.y = fmaf(p0, v0.y, acc0.y);
        acc0.z = fmaf(p0, v0.z, acc0.z); acc0.w = fmaf(p0, v0.w, acc0.w);
        acc1.x = fmaf(p1, v1.x, acc1.x); acc1.y = fmaf(p1, v1.y, acc1.y);
        acc1.z = fmaf(p1, v1.z, acc1.z); acc1.w = fmaf(p1, v1.w, acc1.w);
        den0 += p0; den1 += p1;

        s1 = s2; av = avn; v0 = v0n; v1 = v1n;
    }
    float r0 = 1.f / (den0 + 1e-16f);
    float r1 = 1.f / (den1 + 1e-16f);
    out.x = fmaf(acc0.x, r0, out.x); out.y = fmaf(acc0.y, r0, out.y);
    out.z = fmaf(acc0.z, r0, out.z); out.w = fmaf(acc0.w, r0, out.w);
    out.x = fmaf(acc1.x, r1, out.x); out.y = fmaf(acc1.y, r1, out.y);
    out.z = fmaf(acc1.z, r1, out.z); out.w = fmaf(acc1.w, r1, out.w);
}

// ---------------- fused aggregation + folded inter linear ----------------
// layer 0: warps [0,NS): js -> xs (raw, incl cvs); [NS,2NS): ss -> xs2 (raw);
//          [2NS,2NS+NJ): sj -> xj (relu'd, incl cvj) + fused layer-2 alpd1 dots (fvj2)
// layer 1: warps [0,NJ): sj -> xj (relu'd, incl cvj)
__global__ void gat_kernel(const int* __restrict__ off_js, const int* __restrict__ cnt_js,
                           const int* __restrict__ csr_js,
                           const int* __restrict__ off_ss, const int* __restrict__ cnt_ss,
                           const int* __restrict__ csr_ss,
                           const int* __restrict__ off_sj, const int* __restrict__ cnt_sj,
                           const int* __restrict__ csr_sj,
                           const float* __restrict__ hw0, const float* __restrict__ hw1,
                           const float* __restrict__ hw2,
                           const float* __restrict__ alps0, const float* __restrict__ alps1,
                           const float* __restrict__ alps2,
                           const float* __restrict__ alpd0, const float* __restrict__ alpd1,
                           const float* __restrict__ alpd2,
                           const float* __restrict__ cvj, const float* __restrict__ cvs,
                           const float* __restrict__ fvj2,
                           float* __restrict__ xj, float* __restrict__ xs,
                           float* __restrict__ xs2,
                           float* __restrict__ alpd1_out, int layer)
{
    int w    = (blockIdx.x * blockDim.x + threadIdx.x) >> 5;
    int lane = threadIdx.x & 31;
    if (layer == 0) {
        if (w < NS) {
            int d = w;
            float4 acc = ((const float4*)cvs)[lane];
            agg_one(off_js[d], cnt_js[d], csr_js, hw0, alps0,
                    alpd0[d * 2], alpd0[d * 2 + 1], lane, acc);
            ((float4*)(xs + (size_t)d * 128))[lane] = acc;
        } else if (w < 2 * NS) {
            int d = w - NS;
            float4 acc = make_float4(0.f, 0.f, 0.f, 0.f);
            agg_one(off_ss[d], cnt_ss[d], csr_ss, hw2, alps2,
                    alpd2[d * 2], alpd2[d * 2 + 1], lane, acc);
            ((float4*)(xs2 + (size_t)d * 128))[lane] = acc;
        } else if (w < 2 * NS + NJ) {
            int d = w - 2 * NS;
            float4 acc = ((const float4*)cvj)[lane];
            agg_one(off_sj[d], cnt_sj[d], csr_sj, hw1, alps1,
                    alpd1[d * 2], alpd1[d * 2 + 1], lane, acc);
            acc.x = fmaxf(acc.x, 0.f); acc.y = fmaxf(acc.y, 0.f);
            acc.z = fmaxf(acc.z, 0.f); acc.w = fmaxf(acc.w, 0.f);
            ((float4*)(xj + (size_t)d * 128))[lane] = acc;
            // fused layer-2 alpd1: dot new row with fvj2 cols 2,3
            float4 f2 = ((const float4*)(fvj2 + 2 * 128))[lane];
            float4 f3 = ((const float4*)(fvj2 + 3 * 128))[lane];
            float a2 = warp_sum(acc.x * f2.x + acc.y * f2.y + acc.z * f2.z + acc.w * f2.w);
            float a3 = warp_sum(acc.x * f3.x + acc.y * f3.y + acc.z * f3.z + acc.w * f3.w);
            if (lane == 0) { alpd1_out[d * 2] = a2; alpd1_out[d * 2 + 1] = a3; }
        }
    } else {
        if (w < NJ) {
            int d = w;
            float4 acc = ((const float4*)cvj)[lane];
            agg_one(off_sj[d], cnt_sj[d], csr_sj, hw1, alps1,
                    alpd1[d * 2], alpd1[d * 2 + 1], lane, acc);
            acc.x = fmaxf(acc.x, 0.f); acc.y = fmaxf(acc.y, 0.f);
            acc.z = fmaxf(acc.z, 0.f); acc.w = fmaxf(acc.w, 0.f);
            ((float4*)(xj + (size_t)d * 128))[lane] = acc;
        }
    }
}

// ---------------- q projection ----------------
__global__ void q_kernel(const float* __restrict__ query, const float* __restrict__ Wq,
                         const float* __restrict__ bq, float* __restrict__ q)
{
    int j = threadIdx.x;
    float acc = bq[j];
    for (int k = 0; k < SBERT; k++) acc += query[k] * Wq[(size_t)k * 128 + j];
    q[j] = acc;
}

// ---------------- host ----------------
extern "C" void kernel_launch(void* const* d_in, const int* in_sizes, int n_in,
                              void* d_out, int out_size)
{
    const float* x_job    = (const float*)d_in[0];
    const float* x_skill  = (const float*)d_in[1];
    const int*   ei_js_s  = (const int*)d_in[2];
    const int*   ei_js_d  = (const int*)d_in[3];
    const int*   ei_sj_s  = (const int*)d_in[4];
    const int*   ei_sj_d  = (const int*)d_in[5];
    const int*   ei_ss_s  = (const int*)d_in[6];
    const int*   ei_ss_d  = (const int*)d_in[7];
    const float* query    = (const float*)d_in[8];
    const float* W0_job   = (const float*)d_in[9];
    const float* b0_job   = (const float*)d_in[10];
    const float* g0_job   = (const float*)d_in[11];
    const float* be0_job  = (const float*)d_in[12];
    const float* W0_skill = (const float*)d_in[13];
    const float* b0_skill = (const float*)d_in[14];
    const float* g0_skill = (const float*)d_in[15];
    const float* be0_skill= (const float*)d_in[16];
    const float* gat_Ws   = (const float*)d_in[17];
    const float* gat_Wd   = (const float*)d_in[18];
    const float* gat_as   = (const float*)d_in[19];
    const float* gat_ad   = (const float*)d_in[20];
    const float* gat_b    = (const float*)d_in[21];
    const float* inter_W  = (const float*)d_in[22];
    const float* inter_b  = (const float*)d_in[23];
    const float* Wjf      = (const float*)d_in[24];
    const float* bjf      = (const float*)d_in[25];
    const float* Wq       = (const float*)d_in[26];
    const float* bq       = (const float*)d_in[27];

    float* out     = (float*)d_out;
    float* scores  = out;
    float* job_emb = out + NJ;
    float* qout    = out + NJ + (size_t)NJ * 128;

    void* p;
    cudaGetSymbolAddress(&p, g_xj);    float* xj    = (float*)p;
    cudaGetSymbolAddress(&p, g_xs);    float* xs    = (float*)p;
    cudaGetSymbolAddress(&p, g_xs2);   float* xs2   = (float*)p;
    cudaGetSymbolAddress(&p, g_hw0);   float* hw0   = (float*)p;
    cudaGetSymbolAddress(&p, g_hw1);   float* hw1   = (float*)p;
    cudaGetSymbolAddress(&p, g_hw2);   float* hw2   = (float*)p;
    cudaGetSymbolAddress(&p, g_mw);    float* mw    = (float*)p;
    cudaGetSymbolAddress(&p, g_fvj);   float* fvj   = (float*)p;
    cudaGetSymbolAddress(&p, g_fvs);   float* fvs   = (float*)p;
    cudaGetSymbolAddress(&p, g_cvj);   float* cvj   = (float*)p;
    cudaGetSymbolAddress(&p, g_cvs);   float* cvs   = (float*)p;
    cudaGetSymbolAddress(&p, g_alps0); float* alps0 = (float*)p;
    cudaGetSymbolAddress(&p, g_alps1); float* alps1 = (float*)p;
    cudaGetSymbolAddress(&p, g_alps2); float* alps2 = (float*)p;
    cudaGetSymbolAddress(&p, g_alpd0); float* alpd0 = (float*)p;
    cudaGetSymbolAddress(&p, g_alpd1); float* alpd1 = (float*)p;
    cudaGetSymbolAddress(&p, g_alpd2); float* alpd2 = (float*)p;
    cudaGetSymbolAddress(&p, g_cntcur); int* cntcur = (int*)p;
    int* cnt_js = cntcur;
    int* cur_js = cntcur + NS;
    int* cnt_ss = cntcur + 2 * NS;
    int* cur_ss = cntcur + 3 * NS;
    int* cnt_sj = cntcur + 4 * NS;
    int* cur_sj = cntcur + 4 * NS + NJ;
    cudaGetSymbolAddress(&p, g_off_js); int* off_js = (int*)p;
    cudaGetSymbolAddress(&p, g_off_ss); int* off_ss = (int*)p;
    cudaGetSymbolAddress(&p, g_off_sj); int* off_sj = (int*)p;
    cudaGetSymbolAddress(&p, g_csr_js); int* csr_js = (int*)p;
    cudaGetSymbolAddress(&p, g_csr_ss); int* csr_ss = (int*)p;
    cudaGetSymbolAddress(&p, g_csr_sj); int* csr_sj = (int*)p;

    GJob none = { nullptr, nullptr, nullptr, nullptr, nullptr, nullptr, nullptr,
                  nullptr, nullptr, 0, 0, 0 };
    GJobs J;

    // ---- CSR build ----
    csr_zero_kernel<<<(CNTCUR_N + 255) / 256, 256>>>(cntcur);
    hist3_kernel<<<(E_ALL + 255) / 256, 256>>>(ei_js_d, ei_ss_d, ei_sj_d, cnt_js, cnt_ss, cnt_sj);
    scan3_kernel<<<3, 1024>>>(cnt_js, off_js, cnt_ss, off_ss, cnt_sj, off_sj);
    fill3_kernel<<<(E_ALL + 255) / 256, 256>>>(ei_js_s, ei_js_d, ei_ss_s, ei_ss_d, ei_sj_s, ei_sj_d,
                                               off_js, cur_js, csr_js,
                                               off_ss, cur_ss, csr_ss,
                                               off_sj, cur_sj, csr_sj);

    // ---- weight folding + q projection (input-only deps) ----
    q_kernel<<<1, 128>>>(query, Wq, bq, qout);
    fold_fv_kernel<<<24, 128>>>(gat_Ws, gat_Wd, gat_as, gat_ad, fvj, fvs);
    fold_cvec_kernel<<<4, 128>>>(gat_b, inter_W, inter_b, cvj, cvs);
    // MW[l][r] = Ws_h @ Winter_h; layer 0 needs rel 0,1,2; layer 1 needs rel 1 only
    {
        for (int r = 0; r < 3; r++) {
            int t = (r == 1) ? 0 : 1;
            for (int h = 0; h < 2; h++) {
                J.j[r * 2 + h] = GJob{
                    gat_Ws + (size_t)r * 32768 + h * 128, nullptr,
                    inter_W + (size_t)t * 32768 + (size_t)h * 16384, nullptr,
                    nullptr, nullptr, nullptr,
                    mw + (size_t)r * 32768 + h * 128, nullptr, 128, 256, 256 };
            }
        }
        gemm_kernel<<<dim3(2, 1, 6), 256>>>(J, 128, 128);
        for (int h = 0; h < 2; h++) {
            J.j[h] = GJob{
                gat_Ws + (size_t)(3 + 1) * 32768 + h * 128, nullptr,
                inter_W + (size_t)(2 + 0) * 32768 + (size_t)h * 16384, nullptr,
                nullptr, nullptr, nullptr,
                mw + (size_t)(3 + 1) * 32768 + h * 128, nullptr, 128, 256, 256 };
        }
        for (int z = 2; z < 6; z++) J.j[z] = none;
        gemm_kernel<<<dim3(2, 1, 2), 256>>>(J, 128, 128);
    }

    // ---- initial per-type linear + fused LN + relu ----
    J.j[0] = GJob{ x_job,   nullptr, W0_job,   b0_job,   g0_job,   be0_job,   nullptr,
                   xj, nullptr, NJ, SBERT, 128 };
    J.j[1] = GJob{ x_skill, nullptr, W0_skill, b0_skill, g0_skill, be0_skill, nullptr,
                   xs, nullptr, NS, SBERT, 128 };
    for (int z = 2; z < 6; z++) J.j[z] = none;
    gemm_kernel<<<dim3((NJ + 63) / 64, 1, 2), 256>>>(J, 128, SBERT);

    // ---- layer 1 (all 3 relations) ----
    J.j[0] = GJob{ xj, nullptr, mw + 0 * 32768, nullptr, nullptr, nullptr, nullptr,
                   hw0, nullptr, NJ, 128, 256 };
    J.j[1] = GJob{ xs, nullptr, mw + 1 * 32768, nullptr, nullptr, nullptr, nullptr,
                   hw1, nullptr, NS, 128, 256 };
    J.j[2] = GJob{ xs, nullptr, mw + 2 * 32768, nullptr, nullptr, nullptr, nullptr,
                   hw2, nullptr, NS, 128, 256 };
    for (int z = 3; z < 6; z++) J.j[z] = none;
    gemm_kernel<<<dim3((NJ + 63) / 64, 2, 3), 256>>>(J, 256, 128);

    alpha_fold_kernel<<<((NJ + NS) * 32 + 255) / 256, 256>>>(
        xj, xs, nullptr, fvj, fvs, alps0, alps1, alps2, alpd0, alpd1, alpd2, 0);

    gat_kernel<<<((2 * NS + NJ) * 32 + 255) / 256, 256>>>(
        off_js, cnt_js, csr_js, off_ss, cnt_ss, csr_ss, off_sj, cnt_sj, csr_sj,
        hw0, hw1, hw2, alps0, alps1, alps2, alpd0, alpd1, alpd2,
        cvj, cvs, fvj + 512, xj, xs, xs2, alpd1, 0);

    // ---- layer 2 (sj relation only) ----
    J.j[0] = GJob{ xs, xs2, mw + (size_t)(3 + 1) * 32768, nullptr, nullptr, nullptr, nullptr,
                   hw1, nullptr, NS, 128, 256 };
    for (int z = 1; z < 6; z++) J.j[z] = none;
    gemm_kernel<<<dim3((NS + 63) / 64, 2, 1), 256>>>(J, 256, 128);

    alpha_fold_kernel<<<(NS * 32 + 255) / 256, 256>>>(
        xj, xs, xs2, fvj + 512, fvs + 1024, alps0, alps1, alps2, alpd0, alpd1, alpd2, 1);

    gat_kernel<<<(NJ * 32 + 255) / 256, 256>>>(
        off_js, cnt_js, csr_js, off_ss, cnt_ss, csr_ss, off_sj, cnt_sj, csr_sj,
        hw0, hw1, hw2, alps0, alps1, alps2, alpd0, alpd1, alpd2,
        cvj + 128, cvs + 128, fvj + 512, xj, xs, xs2, alpd1, 1);

    // ---- final projection + fused scores ----
    J.j[0] = GJob{ xj, nullptr, Wjf, bjf, nullptr, nullptr, qout,
                   job_emb, scores, NJ, 128, 128 };
    for (int z = 1; z < 6; z++) J.j[z] = none;
    gemm_kernel<<<dim3((NJ + 63) / 64, 1, 1), 256>>>(J, 128, 128);
}

// round 15
// speedup vs baseline: 3.9219x; 1.0791x over previous
#include <cuda_runtime.h>
#include <cuda_bf16.h>
#include <math.h>

#define NJ 30000
#define NS 12000
#define E_JS 300000
#define E_SJ 300000
#define E_SS 150000
#define E_SS_T (E_SS + NS)
#define E_ALL (E_JS + E_SS_T + E_SJ)
#define SBERT 384
#define HID 128
#define HHID 256

// ---------------- scratch (device globals; no allocation allowed) ----------------
__device__ float g_xj[NJ * HID];
__device__ float g_xs[NS * HID];
__device__ float g_xs2[NS * HID];
__device__ __nv_bfloat16 g_hw0[NJ * HHID];
__device__ __nv_bfloat16 g_hw1[NS * HHID];
__device__ __nv_bfloat16 g_hw2[NS * HHID];
__device__ float g_mw[2 * 3 * 128 * 256];
__device__ float g_fvj[2 * 4 * 128];
__device__ float g_fvs[2 * 8 * 128];
__device__ float g_cvj[2 * 128];
__device__ float g_cvs[2 * 128];
__device__ float g_alps0[NJ * 2], g_alps1[NS * 2], g_alps2[NS * 2];
__device__ float g_alpd0[NS * 2], g_alpd1[NJ * 2], g_alpd2[NS * 2];
#define CNTCUR_N (4 * NS + 2 * NJ)
__device__ int g_cntcur[CNTCUR_N];
__device__ int g_off_js[NS], g_off_ss[NS], g_off_sj[NJ];
__device__ int g_csr_js[E_JS];
__device__ int g_csr_ss[E_SS_T];
__device__ int g_csr_sj[E_SJ];

// ---------------- helpers ----------------
__device__ __forceinline__ float warp_sum(float v) {
    #pragma unroll
    for (int o = 16; o; o >>= 1) v += __shfl_xor_sync(0xffffffffu, v, o);
    return v;
}
__device__ __forceinline__ unsigned long long pk2(float lo, float hi) {
    unsigned long long r;
    asm("mov.b64 %0, {%1, %2};" : "=l"(r) : "r"(__float_as_uint(lo)), "r"(__float_as_uint(hi)));
    return r;
}
__device__ __forceinline__ void upk2(unsigned long long v, float& lo, float& hi) {
    unsigned int a, b;
    asm("mov.b64 {%0, %1}, %2;" : "=r"(a), "=r"(b) : "l"(v));
    lo = __uint_as_float(a); hi = __uint_as_float(b);
}
__device__ __forceinline__ void fma2(unsigned long long& d, unsigned long long a, unsigned long long b) {
    asm("fma.rn.f32x2 %0, %1, %2, %0;" : "+l"(d) : "l"(a), "l"(b));
}
__device__ __forceinline__ float2 bf2f(unsigned int u) {
    __nv_bfloat162 b = *(__nv_bfloat162*)&u;
    return __bfloat1622float2(b);
}

// ---------------- batched GEMM (up to 6 jobs via blockIdx.z) ----------------
// Options per job: A2 (relu(A+A2) on load), bias, g/be (LN+relu epilogue, N==128),
// qv/sc (score written to sc, N==128), Cb (bf16 output instead of C).
struct GJob {
    const float* A; const float* A2; const float* B; const float* bias;
    const float* g; const float* be; const float* qv;
    float* C; __nv_bfloat16* Cb; float* sc; int M; int lda; int ldC;
};
struct GJobs { GJob j[6]; };

__global__ __launch_bounds__(256) void gemm_kernel(GJobs js, int N, int K)
{
    GJob jb = js.j[blockIdx.z];
    const int row0 = blockIdx.x * 64;
    if (jb.A == nullptr || row0 >= jb.M) return;
    const float* __restrict__ A = jb.A;
    const float* __restrict__ B = jb.B;
    const int M = jb.M;
    const int lda = jb.lda;

    __shared__ float As[16][68];
    __shared__ float Bs[16][128];

    const int t   = threadIdx.x;
    const int tc  = t & 31;
    const int tr  = t >> 5;
    const int col0 = blockIdx.y * 128;

    const int arow = t >> 2;
    const int akq  = (t & 3) * 4;
    const int bs0k = t >> 5;
    const int bs0c = (t & 31) * 4;
    const int bs1k = bs0k + 8;

    unsigned long long acc2[4][4];
    #pragma unroll
    for (int i = 0; i < 4; i++)
        #pragma unroll
        for (int j = 0; j < 4; j++) acc2[i][j] = 0ull;

    for (int k0 = 0; k0 < K; k0 += 16) {
        float4 av = make_float4(0.f, 0.f, 0.f, 0.f);
        if (row0 + arow < M) {
            av = *(const float4*)(A + (size_t)(row0 + arow) * lda + k0 + akq);
            if (jb.A2) {
                float4 a2 = *(const float4*)(jb.A2 + (size_t)(row0 + arow) * lda + k0 + akq);
                av.x = fmaxf(av.x + a2.x, 0.f); av.y = fmaxf(av.y + a2.y, 0.f);
                av.z = fmaxf(av.z + a2.z, 0.f); av.w = fmaxf(av.w + a2.w, 0.f);
            }
        }
        float4 bv0 = *(const float4*)(B + (size_t)(k0 + bs0k) * N + col0 + bs0c);
        float4 bv1 = *(const float4*)(B + (size_t)(k0 + bs1k) * N + col0 + bs0c);

        __syncthreads();
        As[akq + 0][arow] = av.x;
        As[akq + 1][arow] = av.y;
        As[akq + 2][arow] = av.z;
        As[akq + 3][arow] = av.w;
        *(float4*)&Bs[bs0k][bs0c] = bv0;
        *(float4*)&Bs[bs1k][bs0c] = bv1;
        __syncthreads();

        #pragma unroll
        for (int kk = 0; kk < 16; kk++) {
            float4 b = *(float4*)&Bs[kk][tc * 4];
            ulonglong2 apA = *(ulonglong2*)&As[kk][tr * 8];
            ulonglong2 apB = *(ulonglong2*)&As[kk][tr * 8 + 4];
            unsigned long long ap0 = apA.x, ap1 = apA.y, ap2 = apB.x, ap3 = apB.y;
            unsigned long long bd0 = pk2(b.x, b.x);
            unsigned long long bd1 = pk2(b.y, b.y);
            unsigned long long bd2 = pk2(b.z, b.z);
            unsigned long long bd3 = pk2(b.w, b.w);
            fma2(acc2[0][0], ap0, bd0); fma2(acc2[0][1], ap0, bd1);
            fma2(acc2[0][2], ap0, bd2); fma2(acc2[0][3], ap0, bd3);
            fma2(acc2[1][0], ap1, bd0); fma2(acc2[1][1], ap1, bd1);
            fma2(acc2[1][2], ap1, bd2); fma2(acc2[1][3], ap1, bd3);
            fma2(acc2[2][0], ap2, bd0); fma2(acc2[2][1], ap2, bd1);
            fma2(acc2[2][2], ap2, bd2); fma2(acc2[2][3], ap2, bd3);
            fma2(acc2[3][0], ap3, bd0); fma2(acc2[3][1], ap3, bd1);
            fma2(acc2[3][2], ap3, bd2); fma2(acc2[3][3], ap3, bd3);
        }
    }

    float acc[8][4];
    #pragma unroll
    for (int i = 0; i < 4; i++)
        #pragma unroll
        for (int j = 0; j < 4; j++)
            upk2(acc2[i][j], acc[2 * i][j], acc[2 * i + 1][j]);

    float4 bv = make_float4(0.f, 0.f, 0.f, 0.f);
    if (jb.bias) bv = *(const float4*)(jb.bias + col0 + tc * 4);

    if (jb.g) {
        // LN + relu epilogue: warp (fixed tr) holds the whole 128-wide row.
        float4 gv  = *(const float4*)(jb.g  + tc * 4);
        float4 bev = *(const float4*)(jb.be + tc * 4);
        #pragma unroll
        for (int i = 0; i < 8; i++) {
            float4 o;
            o.x = acc[i][0] + bv.x; o.y = acc[i][1] + bv.y;
            o.z = acc[i][2] + bv.z; o.w = acc[i][3] + bv.w;
            float s  = warp_sum(o.x + o.y + o.z + o.w);
            float sq = warp_sum(o.x * o.x + o.y * o.y + o.z * o.z + o.w * o.w);
            float mu  = s * (1.f / 128.f);
            float var = sq * (1.f / 128.f) - mu * mu;
            float r = rsqrtf(var + 1e-5f);
            o.x = fmaxf((o.x - mu) * r * gv.x + bev.x, 0.f);
            o.y = fmaxf((o.y - mu) * r * gv.y + bev.y, 0.f);
            o.z = fmaxf((o.z - mu) * r * gv.z + bev.z, 0.f);
            o.w = fmaxf((o.w - mu) * r * gv.w + bev.w, 0.f);
            int row = row0 + tr * 8 + i;
            if (row < M)
                *(float4*)(jb.C + (size_t)row * jb.ldC + col0 + tc * 4) = o;
        }
    } else if (jb.qv) {
        // bias + write + fused dot-with-q epilogue (N==128)
        float4 qv4 = *(const float4*)(jb.qv + tc * 4);
        #pragma unroll
        for (int i = 0; i < 8; i++) {
            int row = row0 + tr * 8 + i;
            float4 o;
            o.x = acc[i][0] + bv.x; o.y = acc[i][1] + bv.y;
            o.z = acc[i][2] + bv.z; o.w = acc[i][3] + bv.w;
            float dot = warp_sum(o.x * qv4.x + o.y * qv4.y + o.z * qv4.z + o.w * qv4.w);
            if (row < M) {
                *(float4*)(jb.C + (size_t)row * jb.ldC + tc * 4) = o;
                if (tc == 0) jb.sc[row] = dot;
            }
        }
    } else if (jb.Cb) {
        // bf16 output
        #pragma unroll
        for (int i = 0; i < 8; i++) {
            int row = row0 + tr * 8 + i;
            if (row < M) {
                float4 o;
                o.x = acc[i][0] + bv.x; o.y = acc[i][1] + bv.y;
                o.z = acc[i][2] + bv.z; o.w = acc[i][3] + bv.w;
                __nv_bfloat162 p0; p0.x = __float2bfloat16(o.x); p0.y = __float2bfloat16(o.y);
                __nv_bfloat162 p1; p1.x = __float2bfloat16(o.z); p1.y = __float2bfloat16(o.w);
                uint2 u = make_uint2(*(unsigned int*)&p0, *(unsigned int*)&p1);
                *(uint2*)(jb.Cb + (size_t)row * jb.ldC + col0 + tc * 4) = u;
            }
        }
    } else {
        #pragma unroll
        for (int i = 0; i < 8; i++) {
            int row = row0 + tr * 8 + i;
            if (row < M) {
                float4 o;
                o.x = acc[i][0] + bv.x; o.y = acc[i][1] + bv.y;
                o.z = acc[i][2] + bv.z; o.w = acc[i][3] + bv.w;
                *(float4*)(jb.C + (size_t)row * jb.ldC + col0 + tc * 4) = o;
            }
        }
    }
}

// ---------------- merged prep: fold_fv (blocks 0-23), fold_cvec (24-27), q (28) ----------------
__global__ void prep_kernel(const float* __restrict__ Ws, const float* __restrict__ Wd,
                            const float* __restrict__ as_, const float* __restrict__ ad_,
                            const float* __restrict__ gat_b,
                            const float* __restrict__ inter_W, const float* __restrict__ inter_b,
                            const float* __restrict__ query, const float* __restrict__ Wq,
                            const float* __restrict__ bq,
                            float* __restrict__ fvj, float* __restrict__ fvs,
                            float* __restrict__ cvj, float* __restrict__ cvs,
                            float* __restrict__ qout)
{
    int bid = blockIdx.x;
    int k = threadIdx.x;   // 128
    if (bid < 24) {
        int l = bid / 12, v = bid % 12;
        int rel, h, col, useWd, isJob;
        if (v < 2)       { rel = 0; h = v;      col = v;     useWd = 0; isJob = 1; }
        else if (v < 4)  { rel = 1; h = v - 2;  col = v;     useWd = 1; isJob = 1; }
        else if (v < 6)  { rel = 1; h = v - 4;  col = v - 4; useWd = 0; isJob = 0; }
        else if (v < 8)  { rel = 2; h = v - 6;  col = v - 4; useWd = 0; isJob = 0; }
        else if (v < 10) { rel = 0; h = v - 8;  col = v - 4; useWd = 1; isJob = 0; }
        else             { rel = 2; h = v - 10; col = v - 4; useWd = 1; isJob = 0; }
        const float* W = (useWd ? Wd : Ws) + (size_t)(l * 3 + rel) * 32768 + h * 128;
        const float* a = (useWd ? ad_ : as_) + (size_t)((l * 3 + rel) * 2 + h) * 128;
        float acc = 0.f;
        #pragma unroll 8
        for (int c = 0; c < 128; c++) acc += W[(size_t)k * 256 + c] * a[c];
        float* out = isJob ? (fvj + l * 512) : (fvs + l * 1024);
        out[col * 128 + k] = acc;
    } else if (bid < 28) {
        int b2 = bid - 24;
        int l = b2 >> 1, t = b2 & 1;
        const float* W = inter_W + (size_t)(l * 2 + t) * 256 * 128;
        float acc = inter_b[(l * 2 + t) * 128 + k];
        if (t == 0) {
            const float* b = gat_b + (size_t)(l * 3 + 1) * 256;
            for (int c = 0; c < 256; c++) acc += b[c] * W[(size_t)c * 128 + k];
            cvj[l * 128 + k] = acc;
        } else {
            const float* b0 = gat_b + (size_t)(l * 3 + 0) * 256;
            const float* b2p = gat_b + (size_t)(l * 3 + 2) * 256;
            for (int c = 0; c < 256; c++) acc += (b0[c] + b2p[c]) * W[(size_t)c * 128 + k];
            cvs[l * 128 + k] = acc;
        }
    } else {
        float acc = bq[k];
        for (int c = 0; c < SBERT; c++) acc += query[c] * Wq[(size_t)c * 128 + k];
        qout[k] = acc;
    }
}

// ---------------- fused alpha (src+dst) ----------------
__global__ void alpha_fold_kernel(const float* __restrict__ xj, const float* __restrict__ xs,
                                  const float* __restrict__ xs2,
                                  const float* __restrict__ fvj, const float* __restrict__ fvs,
                                  float* __restrict__ alps0, float* __restrict__ alps1,
                                  float* __restrict__ alps2,
                                  float* __restrict__ alpd0, float* __restrict__ alpd1,
                                  float* __restrict__ alpd2, int layer)
{
    int w    = (blockIdx.x * blockDim.x + threadIdx.x) >> 5;
    int lane = threadIdx.x & 31;
    if (layer == 0) {
        if (w < NJ) {
            const float* xp = xj + (size_t)w * 128;
            float xv[4];
            #pragma unroll
            for (int q = 0; q < 4; q++) xv[q] = xp[lane + 32 * q];
            float a[4];
            #pragma unroll
            for (int col = 0; col < 4; col++) {
                float acc = 0.f;
                #pragma unroll
                for (int q = 0; q < 4; q++) acc += xv[q] * fvj[col * 128 + lane + 32 * q];
                a[col] = warp_sum(acc);
            }
            if (lane == 0) {
                alps0[w * 2] = a[0]; alps0[w * 2 + 1] = a[1];
                alpd1[w * 2] = a[2]; alpd1[w * 2 + 1] = a[3];
            }
        } else if (w < NJ + NS) {
            int n = w - NJ;
            const float* xp = xs + (size_t)n * 128;
            float xv[4];
            #pragma unroll
            for (int q = 0; q < 4; q++) xv[q] = xp[lane + 32 * q];
            float a[8];
            #pragma unroll
            for (int col = 0; col < 8; col++) {
                float acc = 0.f;
                #pragma unroll
                for (int q = 0; q < 4; q++) acc += xv[q] * fvs[col * 128 + lane + 32 * q];
                a[col] = warp_sum(acc);
            }
            if (lane == 0) {
                alps1[n * 2] = a[0]; alps1[n * 2 + 1] = a[1];
                alps2[n * 2] = a[2]; alps2[n * 2 + 1] = a[3];
                alpd0[n * 2] = a[4]; alpd0[n * 2 + 1] = a[5];
                alpd2[n * 2] = a[6]; alpd2[n * 2 + 1] = a[7];
            }
        }
    } else {
        if (w < NS) {
            const float* xp  = xs  + (size_t)w * 128;
            const float* xp2 = xs2 + (size_t)w * 128;
            float xv[4];
            #pragma unroll
            for (int q = 0; q < 4; q++)
                xv[q] = fmaxf(xp[lane + 32 * q] + xp2[lane + 32 * q], 0.f);
            float a0 = 0.f, a1 = 0.f;
            #pragma unroll
            for (int q = 0; q < 4; q++) {
                a0 += xv[q] * fvs[0 * 128 + lane + 32 * q];
                a1 += xv[q] * fvs[1 * 128 + lane + 32 * q];
            }
            a0 = warp_sum(a0); a1 = warp_sum(a1);
            if (lane == 0) { alps1[w * 2] = a0; alps1[w * 2 + 1] = a1; }
        }
    }
}

// ---------------- CSR build ----------------
__global__ void csr_zero_kernel(int* __restrict__ cntcur)
{
    int i = blockIdx.x * blockDim.x + threadIdx.x;
    if (i < CNTCUR_N) cntcur[i] = 0;
}

__global__ void hist3_kernel(const int* __restrict__ js_d, const int* __restrict__ ss_d,
                             const int* __restrict__ sj_d,
                             int* __restrict__ cnt_js, int* __restrict__ cnt_ss,
                             int* __restrict__ cnt_sj)
{
    int e = blockIdx.x * blockDim.x + threadIdx.x;
    if (e >= E_ALL) return;
    if (e < E_JS)                  atomicAdd(&cnt_js[js_d[e]], 1);
    else if (e < E_JS + E_SS)      atomicAdd(&cnt_ss[ss_d[e - E_JS]], 1);
    else if (e < E_JS + E_SS + NS) atomicAdd(&cnt_ss[e - E_JS - E_SS], 1);
    else                           atomicAdd(&cnt_sj[sj_d[e - E_JS - E_SS_T]], 1);
}

__global__ void scan3_kernel(const int* __restrict__ cnt_js, int* __restrict__ off_js,
                             const int* __restrict__ cnt_ss, int* __restrict__ off_ss,
                             const int* __restrict__ cnt_sj, int* __restrict__ off_sj)
{
    const int* cnt; int* off; int n;
    if (blockIdx.x == 0)      { cnt = cnt_js; off = off_js; n = NS; }
    else if (blockIdx.x == 1) { cnt = cnt_ss; off = off_ss; n = NS; }
    else                      { cnt = cnt_sj; off = off_sj; n = NJ; }
    __shared__ int sh_carry;
    __shared__ int wsum[32];
    int lane = threadIdx.x & 31, wid = threadIdx.x >> 5;
    if (threadIdx.x == 0) sh_carry = 0;
    __syncthreads();
    for (int base = 0; base < n; base += 1024) {
        int i = base + threadIdx.x;
        int x = (i < n) ? cnt[i] : 0;
        int v = x;
        #pragma unroll
        for (int o = 1; o < 32; o <<= 1) {
            int tv = __shfl_up_sync(0xffffffffu, v, o);
            if (lane >= o) v += tv;
        }
        if (lane == 31) wsum[wid] = v;
        __syncthreads();
        if (wid == 0) {
            int s = wsum[lane];
            #pragma unroll
            for (int o = 1; o < 32; o <<= 1) {
                int tv = __shfl_up_sync(0xffffffffu, s, o);
                if (lane >= o) s += tv;
            }
            wsum[lane] = s;
        }
        __syncthreads();
        int pre = wid ? wsum[wid - 1] : 0;
        int incl = v + pre;
        int carry = sh_carry;
        if (i < n) off[i] = carry + incl - x;
        __syncthreads();
        if (threadIdx.x == 1023) sh_carry = carry + incl;
        __syncthreads();
    }
}

__global__ void fill3_kernel(const int* __restrict__ js_s, const int* __restrict__ js_d,
                             const int* __restrict__ ss_s, const int* __restrict__ ss_d,
                             const int* __restrict__ sj_s, const int* __restrict__ sj_d,
                             const int* __restrict__ off_js, int* __restrict__ cur_js,
                             int* __restrict__ csr_js,
                             const int* __restrict__ off_ss, int* __restrict__ cur_ss,
                             int* __restrict__ csr_ss,
                             const int* __restrict__ off_sj, int* __restrict__ cur_sj,
                             int* __restrict__ csr_sj)
{
    int e = blockIdx.x * blockDim.x + threadIdx.x;
    if (e >= E_ALL) return;
    int s, d;
    const int* off; int* cur; int* csr;
    if (e < E_JS) {
        s = js_s[e]; d = js_d[e]; off = off_js; cur = cur_js; csr = csr_js;
    } else if (e < E_JS + E_SS) {
        int i = e - E_JS; s = ss_s[i]; d = ss_d[i]; off = off_ss; cur = cur_ss; csr = csr_ss;
    } else if (e < E_JS + E_SS + NS) {
        s = d = e - E_JS - E_SS; off = off_ss; cur = cur_ss; csr = csr_ss;
    } else {
        int i = e - E_JS - E_SS_T; s = sj_s[i]; d = sj_d[i]; off = off_sj; cur = cur_sj; csr = csr_sj;
    }
    int pos = off[d] + atomicAdd(&cur[d], 1);
    csr[pos] = s;
}

// ---------------- softmax-aggregate one relation (bf16 features) ----------------
// Lane layout: lane<16 owns out cols 8*lane..8*lane+7 (head 0 side);
// lane>=16 owns the SAME cols' head-1 partials; heads combined via shfl_xor(16).
__device__ __forceinline__ void agg_one_bf(int o, int deg, const int* __restrict__ csrc,
                                           const __nv_bfloat16* __restrict__ hw,
                                           const float* __restrict__ alps,
                                           float ad0, float ad1, int lane, float* out)
{
    if (deg <= 0) return;
    float acc[8];
    #pragma unroll
    for (int i = 0; i < 8; i++) acc[i] = 0.f;
    float den0 = 0.f, den1 = 0.f;
    const float2* ap = (const float2*)alps;

    int s  = csrc[o];
    int s1 = (deg > 1) ? csrc[o + 1] : 0;
    float2 av = ap[s];
    uint4 v = ((const uint4*)(hw + (size_t)s * 256))[lane];

    for (int k = 0; k < deg; k++) {
        int s2 = (k + 2 < deg) ? csrc[o + k + 2] : 0;
        float2 avn = ap[s1];
        uint4 vn = ((const uint4*)(hw + (size_t)s1 * 256))[lane];

        float e0 = av.x + ad0; e0 = e0 > 0.f ? e0 : 0.2f * e0;
        float e1 = av.y + ad1; e1 = e1 > 0.f ? e1 : 0.2f * e1;
        float p0 = __expf(e0), p1 = __expf(e1);
        float pw = (lane < 16) ? p0 : p1;
        float2 f;
        f = bf2f(v.x); acc[0] = fmaf(pw, f.x, acc[0]); acc[1] = fmaf(pw, f.y, acc[1]);
        f = bf2f(v.y); acc[2] = fmaf(pw, f.x, acc[2]); acc[3] = fmaf(pw, f.y, acc[3]);
        f = bf2f(v.z); acc[4] = fmaf(pw, f.x, acc[4]); acc[5] = fmaf(pw, f.y, acc[5]);
        f = bf2f(v.w); acc[6] = fmaf(pw, f.x, acc[6]); acc[7] = fmaf(pw, f.y, acc[7]);
        den0 += p0; den1 += p1;

        s1 = s2; av = avn; v = vn;
    }
    float r = (lane < 16) ? 1.f / (den0 + 1e-16f) : 1.f / (den1 + 1e-16f);
    #pragma unroll
    for (int i = 0; i < 8; i++) {
        float tmp = acc[i] * r;
        out[i] += tmp + __shfl_xor_sync(0xffffffffu, tmp, 16);
    }
}

// ---------------- fused aggregation + folded inter linear ----------------
__global__ void gat_kernel(const int* __restrict__ off_js, const int* __restrict__ cnt_js,
                           const int* __restrict__ csr_js,
                           const int* __restrict__ off_ss, const int* __restrict__ cnt_ss,
                           const int* __restrict__ csr_ss,
                           const int* __restrict__ off_sj, const int* __restrict__ cnt_sj,
                           const int* __restrict__ csr_sj,
                           const __nv_bfloat16* __restrict__ hw0,
                           const __nv_bfloat16* __restrict__ hw1,
                           const __nv_bfloat16* __restrict__ hw2,
                           const float* __restrict__ alps0, const float* __restrict__ alps1,
                           const float* __restrict__ alps2,
                           const float* __restrict__ alpd0, const float* __restrict__ alpd1,
                           const float* __restrict__ alpd2,
                           const float* __restrict__ cvj, const float* __restrict__ cvs,
                           const float* __restrict__ fvj2,
                           float* __restrict__ xj, float* __restrict__ xs,
                           float* __restrict__ xs2,
                           float* __restrict__ alpd1_out, int layer)
{
    int w    = (blockIdx.x * blockDim.x + threadIdx.x) >> 5;
    int lane = threadIdx.x & 31;
    int lc   = (lane & 15) * 8;   // column base for this lane
    float out[8];
    if (layer == 0) {
        if (w < NS) {
            int d = w;
            #pragma unroll
            for (int i = 0; i < 8; i++) out[i] = cvs[lc + i];
            agg_one_bf(off_js[d], cnt_js[d], csr_js, hw0, alps0,
                       alpd0[d * 2], alpd0[d * 2 + 1], lane, out);
            if (lane < 16) {
                float4* op = (float4*)(xs + (size_t)d * 128 + lc);
                op[0] = make_float4(out[0], out[1], out[2], out[3]);
                op[1] = make_float4(out[4], out[5], out[6], out[7]);
            }
        } else if (w < 2 * NS) {
            int d = w - NS;
            #pragma unroll
            for (int i = 0; i < 8; i++) out[i] = 0.f;
            agg_one_bf(off_ss[d], cnt_ss[d], csr_ss, hw2, alps2,
                       alpd2[d * 2], alpd2[d * 2 + 1], lane, out);
            if (lane < 16) {
                float4* op = (float4*)(xs2 + (size_t)d * 128 + lc);
                op[0] = make_float4(out[0], out[1], out[2], out[3]);
                op[1] = make_float4(out[4], out[5], out[6], out[7]);
            }
        } else if (w < 2 * NS + NJ) {
            int d = w - 2 * NS;
            #pragma unroll
            for (int i = 0; i < 8; i++) out[i] = cvj[lc + i];
            agg_one_bf(off_sj[d], cnt_sj[d], csr_sj, hw1, alps1,
                       alpd1[d * 2], alpd1[d * 2 + 1], lane, out);
            #pragma unroll
            for (int i = 0; i < 8; i++) out[i] = fmaxf(out[i], 0.f);
            float a2p = 0.f, a3p = 0.f;
            if (lane < 16) {
                float4* op = (float4*)(xj + (size_t)d * 128 + lc);
                op[0] = make_float4(out[0], out[1], out[2], out[3]);
                op[1] = make_float4(out[4], out[5], out[6], out[7]);
                #pragma unroll
                for (int i = 0; i < 8; i++) {
                    a2p += out[i] * fvj2[2 * 128 + lc + i];
                    a3p += out[i] * fvj2[3 * 128 + lc + i];
                }
            }
            float a2 = warp_sum(a2p);
            float a3 = warp_sum(a3p);
            if (lane == 0) { alpd1_out[d * 2] = a2; alpd1_out[d * 2 + 1] = a3; }
        }
    } else {
        if (w < NJ) {
            int d = w;
            #pragma unroll
            for (int i = 0; i < 8; i++) out[i] = cvj[lc + i];
            agg_one_bf(off_sj[d], cnt_sj[d], csr_sj, hw1, alps1,
                       alpd1[d * 2], alpd1[d * 2 + 1], lane, out);
            if (lane < 16) {
                float4* op = (float4*)(xj + (size_t)d * 128 + lc);
                op[0] = make_float4(fmaxf(out[0], 0.f), fmaxf(out[1], 0.f),
                                    fmaxf(out[2], 0.f), fmaxf(out[3], 0.f));
                op[1] = make_float4(fmaxf(out[4], 0.f), fmaxf(out[5], 0.f),
                                    fmaxf(out[6], 0.f), fmaxf(out[7], 0.f));
            }
        }
    }
}

// ---------------- host ----------------
extern "C" void kernel_launch(void* const* d_in, const int* in_sizes, int n_in,
                              void* d_out, int out_size)
{
    const float* x_job    = (const float*)d_in[0];
    const float* x_skill  = (const float*)d_in[1];
    const int*   ei_js_s  = (const int*)d_in[2];
    const int*   ei_js_d  = (const int*)d_in[3];
    const int*   ei_sj_s  = (const int*)d_in[4];
    const int*   ei_sj_d  = (const int*)d_in[5];
    const int*   ei_ss_s  = (const int*)d_in[6];
    const int*   ei_ss_d  = (const int*)d_in[7];
    const float* query    = (const float*)d_in[8];
    const float* W0_job   = (const float*)d_in[9];
    const float* b0_job   = (const float*)d_in[10];
    const float* g0_job   = (const float*)d_in[11];
    const float* be0_job  = (const float*)d_in[12];
    const float* W0_skill = (const float*)d_in[13];
    const float* b0_skill = (const float*)d_in[14];
    const float* g0_skill = (const float*)d_in[15];
    const float* be0_skill= (const float*)d_in[16];
    const float* gat_Ws   = (const float*)d_in[17];
    const float* gat_Wd   = (const float*)d_in[18];
    const float* gat_as   = (const float*)d_in[19];
    const float* gat_ad   = (const float*)d_in[20];
    const float* gat_b    = (const float*)d_in[21];
    const float* inter_W  = (const float*)d_in[22];
    const float* inter_b  = (const float*)d_in[23];
    const float* Wjf      = (const float*)d_in[24];
    const float* bjf      = (const float*)d_in[25];
    const float* Wq       = (const float*)d_in[26];
    const float* bq       = (const float*)d_in[27];

    float* out     = (float*)d_out;
    float* scores  = out;
    float* job_emb = out + NJ;
    float* qout    = out + NJ + (size_t)NJ * 128;

    void* p;
    cudaGetSymbolAddress(&p, g_xj);    float* xj    = (float*)p;
    cudaGetSymbolAddress(&p, g_xs);    float* xs    = (float*)p;
    cudaGetSymbolAddress(&p, g_xs2);   float* xs2   = (float*)p;
    cudaGetSymbolAddress(&p, g_hw0);   __nv_bfloat16* hw0 = (__nv_bfloat16*)p;
    cudaGetSymbolAddress(&p, g_hw1);   __nv_bfloat16* hw1 = (__nv_bfloat16*)p;
    cudaGetSymbolAddress(&p, g_hw2);   __nv_bfloat16* hw2 = (__nv_bfloat16*)p;
    cudaGetSymbolAddress(&p, g_mw);    float* mw    = (float*)p;
    cudaGetSymbolAddress(&p, g_fvj);   float* fvj   = (float*)p;
    cudaGetSymbolAddress(&p, g_fvs);   float* fvs   = (float*)p;
    cudaGetSymbolAddress(&p, g_cvj);   float* cvj   = (float*)p;
    cudaGetSymbolAddress(&p, g_cvs);   float* cvs   = (float*)p;
    cudaGetSymbolAddress(&p, g_alps0); float* alps0 = (float*)p;
    cudaGetSymbolAddress(&p, g_alps1); float* alps1 = (float*)p;
    cudaGetSymbolAddress(&p, g_alps2); float* alps2 = (float*)p;
    cudaGetSymbolAddress(&p, g_alpd0); float* alpd0 = (float*)p;
    cudaGetSymbolAddress(&p, g_alpd1); float* alpd1 = (float*)p;
    cudaGetSymbolAddress(&p, g_alpd2); float* alpd2 = (float*)p;
    cudaGetSymbolAddress(&p, g_cntcur); int* cntcur = (int*)p;
    int* cnt_js = cntcur;
    int* cur_js = cntcur + NS;
    int* cnt_ss = cntcur + 2 * NS;
    int* cur_ss = cntcur + 3 * NS;
    int* cnt_sj = cntcur + 4 * NS;
    int* cur_sj = cntcur + 4 * NS + NJ;
    cudaGetSymbolAddress(&p, g_off_js); int* off_js = (int*)p;
    cudaGetSymbolAddress(&p, g_off_ss); int* off_ss = (int*)p;
    cudaGetSymbolAddress(&p, g_off_sj); int* off_sj = (int*)p;
    cudaGetSymbolAddress(&p, g_csr_js); int* csr_js = (int*)p;
    cudaGetSymbolAddress(&p, g_csr_ss); int* csr_ss = (int*)p;
    cudaGetSymbolAddress(&p, g_csr_sj); int* csr_sj = (int*)p;

    GJobs J;

    // ---- CSR build ----
    csr_zero_kernel<<<(CNTCUR_N + 255) / 256, 256>>>(cntcur);
    hist3_kernel<<<(E_ALL + 255) / 256, 256>>>(ei_js_d, ei_ss_d, ei_sj_d, cnt_js, cnt_ss, cnt_sj);
    scan3_kernel<<<3, 1024>>>(cnt_js, off_js, cnt_ss, off_ss, cnt_sj, off_sj);
    fill3_kernel<<<(E_ALL + 255) / 256, 256>>>(ei_js_s, ei_js_d, ei_ss_s, ei_ss_d, ei_sj_s, ei_sj_d,
                                               off_js, cur_js, csr_js,
                                               off_ss, cur_ss, csr_ss,
                                               off_sj, cur_sj, csr_sj);

    // ---- merged prep (fv, cvec, q) ----
    prep_kernel<<<29, 128>>>(gat_Ws, gat_Wd, gat_as, gat_ad, gat_b, inter_W, inter_b,
                             query, Wq, bq, fvj, fvs, cvj, cvs, qout);

    // MW[l][r] = Ws_h @ Winter_h; layer 0 rel 0,1,2 (6 jobs), then layer 1 rel 1 (2 jobs)
    {
        for (int z = 0; z < 6; z++) J.j[z] = GJob{};
        for (int r = 0; r < 3; r++) {
            int t = (r == 1) ? 0 : 1;
            for (int h = 0; h < 2; h++) {
                GJob& jj = J.j[r * 2 + h];
                jj.A = gat_Ws + (size_t)r * 32768 + h * 128;
                jj.B = inter_W + (size_t)t * 32768 + (size_t)h * 16384;
                jj.C = mw + (size_t)r * 32768 + h * 128;
                jj.M = 128; jj.lda = 256; jj.ldC = 256;
            }
        }
        gemm_kernel<<<dim3(2, 1, 6), 256>>>(J, 128, 128);

        for (int z = 0; z < 6; z++) J.j[z] = GJob{};
        for (int h = 0; h < 2; h++) {
            GJob& jj = J.j[h];
            jj.A = gat_Ws + (size_t)(3 + 1) * 32768 + h * 128;
            jj.B = inter_W + (size_t)(2 + 0) * 32768 + (size_t)h * 16384;
            jj.C = mw + (size_t)(3 + 1) * 32768 + h * 128;
            jj.M = 128; jj.lda = 256; jj.ldC = 256;
        }
        gemm_kernel<<<dim3(2, 1, 2), 256>>>(J, 128, 128);
    }

    // ---- initial per-type linear + fused LN + relu ----
    for (int z = 0; z < 6; z++) J.j[z] = GJob{};
    J.j[0].A = x_job;   J.j[0].B = W0_job;   J.j[0].bias = b0_job;
    J.j[0].g = g0_job;  J.j[0].be = be0_job; J.j[0].C = xj;
    J.j[0].M = NJ; J.j[0].lda = SBERT; J.j[0].ldC = 128;
    J.j[1].A = x_skill; J.j[1].B = W0_skill; J.j[1].bias = b0_skill;
    J.j[1].g = g0_skill;J.j[1].be = be0_skill;J.j[1].C = xs;
    J.j[1].M = NS; J.j[1].lda = SBERT; J.j[1].ldC = 128;
    gemm_kernel<<<dim3((NJ + 63) / 64, 1, 2), 256>>>(J, 128, SBERT);

    // ---- layer 1 hw GEMMs (bf16 out, all 3 relations) ----
    for (int z = 0; z < 6; z++) J.j[z] = GJob{};
    J.j[0].A = xj; J.j[0].B = mw + 0 * 32768; J.j[0].Cb = hw0;
    J.j[0].M = NJ; J.j[0].lda = 128; J.j[0].ldC = 256;
    J.j[1].A = xs; J.j[1].B = mw + 1 * 32768; J.j[1].Cb = hw1;
    J.j[1].M = NS; J.j[1].lda = 128; J.j[1].ldC = 256;
    J.j[2].A = xs; J.j[2].B = mw + 2 * 32768; J.j[2].Cb = hw2;
    J.j[2].M = NS; J.j[2].lda = 128; J.j[2].ldC = 256;
    gemm_kernel<<<dim3((NJ + 63) / 64, 2, 3), 256>>>(J, 256, 128);

    alpha_fold_kernel<<<((NJ + NS) * 32 + 255) / 256, 256>>>(
        xj, xs, nullptr, fvj, fvs, alps0, alps1, alps2, alpd0, alpd1, alpd2, 0);

    gat_kernel<<<((2 * NS + NJ) * 32 + 255) / 256, 256>>>(
        off_js, cnt_js, csr_js, off_ss, cnt_ss, csr_ss, off_sj, cnt_sj, csr_sj,
        hw0, hw1, hw2, alps0, alps1, alps2, alpd0, alpd1, alpd2,
        cvj, cvs, fvj + 512, xj, xs, xs2, alpd1, 0);

    // ---- layer 2 (sj relation only) ----
    for (int z = 0; z < 6; z++) J.j[z] = GJob{};
    J.j[0].A = xs; J.j[0].A2 = xs2; J.j[0].B = mw + (size_t)(3 + 1) * 32768; J.j[0].Cb = hw1;
    J.j[0].M = NS; J.j[0].lda = 128; J.j[0].ldC = 256;
    gemm_kernel<<<dim3((NS + 63) / 64, 2, 1), 256>>>(J, 256, 128);

    alpha_fold_kernel<<<(NS * 32 + 255) / 256, 256>>>(
        xj, xs, xs2, fvj + 512, fvs + 1024, alps0, alps1, alps2, alpd0, alpd1, alpd2, 1);

    gat_kernel<<<(NJ * 32 + 255) / 256, 256>>>(
        off_js, cnt_js, csr_js, off_ss, cnt_ss, csr_ss, off_sj, cnt_sj, csr_sj,
        hw0, hw1, hw2, alps0, alps1, alps2, alpd0, alpd1, alpd2,
        cvj + 128, cvs + 128, fvj + 512, xj, xs, xs2, alpd1, 1);

    // ---- final projection + fused scores ----
    for (int z = 0; z < 6; z++) J.j[z] = GJob{};
    J.j[0].A = xj; J.j[0].B = Wjf; J.j[0].bias = bjf; J.j[0].qv = qout;
    J.j[0].C = job_emb; J.j[0].sc = scores;
    J.j[0].M = NJ; J.j[0].lda = 128; J.j[0].ldC = 128;
    gemm_kernel<<<dim3((NJ + 63) / 64, 1, 1), 256>>>(J, 128, 128);
}

// round 16
// speedup vs baseline: 3.9763x; 1.0139x over previous
#include <cuda_runtime.h>
#include <cuda_bf16.h>
#include <math.h>

#define NJ 30000
#define NS 12000
#define E_JS 300000
#define E_SJ 300000
#define E_SS 150000
#define E_SS_T (E_SS + NS)
#define E_ALL (E_JS + E_SS_T + E_SJ)
#define SBERT 384
#define HID 128
#define HHID 256

// ---------------- scratch (device globals; no allocation allowed) ----------------
__device__ float g_xj[NJ * HID];
__device__ float g_xs[NS * HID];
__device__ float g_xs2[NS * HID];
__device__ __nv_bfloat16 g_hw0[NJ * HHID];
__device__ __nv_bfloat16 g_hw1[NS * HHID];
__device__ __nv_bfloat16 g_hw2[NS * HHID];
__device__ float g_hw1f[NS * HHID];          // layer-2 sj features in fp32 (precision)
__device__ float g_mw[2 * 3 * 128 * 256];
__device__ float g_fvj[2 * 4 * 128];
__device__ float g_fvs[2 * 8 * 128];
__device__ float g_cvj[2 * 128];
__device__ float g_cvs[2 * 128];
// contiguous per-node alpha arrays:
// alpj[n*4 + {0,1}] = alps0 h0/h1 ; alpj[n*4 + {2,3}] = alpd1 h0/h1
// alp_s[n*8 + {0,1}] = alps1 ; {2,3} = alps2 ; {4,5} = alpd0 ; {6,7} = alpd2
__device__ float g_alpj[NJ * 4];
__device__ float g_alp_s[NS * 8];
#define CNTCUR_N (4 * NS + 2 * NJ)
__device__ int g_cntcur[CNTCUR_N];
__device__ int g_off_js[NS], g_off_ss[NS], g_off_sj[NJ];
__device__ int g_csr_js[E_JS];
__device__ int g_csr_ss[E_SS_T];
__device__ int g_csr_sj[E_SJ];

// ---------------- helpers ----------------
__device__ __forceinline__ float warp_sum(float v) {
    #pragma unroll
    for (int o = 16; o; o >>= 1) v += __shfl_xor_sync(0xffffffffu, v, o);
    return v;
}
__device__ __forceinline__ unsigned long long pk2(float lo, float hi) {
    unsigned long long r;
    asm("mov.b64 %0, {%1, %2};" : "=l"(r) : "r"(__float_as_uint(lo)), "r"(__float_as_uint(hi)));
    return r;
}
__device__ __forceinline__ void upk2(unsigned long long v, float& lo, float& hi) {
    unsigned int a, b;
    asm("mov.b64 {%0, %1}, %2;" : "=r"(a), "=r"(b) : "l"(v));
    lo = __uint_as_float(a); hi = __uint_as_float(b);
}
__device__ __forceinline__ void fma2(unsigned long long& d, unsigned long long a, unsigned long long b) {
    asm("fma.rn.f32x2 %0, %1, %2, %0;" : "+l"(d) : "l"(a), "l"(b));
}
__device__ __forceinline__ float2 bf2f(unsigned int u) {
    __nv_bfloat162 b = *(__nv_bfloat162*)&u;
    return __bfloat1622float2(b);
}

// ---------------- batched GEMM (up to 8 jobs via blockIdx.z) ----------------
// Options: A2 (relu(A+A2) on load), bias, g/be (LN+relu, N==128), qv/sc (fused score, N==128),
// Cb (bf16 out), fv/alp/n_alpha/alp_ld (fused alpha dots, K==128, computed on blockIdx.y==0).
struct GJob {
    const float* A; const float* A2; const float* B; const float* bias;
    const float* g; const float* be; const float* qv; const float* fv;
    float* C; __nv_bfloat16* Cb; float* sc; float* alp;
    int M; int lda; int ldC; int n_alpha; int alp_ld;
};
struct GJobs { GJob j[8]; };

__global__ __launch_bounds__(256) void gemm_kernel(GJobs js, int N, int K)
{
    GJob jb = js.j[blockIdx.z];
    const int row0 = blockIdx.x * 64;
    if (jb.A == nullptr || row0 >= jb.M) return;
    const float* __restrict__ A = jb.A;
    const float* __restrict__ B = jb.B;
    const int M = jb.M;
    const int lda = jb.lda;

    __shared__ float As[16][68];
    __shared__ float Bs[16][128];
    __shared__ float fv_sh[8 * 128];

    const int t   = threadIdx.x;
    const int tc  = t & 31;
    const int tr  = t >> 5;
    const int col0 = blockIdx.y * 128;

    const int arow = t >> 2;
    const int akq  = (t & 3) * 4;
    const int bs0k = t >> 5;
    const int bs0c = (t & 31) * 4;
    const int bs1k = bs0k + 8;

    const bool do_alpha = (jb.fv != nullptr) && (blockIdx.y == 0);
    if (do_alpha) {
        for (int i = t; i < jb.n_alpha * 128; i += 256) fv_sh[i] = jb.fv[i];
    }
    float alp_acc[8];
    #pragma unroll
    for (int i = 0; i < 8; i++) alp_acc[i] = 0.f;

    unsigned long long acc2[4][4];
    #pragma unroll
    for (int i = 0; i < 4; i++)
        #pragma unroll
        for (int j = 0; j < 4; j++) acc2[i][j] = 0ull;

    for (int k0 = 0; k0 < K; k0 += 16) {
        float4 av = make_float4(0.f, 0.f, 0.f, 0.f);
        if (row0 + arow < M) {
            av = *(const float4*)(A + (size_t)(row0 + arow) * lda + k0 + akq);
            if (jb.A2) {
                float4 a2 = *(const float4*)(jb.A2 + (size_t)(row0 + arow) * lda + k0 + akq);
                av.x = fmaxf(av.x + a2.x, 0.f); av.y = fmaxf(av.y + a2.y, 0.f);
                av.z = fmaxf(av.z + a2.z, 0.f); av.w = fmaxf(av.w + a2.w, 0.f);
            }
        }
        float4 bv0 = *(const float4*)(B + (size_t)(k0 + bs0k) * N + col0 + bs0c);
        float4 bv1 = *(const float4*)(B + (size_t)(k0 + bs1k) * N + col0 + bs0c);

        __syncthreads();
        As[akq + 0][arow] = av.x;
        As[akq + 1][arow] = av.y;
        As[akq + 2][arow] = av.z;
        As[akq + 3][arow] = av.w;
        *(float4*)&Bs[bs0k][bs0c] = bv0;
        *(float4*)&Bs[bs1k][bs0c] = bv1;
        __syncthreads();

        if (do_alpha) {
            #pragma unroll
            for (int c = 0; c < 8; c++) {
                if (c < jb.n_alpha) {
                    float4 fq = *(float4*)&fv_sh[c * 128 + k0 + akq];
                    alp_acc[c] += av.x * fq.x + av.y * fq.y + av.z * fq.z + av.w * fq.w;
                }
            }
        }

        #pragma unroll
        for (int kk = 0; kk < 16; kk++) {
            float4 b = *(float4*)&Bs[kk][tc * 4];
            ulonglong2 apA = *(ulonglong2*)&As[kk][tr * 8];
            ulonglong2 apB = *(ulonglong2*)&As[kk][tr * 8 + 4];
            unsigned long long ap0 = apA.x, ap1 = apA.y, ap2 = apB.x, ap3 = apB.y;
            unsigned long long bd0 = pk2(b.x, b.x);
            unsigned long long bd1 = pk2(b.y, b.y);
            unsigned long long bd2 = pk2(b.z, b.z);
            unsigned long long bd3 = pk2(b.w, b.w);
            fma2(acc2[0][0], ap0, bd0); fma2(acc2[0][1], ap0, bd1);
            fma2(acc2[0][2], ap0, bd2); fma2(acc2[0][3], ap0, bd3);
            fma2(acc2[1][0], ap1, bd0); fma2(acc2[1][1], ap1, bd1);
            fma2(acc2[1][2], ap1, bd2); fma2(acc2[1][3], ap1, bd3);
            fma2(acc2[2][0], ap2, bd0); fma2(acc2[2][1], ap2, bd1);
            fma2(acc2[2][2], ap2, bd2); fma2(acc2[2][3], ap2, bd3);
            fma2(acc2[3][0], ap3, bd0); fma2(acc2[3][1], ap3, bd1);
            fma2(acc2[3][2], ap3, bd2); fma2(acc2[3][3], ap3, bd3);
        }
    }

    // fused alpha epilogue: rows are owned by 4 consecutive threads (t>>2)
    if (do_alpha) {
        #pragma unroll
        for (int c = 0; c < 8; c++) {
            float v = alp_acc[c];
            v += __shfl_xor_sync(0xffffffffu, v, 1);
            v += __shfl_xor_sync(0xffffffffu, v, 2);
            alp_acc[c] = v;
        }
        if ((t & 3) == 0 && row0 + arow < M) {
            for (int c = 0; c < jb.n_alpha; c++)
                jb.alp[(size_t)(row0 + arow) * jb.alp_ld + c] = alp_acc[c];
        }
    }

    float acc[8][4];
    #pragma unroll
    for (int i = 0; i < 4; i++)
        #pragma unroll
        for (int j = 0; j < 4; j++)
            upk2(acc2[i][j], acc[2 * i][j], acc[2 * i + 1][j]);

    float4 bv = make_float4(0.f, 0.f, 0.f, 0.f);
    if (jb.bias) bv = *(const float4*)(jb.bias + col0 + tc * 4);

    if (jb.g) {
        float4 gv  = *(const float4*)(jb.g  + tc * 4);
        float4 bev = *(const float4*)(jb.be + tc * 4);
        #pragma unroll
        for (int i = 0; i < 8; i++) {
            float4 o;
            o.x = acc[i][0] + bv.x; o.y = acc[i][1] + bv.y;
            o.z = acc[i][2] + bv.z; o.w = acc[i][3] + bv.w;
            float s  = warp_sum(o.x + o.y + o.z + o.w);
            float sq = warp_sum(o.x * o.x + o.y * o.y + o.z * o.z + o.w * o.w);
            float mu  = s * (1.f / 128.f);
            float var = sq * (1.f / 128.f) - mu * mu;
            float r = rsqrtf(var + 1e-5f);
            o.x = fmaxf((o.x - mu) * r * gv.x + bev.x, 0.f);
            o.y = fmaxf((o.y - mu) * r * gv.y + bev.y, 0.f);
            o.z = fmaxf((o.z - mu) * r * gv.z + bev.z, 0.f);
            o.w = fmaxf((o.w - mu) * r * gv.w + bev.w, 0.f);
            int row = row0 + tr * 8 + i;
            if (row < M)
                *(float4*)(jb.C + (size_t)row * jb.ldC + col0 + tc * 4) = o;
        }
    } else if (jb.qv) {
        float4 qv4 = *(const float4*)(jb.qv + tc * 4);
        #pragma unroll
        for (int i = 0; i < 8; i++) {
            int row = row0 + tr * 8 + i;
            float4 o;
            o.x = acc[i][0] + bv.x; o.y = acc[i][1] + bv.y;
            o.z = acc[i][2] + bv.z; o.w = acc[i][3] + bv.w;
            float dot = warp_sum(o.x * qv4.x + o.y * qv4.y + o.z * qv4.z + o.w * qv4.w);
            if (row < M) {
                *(float4*)(jb.C + (size_t)row * jb.ldC + tc * 4) = o;
                if (tc == 0) jb.sc[row] = dot;
            }
        }
    } else if (jb.Cb) {
        #pragma unroll
        for (int i = 0; i < 8; i++) {
            int row = row0 + tr * 8 + i;
            if (row < M) {
                float4 o;
                o.x = acc[i][0] + bv.x; o.y = acc[i][1] + bv.y;
                o.z = acc[i][2] + bv.z; o.w = acc[i][3] + bv.w;
                __nv_bfloat162 p0; p0.x = __float2bfloat16(o.x); p0.y = __float2bfloat16(o.y);
                __nv_bfloat162 p1; p1.x = __float2bfloat16(o.z); p1.y = __float2bfloat16(o.w);
                uint2 u = make_uint2(*(unsigned int*)&p0, *(unsigned int*)&p1);
                *(uint2*)(jb.Cb + (size_t)row * jb.ldC + col0 + tc * 4) = u;
            }
        }
    } else {
        #pragma unroll
        for (int i = 0; i < 8; i++) {
            int row = row0 + tr * 8 + i;
            if (row < M) {
                float4 o;
                o.x = acc[i][0] + bv.x; o.y = acc[i][1] + bv.y;
                o.z = acc[i][2] + bv.z; o.w = acc[i][3] + bv.w;
                *(float4*)(jb.C + (size_t)row * jb.ldC + col0 + tc * 4) = o;
            }
        }
    }
}

// ---------------- merged prep: fold_fv (blocks 0-23), fold_cvec (24-27), q (28) ----------------
__global__ void prep_kernel(const float* __restrict__ Ws, const float* __restrict__ Wd,
                            const float* __restrict__ as_, const float* __restrict__ ad_,
                            const float* __restrict__ gat_b,
                            const float* __restrict__ inter_W, const float* __restrict__ inter_b,
                            const float* __restrict__ query, const float* __restrict__ Wq,
                            const float* __restrict__ bq,
                            float* __restrict__ fvj, float* __restrict__ fvs,
                            float* __restrict__ cvj, float* __restrict__ cvs,
                            float* __restrict__ qout)
{
    int bid = blockIdx.x;
    int k = threadIdx.x;
    if (bid < 24) {
        int l = bid / 12, v = bid % 12;
        int rel, h, col, useWd, isJob;
        if (v < 2)       { rel = 0; h = v;      col = v;     useWd = 0; isJob = 1; }
        else if (v < 4)  { rel = 1; h = v - 2;  col = v;     useWd = 1; isJob = 1; }
        else if (v < 6)  { rel = 1; h = v - 4;  col = v - 4; useWd = 0; isJob = 0; }
        else if (v < 8)  { rel = 2; h = v - 6;  col = v - 4; useWd = 0; isJob = 0; }
        else if (v < 10) { rel = 0; h = v - 8;  col = v - 4; useWd = 1; isJob = 0; }
        else             { rel = 2; h = v - 10; col = v - 4; useWd = 1; isJob = 0; }
        const float* W = (useWd ? Wd : Ws) + (size_t)(l * 3 + rel) * 32768 + h * 128;
        const float* a = (useWd ? ad_ : as_) + (size_t)((l * 3 + rel) * 2 + h) * 128;
        float acc = 0.f;
        #pragma unroll 8
        for (int c = 0; c < 128; c++) acc += W[(size_t)k * 256 + c] * a[c];
        float* out = isJob ? (fvj + l * 512) : (fvs + l * 1024);
        out[col * 128 + k] = acc;
    } else if (bid < 28) {
        int b2 = bid - 24;
        int l = b2 >> 1, t = b2 & 1;
        const float* W = inter_W + (size_t)(l * 2 + t) * 256 * 128;
        float acc = inter_b[(l * 2 + t) * 128 + k];
        if (t == 0) {
            const float* b = gat_b + (size_t)(l * 3 + 1) * 256;
            for (int c = 0; c < 256; c++) acc += b[c] * W[(size_t)c * 128 + k];
            cvj[l * 128 + k] = acc;
        } else {
            const float* b0 = gat_b + (size_t)(l * 3 + 0) * 256;
            const float* b2p = gat_b + (size_t)(l * 3 + 2) * 256;
            for (int c = 0; c < 256; c++) acc += (b0[c] + b2p[c]) * W[(size_t)c * 128 + k];
            cvs[l * 128 + k] = acc;
        }
    } else {
        float acc = bq[k];
        for (int c = 0; c < SBERT; c++) acc += query[c] * Wq[(size_t)c * 128 + k];
        qout[k] = acc;
    }
}

// ---------------- CSR build ----------------
__global__ void csr_zero_kernel(int* __restrict__ cntcur)
{
    int i = blockIdx.x * blockDim.x + threadIdx.x;
    if (i < CNTCUR_N) cntcur[i] = 0;
}

__global__ void hist3_kernel(const int* __restrict__ js_d, const int* __restrict__ ss_d,
                             const int* __restrict__ sj_d,
                             int* __restrict__ cnt_js, int* __restrict__ cnt_ss,
                             int* __restrict__ cnt_sj)
{
    int e = blockIdx.x * blockDim.x + threadIdx.x;
    if (e >= E_ALL) return;
    if (e < E_JS)                  atomicAdd(&cnt_js[js_d[e]], 1);
    else if (e < E_JS + E_SS)      atomicAdd(&cnt_ss[ss_d[e - E_JS]], 1);
    else if (e < E_JS + E_SS + NS) atomicAdd(&cnt_ss[e - E_JS - E_SS], 1);
    else                           atomicAdd(&cnt_sj[sj_d[e - E_JS - E_SS_T]], 1);
}

__global__ void scan3_kernel(const int* __restrict__ cnt_js, int* __restrict__ off_js,
                             const int* __restrict__ cnt_ss, int* __restrict__ off_ss,
                             const int* __restrict__ cnt_sj, int* __restrict__ off_sj)
{
    const int* cnt; int* off; int n;
    if (blockIdx.x == 0)      { cnt = cnt_js; off = off_js; n = NS; }
    else if (blockIdx.x == 1) { cnt = cnt_ss; off = off_ss; n = NS; }
    else                      { cnt = cnt_sj; off = off_sj; n = NJ; }
    __shared__ int sh_carry;
    __shared__ int wsum[32];
    int lane = threadIdx.x & 31, wid = threadIdx.x >> 5;
    if (threadIdx.x == 0) sh_carry = 0;
    __syncthreads();
    for (int base = 0; base < n; base += 1024) {
        int i = base + threadIdx.x;
        int x = (i < n) ? cnt[i] : 0;
        int v = x;
        #pragma unroll
        for (int o = 1; o < 32; o <<= 1) {
            int tv = __shfl_up_sync(0xffffffffu, v, o);
            if (lane >= o) v += tv;
        }
        if (lane == 31) wsum[wid] = v;
        __syncthreads();
        if (wid == 0) {
            int s = wsum[lane];
            #pragma unroll
            for (int o = 1; o < 32; o <<= 1) {
                int tv = __shfl_up_sync(0xffffffffu, s, o);
                if (lane >= o) s += tv;
            }
            wsum[lane] = s;
        }
        __syncthreads();
        int pre = wid ? wsum[wid - 1] : 0;
        int incl = v + pre;
        int carry = sh_carry;
        if (i < n) off[i] = carry + incl - x;
        __syncthreads();
        if (threadIdx.x == 1023) sh_carry = carry + incl;
        __syncthreads();
    }
}

__global__ void fill3_kernel(const int* __restrict__ js_s, const int* __restrict__ js_d,
                             const int* __restrict__ ss_s, const int* __restrict__ ss_d,
                             const int* __restrict__ sj_s, const int* __restrict__ sj_d,
                             const int* __restrict__ off_js, int* __restrict__ cur_js,
                             int* __restrict__ csr_js,
                             const int* __restrict__ off_ss, int* __restrict__ cur_ss,
                             int* __restrict__ csr_ss,
                             const int* __restrict__ off_sj, int* __restrict__ cur_sj,
                             int* __restrict__ csr_sj)
{
    int e = blockIdx.x * blockDim.x + threadIdx.x;
    if (e >= E_ALL) return;
    int s, d;
    const int* off; int* cur; int* csr;
    if (e < E_JS) {
        s = js_s[e]; d = js_d[e]; off = off_js; cur = cur_js; csr = csr_js;
    } else if (e < E_JS + E_SS) {
        int i = e - E_JS; s = ss_s[i]; d = ss_d[i]; off = off_ss; cur = cur_ss; csr = csr_ss;
    } else if (e < E_JS + E_SS + NS) {
        s = d = e - E_JS - E_SS; off = off_ss; cur = cur_ss; csr = csr_ss;
    } else {
        int i = e - E_JS - E_SS_T; s = sj_s[i]; d = sj_d[i]; off = off_sj; cur = cur_sj; csr = csr_sj;
    }
    int pos = off[d] + atomicAdd(&cur[d], 1);
    csr[pos] = s;
}

// ---------------- softmax-aggregate: bf16 features ----------------
// lane<16 -> head0 cols lc..lc+7 ; lane>=16 -> head1 same cols ; combine via shfl_xor(16).
// alps: base pointer to the 2 head columns; ldh = row stride in float2 units.
__device__ __forceinline__ void agg_one_bf(int o, int deg, const int* __restrict__ csrc,
                                           const __nv_bfloat16* __restrict__ hw,
                                           const float* __restrict__ alps, int ldh,
                                           float ad0, float ad1, int lane, float* out)
{
    if (deg <= 0) return;
    float acc[8];
    #pragma unroll
    for (int i = 0; i < 8; i++) acc[i] = 0.f;
    float den0 = 0.f, den1 = 0.f;
    const float2* ap = (const float2*)alps;

    int s  = csrc[o];
    int s1 = (deg > 1) ? csrc[o + 1] : 0;
    float2 av = ap[s * ldh];
    uint4 v = ((const uint4*)(hw + (size_t)s * 256))[lane];

    for (int k = 0; k < deg; k++) {
        int s2 = (k + 2 < deg) ? csrc[o + k + 2] : 0;
        float2 avn = ap[s1 * ldh];
        uint4 vn = ((const uint4*)(hw + (size_t)s1 * 256))[lane];

        float e0 = av.x + ad0; e0 = e0 > 0.f ? e0 : 0.2f * e0;
        float e1 = av.y + ad1; e1 = e1 > 0.f ? e1 : 0.2f * e1;
        float p0 = __expf(e0), p1 = __expf(e1);
        float pw = (lane < 16) ? p0 : p1;
        float2 f;
        f = bf2f(v.x); acc[0] = fmaf(pw, f.x, acc[0]); acc[1] = fmaf(pw, f.y, acc[1]);
        f = bf2f(v.y); acc[2] = fmaf(pw, f.x, acc[2]); acc[3] = fmaf(pw, f.y, acc[3]);
        f = bf2f(v.z); acc[4] = fmaf(pw, f.x, acc[4]); acc[5] = fmaf(pw, f.y, acc[5]);
        f = bf2f(v.w); acc[6] = fmaf(pw, f.x, acc[6]); acc[7] = fmaf(pw, f.y, acc[7]);
        den0 += p0; den1 += p1;

        s1 = s2; av = avn; v = vn;
    }
    float r = (lane < 16) ? 1.f / (den0 + 1e-16f) : 1.f / (den1 + 1e-16f);
    #pragma unroll
    for (int i = 0; i < 8; i++) {
        float tmp = acc[i] * r;
        out[i] += tmp + __shfl_xor_sync(0xffffffffu, tmp, 16);
    }
}

// ---------------- softmax-aggregate: fp32 features (layer 2) ----------------
__device__ __forceinline__ void agg_one_f32(int o, int deg, const int* __restrict__ csrc,
                                            const float* __restrict__ hwf,
                                            const float* __restrict__ alps, int ldh,
                                            float ad0, float ad1, int lane, float* out)
{
    if (deg <= 0) return;
    float acc[8];
    #pragma unroll
    for (int i = 0; i < 8; i++) acc[i] = 0.f;
    float den0 = 0.f, den1 = 0.f;
    const float2* ap = (const float2*)alps;
    const int hb = ((lane < 16) ? 0 : 128) + (lane & 15) * 8;

    int s  = csrc[o];
    int s1 = (deg > 1) ? csrc[o + 1] : 0;
    float2 av = ap[s * ldh];
    float4 va = *(const float4*)(hwf + (size_t)s * 256 + hb);
    float4 vb = *(const float4*)(hwf + (size_t)s * 256 + hb + 4);

    for (int k = 0; k < deg; k++) {
        int s2 = (k + 2 < deg) ? csrc[o + k + 2] : 0;
        float2 avn = ap[s1 * ldh];
        float4 van = *(const float4*)(hwf + (size_t)s1 * 256 + hb);
        float4 vbn = *(const float4*)(hwf + (size_t)s1 * 256 + hb + 4);

        float e0 = av.x + ad0; e0 = e0 > 0.f ? e0 : 0.2f * e0;
        float e1 = av.y + ad1; e1 = e1 > 0.f ? e1 : 0.2f * e1;
        float p0 = __expf(e0), p1 = __expf(e1);
        float pw = (lane < 16) ? p0 : p1;
        acc[0] = fmaf(pw, va.x, acc[0]); acc[1] = fmaf(pw, va.y, acc[1]);
        acc[2] = fmaf(pw, va.z, acc[2]); acc[3] = fmaf(pw, va.w, acc[3]);
        acc[4] = fmaf(pw, vb.x, acc[4]); acc[5] = fmaf(pw, vb.y, acc[5]);
        acc[6] = fmaf(pw, vb.z, acc[6]); acc[7] = fmaf(pw, vb.w, acc[7]);
        den0 += p0; den1 += p1;

        s1 = s2; av = avn; va = van; vb = vbn;
    }
    float r = (lane < 16) ? 1.f / (den0 + 1e-16f) : 1.f / (den1 + 1e-16f);
    #pragma unroll
    for (int i = 0; i < 8; i++) {
        float tmp = acc[i] * r;
        out[i] += tmp + __shfl_xor_sync(0xffffffffu, tmp, 16);
    }
}

// ---------------- fused aggregation + folded inter linear ----------------
__global__ void gat_kernel(const int* __restrict__ off_js, const int* __restrict__ cnt_js,
                           const int* __restrict__ csr_js,
                           const int* __restrict__ off_ss, const int* __restrict__ cnt_ss,
                           const int* __restrict__ csr_ss,
                           const int* __restrict__ off_sj, const int* __restrict__ cnt_sj,
                           const int* __restrict__ csr_sj,
                           const __nv_bfloat16* __restrict__ hw0,
                           const __nv_bfloat16* __restrict__ hw1,
                           const __nv_bfloat16* __restrict__ hw2,
                           const float* __restrict__ hw1f,
                           const float* __restrict__ alpj, const float* __restrict__ alp_s,
                           const float* __restrict__ cvj, const float* __restrict__ cvs,
                           const float* __restrict__ fvj2,
                           float* __restrict__ xj, float* __restrict__ xs,
                           float* __restrict__ xs2,
                           float* __restrict__ alpj_out, int layer)
{
    int w    = (blockIdx.x * blockDim.x + threadIdx.x) >> 5;
    int lane = threadIdx.x & 31;
    int lc   = (lane & 15) * 8;
    float out[8];
    if (layer == 0) {
        if (w < NS) {
            int d = w;
            #pragma unroll
            for (int i = 0; i < 8; i++) out[i] = cvs[lc + i];
            // js: src jobs (alps0 = alpj cols 0,1; ldh=2), dst alpd0 = alp_s cols 4,5
            agg_one_bf(off_js[d], cnt_js[d], csr_js, hw0, alpj, 2,
                       alp_s[d * 8 + 4], alp_s[d * 8 + 5], lane, out);
            if (lane < 16) {
                float4* op = (float4*)(xs + (size_t)d * 128 + lc);
                op[0] = make_float4(out[0], out[1], out[2], out[3]);
                op[1] = make_float4(out[4], out[5], out[6], out[7]);
            }
        } else if (w < 2 * NS) {
            int d = w - NS;
            #pragma unroll
            for (int i = 0; i < 8; i++) out[i] = 0.f;
            // ss: src skills (alps2 = alp_s cols 2,3; ldh=4), dst alpd2 = alp_s cols 6,7
            agg_one_bf(off_ss[d], cnt_ss[d], csr_ss, hw2, alp_s + 2, 4,
                       alp_s[d * 8 + 6], alp_s[d * 8 + 7], lane, out);
            if (lane < 16) {
                float4* op = (float4*)(xs2 + (size_t)d * 128 + lc);
                op[0] = make_float4(out[0], out[1], out[2], out[3]);
                op[1] = make_float4(out[4], out[5], out[6], out[7]);
            }
        } else if (w < 2 * NS + NJ) {
            int d = w - 2 * NS;
            #pragma unroll
            for (int i = 0; i < 8; i++) out[i] = cvj[lc + i];
            // sj: src skills (alps1 = alp_s cols 0,1; ldh=4), dst alpd1 = alpj cols 2,3
            agg_one_bf(off_sj[d], cnt_sj[d], csr_sj, hw1, alp_s, 4,
                       alpj[d * 4 + 2], alpj[d * 4 + 3], lane, out);
            #pragma unroll
            for (int i = 0; i < 8; i++) out[i] = fmaxf(out[i], 0.f);
            float a2p = 0.f, a3p = 0.f;
            if (lane < 16) {
                float4* op = (float4*)(xj + (size_t)d * 128 + lc);
                op[0] = make_float4(out[0], out[1], out[2], out[3]);
                op[1] = make_float4(out[4], out[5], out[6], out[7]);
                #pragma unroll
                for (int i = 0; i < 8; i++) {
                    a2p += out[i] * fvj2[2 * 128 + lc + i];
                    a3p += out[i] * fvj2[3 * 128 + lc + i];
                }
            }
            float a2 = warp_sum(a2p);
            float a3 = warp_sum(a3p);
            if (lane == 0) { alpj_out[d * 4 + 2] = a2; alpj_out[d * 4 + 3] = a3; }
        }
    } else {
        if (w < NJ) {
            int d = w;
            #pragma unroll
            for (int i = 0; i < 8; i++) out[i] = cvj[lc + i];
            agg_one_f32(off_sj[d], cnt_sj[d], csr_sj, hw1f, alp_s, 4,
                        alpj[d * 4 + 2], alpj[d * 4 + 3], lane, out);
            if (lane < 16) {
                float4* op = (float4*)(xj + (size_t)d * 128 + lc);
                op[0] = make_float4(fmaxf(out[0], 0.f), fmaxf(out[1], 0.f),
                                    fmaxf(out[2], 0.f), fmaxf(out[3], 0.f));
                op[1] = make_float4(fmaxf(out[4], 0.f), fmaxf(out[5], 0.f),
                                    fmaxf(out[6], 0.f), fmaxf(out[7], 0.f));
            }
        }
    }
}

// ---------------- host ----------------
extern "C" void kernel_launch(void* const* d_in, const int* in_sizes, int n_in,
                              void* d_out, int out_size)
{
    const float* x_job    = (const float*)d_in[0];
    const float* x_skill  = (const float*)d_in[1];
    const int*   ei_js_s  = (const int*)d_in[2];
    const int*   ei_js_d  = (const int*)d_in[3];
    const int*   ei_sj_s  = (const int*)d_in[4];
    const int*   ei_sj_d  = (const int*)d_in[5];
    const int*   ei_ss_s  = (const int*)d_in[6];
    const int*   ei_ss_d  = (const int*)d_in[7];
    const float* query    = (const float*)d_in[8];
    const float* W0_job   = (const float*)d_in[9];
    const float* b0_job   = (const float*)d_in[10];
    const float* g0_job   = (const float*)d_in[11];
    const float* be0_job  = (const float*)d_in[12];
    const float* W0_skill = (const float*)d_in[13];
    const float* b0_skill = (const float*)d_in[14];
    const float* g0_skill = (const float*)d_in[15];
    const float* be0_skill= (const float*)d_in[16];
    const float* gat_Ws   = (const float*)d_in[17];
    const float* gat_Wd   = (const float*)d_in[18];
    const float* gat_as   = (const float*)d_in[19];
    const float* gat_ad   = (const float*)d_in[20];
    const float* gat_b    = (const float*)d_in[21];
    const float* inter_W  = (const float*)d_in[22];
    const float* inter_b  = (const float*)d_in[23];
    const float* Wjf      = (const float*)d_in[24];
    const float* bjf      = (const float*)d_in[25];
    const float* Wq       = (const float*)d_in[26];
    const float* bq       = (const float*)d_in[27];

    float* out     = (float*)d_out;
    float* scores  = out;
    float* job_emb = out + NJ;
    float* qout    = out + NJ + (size_t)NJ * 128;

    void* p;
    cudaGetSymbolAddress(&p, g_xj);    float* xj    = (float*)p;
    cudaGetSymbolAddress(&p, g_xs);    float* xs    = (float*)p;
    cudaGetSymbolAddress(&p, g_xs2);   float* xs2   = (float*)p;
    cudaGetSymbolAddress(&p, g_hw0);   __nv_bfloat16* hw0 = (__nv_bfloat16*)p;
    cudaGetSymbolAddress(&p, g_hw1);   __nv_bfloat16* hw1 = (__nv_bfloat16*)p;
    cudaGetSymbolAddress(&p, g_hw2);   __nv_bfloat16* hw2 = (__nv_bfloat16*)p;
    cudaGetSymbolAddress(&p, g_hw1f);  float* hw1f  = (float*)p;
    cudaGetSymbolAddress(&p, g_mw);    float* mw    = (float*)p;
    cudaGetSymbolAddress(&p, g_fvj);   float* fvj   = (float*)p;
    cudaGetSymbolAddress(&p, g_fvs);   float* fvs   = (float*)p;
    cudaGetSymbolAddress(&p, g_cvj);   float* cvj   = (float*)p;
    cudaGetSymbolAddress(&p, g_cvs);   float* cvs   = (float*)p;
    cudaGetSymbolAddress(&p, g_alpj);  float* alpj  = (float*)p;
    cudaGetSymbolAddress(&p, g_alp_s); float* alp_s = (float*)p;
    cudaGetSymbolAddress(&p, g_cntcur); int* cntcur = (int*)p;
    int* cnt_js = cntcur;
    int* cur_js = cntcur + NS;
    int* cnt_ss = cntcur + 2 * NS;
    int* cur_ss = cntcur + 3 * NS;
    int* cnt_sj = cntcur + 4 * NS;
    int* cur_sj = cntcur + 4 * NS + NJ;
    cudaGetSymbolAddress(&p, g_off_js); int* off_js = (int*)p;
    cudaGetSymbolAddress(&p, g_off_ss); int* off_ss = (int*)p;
    cudaGetSymbolAddress(&p, g_off_sj); int* off_sj = (int*)p;
    cudaGetSymbolAddress(&p, g_csr_js); int* csr_js = (int*)p;
    cudaGetSymbolAddress(&p, g_csr_ss); int* csr_ss = (int*)p;
    cudaGetSymbolAddress(&p, g_csr_sj); int* csr_sj = (int*)p;

    GJobs J;

    // ---- CSR build ----
    csr_zero_kernel<<<(CNTCUR_N + 255) / 256, 256>>>(cntcur);
    hist3_kernel<<<(E_ALL + 255) / 256, 256>>>(ei_js_d, ei_ss_d, ei_sj_d, cnt_js, cnt_ss, cnt_sj);
    scan3_kernel<<<3, 1024>>>(cnt_js, off_js, cnt_ss, off_ss, cnt_sj, off_sj);
    fill3_kernel<<<(E_ALL + 255) / 256, 256>>>(ei_js_s, ei_js_d, ei_ss_s, ei_ss_d, ei_sj_s, ei_sj_d,
                                               off_js, cur_js, csr_js,
                                               off_ss, cur_ss, csr_ss,
                                               off_sj, cur_sj, csr_sj);

    // ---- merged prep (fv, cvec, q) ----
    prep_kernel<<<29, 128>>>(gat_Ws, gat_Wd, gat_as, gat_ad, gat_b, inter_W, inter_b,
                             query, Wq, bq, fvj, fvs, cvj, cvs, qout);

    // ---- MW folds: all 8 small GEMMs in one launch ----
    {
        for (int z = 0; z < 8; z++) J.j[z] = GJob{};
        for (int r = 0; r < 3; r++) {
            int t = (r == 1) ? 0 : 1;
            for (int h = 0; h < 2; h++) {
                GJob& jj = J.j[r * 2 + h];
                jj.A = gat_Ws + (size_t)r * 32768 + h * 128;
                jj.B = inter_W + (size_t)t * 32768 + (size_t)h * 16384;
                jj.C = mw + (size_t)r * 32768 + h * 128;
                jj.M = 128; jj.lda = 256; jj.ldC = 256;
            }
        }
        for (int h = 0; h < 2; h++) {
            GJob& jj = J.j[6 + h];
            jj.A = gat_Ws + (size_t)(3 + 1) * 32768 + h * 128;
            jj.B = inter_W + (size_t)(2 + 0) * 32768 + (size_t)h * 16384;
            jj.C = mw + (size_t)(3 + 1) * 32768 + h * 128;
            jj.M = 128; jj.lda = 256; jj.ldC = 256;
        }
        gemm_kernel<<<dim3(2, 1, 8), 256>>>(J, 128, 128);
    }

    // ---- initial per-type linear + fused LN + relu ----
    for (int z = 0; z < 8; z++) J.j[z] = GJob{};
    J.j[0].A = x_job;   J.j[0].B = W0_job;   J.j[0].bias = b0_job;
    J.j[0].g = g0_job;  J.j[0].be = be0_job; J.j[0].C = xj;
    J.j[0].M = NJ; J.j[0].lda = SBERT; J.j[0].ldC = 128;
    J.j[1].A = x_skill; J.j[1].B = W0_skill; J.j[1].bias = b0_skill;
    J.j[1].g = g0_skill;J.j[1].be = be0_skill;J.j[1].C = xs;
    J.j[1].M = NS; J.j[1].lda = SBERT; J.j[1].ldC = 128;
    gemm_kernel<<<dim3((NJ + 63) / 64, 1, 2), 256>>>(J, 128, SBERT);

    // ---- layer 1 hw GEMMs (bf16 out) with FUSED alpha dots ----
    for (int z = 0; z < 8; z++) J.j[z] = GJob{};
    J.j[0].A = xj; J.j[0].B = mw + 0 * 32768; J.j[0].Cb = hw0;
    J.j[0].M = NJ; J.j[0].lda = 128; J.j[0].ldC = 256;
    J.j[0].fv = fvj; J.j[0].alp = alpj; J.j[0].n_alpha = 4; J.j[0].alp_ld = 4;
    J.j[1].A = xs; J.j[1].B = mw + 1 * 32768; J.j[1].Cb = hw1;
    J.j[1].M = NS; J.j[1].lda = 128; J.j[1].ldC = 256;
    J.j[1].fv = fvs; J.j[1].alp = alp_s; J.j[1].n_alpha = 8; J.j[1].alp_ld = 8;
    J.j[2].A = xs; J.j[2].B = mw + 2 * 32768; J.j[2].Cb = hw2;
    J.j[2].M = NS; J.j[2].lda = 128; J.j[2].ldC = 256;
    gemm_kernel<<<dim3((NJ + 63) / 64, 2, 3), 256>>>(J, 256, 128);

    gat_kernel<<<((2 * NS + NJ) * 32 + 255) / 256, 256>>>(
        off_js, cnt_js, csr_js, off_ss, cnt_ss, csr_ss, off_sj, cnt_sj, csr_sj,
        hw0, hw1, hw2, hw1f, alpj, alp_s,
        cvj, cvs, fvj + 512, xj, xs, xs2, alpj, 0);

    // ---- layer 2 GEMM (fp32 out for precision) with FUSED alps1 dots ----
    for (int z = 0; z < 8; z++) J.j[z] = GJob{};
    J.j[0].A = xs; J.j[0].A2 = xs2; J.j[0].B = mw + (size_t)(3 + 1) * 32768; J.j[0].C = hw1f;
    J.j[0].M = NS; J.j[0].lda = 128; J.j[0].ldC = 256;
    J.j[0].fv = fvs + 1024; J.j[0].alp = alp_s; J.j[0].n_alpha = 2; J.j[0].alp_ld = 8;
    gemm_kernel<<<dim3((NS + 63) / 64, 2, 1), 256>>>(J, 256, 128);

    gat_kernel<<<(NJ * 32 + 255) / 256, 256>>>(
        off_js, cnt_js, csr_js, off_ss, cnt_ss, csr_ss, off_sj, cnt_sj, csr_sj,
        hw0, hw1, hw2, hw1f, alpj, alp_s,
        cvj + 128, cvs + 128, fvj + 512, xj, xs, xs2, alpj, 1);

    // ---- final projection + fused scores ----
    for (int z = 0; z < 8; z++) J.j[z] = GJob{};
    J.j[0].A = xj; J.j[0].B = Wjf; J.j[0].bias = bjf; J.j[0].qv = qout;
    J.j[0].C = job_emb; J.j[0].sc = scores;
    J.j[0].M = NJ; J.j[0].lda = 128; J.j[0].ldC = 128;
    gemm_kernel<<<dim3((NJ + 63) / 64, 1, 1), 256>>>(J, 128, 128);
}